// round 1
// baseline (speedup 1.0000x reference)
#include <cuda_runtime.h>
#include <cuda_bf16.h>
#include <math.h>

#define BB 4
#define SS 1024
#define DD 1024
#define HH 16
#define INNER 16384
#define DI2 2048

// ---- scratch (static device globals; no allocation in kernel_launch) ----
__device__ float g_qkv[BB * SS * 3 * DD];   // 48 MB
__device__ float g_vals[BB * SS * DD];      // 16 MB  (self-attn output before o-proj)
__device__ float g_qkimg[BB * INNER];
__device__ float g_vv[BB * INNER];
__device__ float g_wq[BB * HH * DD];
__device__ float g_uq[BB * HH * DD];
__device__ float g_sim[BB * HH * SS];
__device__ float g_wvals[BB * HH * DD];
__device__ float g_wtext[BB * HH * DD];
__device__ float g_outpre[BB * INNER];
__device__ float g_ctxrow[BB * DD];
__device__ float g_h1[BB * DI2];
__device__ float g_h2[BB * DI2];
__device__ float g_trow[BB * DD];

// ---------------------------------------------------------------------------
// init: C[i] = bias[i % n] (or 0)
__global__ void init_bias_k(float* __restrict__ C, const float* __restrict__ bias,
                            int n, int total) {
    int i = blockIdx.x * 256 + threadIdx.x;
    if (i < total) C[i] = bias ? bias[i % n] : 0.f;
}

// ---------------------------------------------------------------------------
// Classic 128x128x8 SGEMM with bias: C[M,N] = A[M,K] @ B[K,N] + bias[N]
// M,N multiples of 128; K multiple of 8.
__global__ __launch_bounds__(256) void sgemm128(const float* __restrict__ A,
                                                const float* __restrict__ Bm,
                                                const float* __restrict__ bias,
                                                float* __restrict__ C,
                                                int M, int N, int K) {
    __shared__ float As[8][128];
    __shared__ float Bs[8][128];
    const int tid = threadIdx.x;
    const int rowBase = blockIdx.y * 128;
    const int colBase = blockIdx.x * 128;
    const int aRow = tid >> 1, aCol = (tid & 1) * 4;
    const int bRowL = tid >> 5, bColL = (tid & 31) * 4;
    const int tx = tid & 15, ty = tid >> 4;
    float acc[8][8];
#pragma unroll
    for (int i = 0; i < 8; i++)
#pragma unroll
        for (int j = 0; j < 8; j++) acc[i][j] = 0.f;

    for (int k0 = 0; k0 < K; k0 += 8) {
        float4 a4 = *(const float4*)&A[(size_t)(rowBase + aRow) * K + k0 + aCol];
        As[aCol + 0][aRow] = a4.x;
        As[aCol + 1][aRow] = a4.y;
        As[aCol + 2][aRow] = a4.z;
        As[aCol + 3][aRow] = a4.w;
        float4 b4 = *(const float4*)&Bm[(size_t)(k0 + bRowL) * N + colBase + bColL];
        *(float4*)&Bs[bRowL][bColL] = b4;
        __syncthreads();
#pragma unroll
        for (int k = 0; k < 8; k++) {
            float ar[8], br[8];
#pragma unroll
            for (int i = 0; i < 8; i++) ar[i] = As[k][ty * 8 + i];
#pragma unroll
            for (int j = 0; j < 8; j++) br[j] = Bs[k][tx * 8 + j];
#pragma unroll
            for (int i = 0; i < 8; i++)
#pragma unroll
                for (int j = 0; j < 8; j++) acc[i][j] += ar[i] * br[j];
        }
        __syncthreads();
    }
#pragma unroll
    for (int i = 0; i < 8; i++) {
        int row = rowBase + ty * 8 + i;
#pragma unroll
        for (int j = 0; j < 8; j += 4) {
            int col = colBase + tx * 8 + j;
            float4 r;
            r.x = acc[i][j + 0] + bias[col + 0];
            r.y = acc[i][j + 1] + bias[col + 1];
            r.z = acc[i][j + 2] + bias[col + 2];
            r.w = acc[i][j + 3] + bias[col + 3];
            *(float4*)&C[(size_t)row * N + col] = r;
        }
    }
}

// ---------------------------------------------------------------------------
// Flash-style self attention. qkv layout [B,S,3072]; per (b,s,h):
// q at h*192, k at h*192+64, v at h*192+128. Output vals[b,s,h*64+d].
__global__ __launch_bounds__(128) void attn_kernel(const float* __restrict__ qkv,
                                                   float* __restrict__ vals) {
    const int bh = blockIdx.x;
    const int b = bh >> 4, h = bh & 15;
    const int row = blockIdx.y * 128 + threadIdx.x;
    const float* base = qkv + (size_t)b * SS * 3072;
    const float* qptr = base + (size_t)row * 3072 + h * 192;
    float q[64];
#pragma unroll
    for (int d = 0; d < 64; d += 4) {
        float4 t = *(const float4*)&qptr[d];
        q[d] = t.x * 0.125f; q[d + 1] = t.y * 0.125f;
        q[d + 2] = t.z * 0.125f; q[d + 3] = t.w * 0.125f;
    }
    float acc[64];
#pragma unroll
    for (int d = 0; d < 64; d++) acc[d] = 0.f;
    float m = -1e30f, l = 0.f;

    __shared__ float ks[32][64];
    __shared__ float vs[32][64];

    for (int j0 = 0; j0 < SS; j0 += 32) {
        __syncthreads();
#pragma unroll
        for (int i = threadIdx.x; i < 512; i += 128) {
            int j = i >> 4, dd = (i & 15) << 2;
            const float* kp = base + (size_t)(j0 + j) * 3072 + h * 192;
            *(float4*)&ks[j][dd] = *(const float4*)&kp[64 + dd];
            *(float4*)&vs[j][dd] = *(const float4*)&kp[128 + dd];
        }
        __syncthreads();
        float s[32];
        float mc = -1e30f;
#pragma unroll 4
        for (int j = 0; j < 32; j++) {
            float t = 0.f;
#pragma unroll
            for (int d = 0; d < 64; d += 4) {
                float4 kk = *(const float4*)&ks[j][d];
                t += q[d] * kk.x + q[d + 1] * kk.y + q[d + 2] * kk.z + q[d + 3] * kk.w;
            }
            s[j] = t;
            mc = fmaxf(mc, t);
        }
        float mn = fmaxf(m, mc);
        float corr = __expf(m - mn);
        l *= corr;
#pragma unroll
        for (int d = 0; d < 64; d++) acc[d] *= corr;
#pragma unroll 2
        for (int j = 0; j < 32; j++) {
            float p = __expf(s[j] - mn);
            l += p;
#pragma unroll
            for (int d = 0; d < 64; d += 4) {
                float4 vv4 = *(const float4*)&vs[j][d];
                acc[d] += p * vv4.x; acc[d + 1] += p * vv4.y;
                acc[d + 2] += p * vv4.z; acc[d + 3] += p * vv4.w;
            }
        }
        m = mn;
    }
    float inv = 1.f / l;
    float* op = vals + (size_t)(b * SS + row) * DD + h * 64;
#pragma unroll
    for (int d = 0; d < 64; d += 4) {
        float4 t;
        t.x = acc[d] * inv; t.y = acc[d + 1] * inv;
        t.z = acc[d + 2] * inv; t.w = acc[d + 3] * inv;
        *(float4*)&op[d] = t;
    }
}

// ---------------------------------------------------------------------------
// img [4,1024] projections through two [1024,16384] matrices (memory stream).
// grid (INNER/256, 8 ksplits, 2 matrices), atomicAdd into zero-inited outputs.
__global__ void img_proj(const float* __restrict__ img,
                         const float* __restrict__ W1, const float* __restrict__ W2,
                         float* __restrict__ O1, float* __restrict__ O2) {
    const float* W = blockIdx.z ? W2 : W1;
    float* O = blockIdx.z ? O2 : O1;
    int col = blockIdx.x * 256 + threadIdx.x;
    int k0 = blockIdx.y * 128;
    __shared__ float xs[4][128];
    for (int i = threadIdx.x; i < 512; i += 256)
        xs[i >> 7][i & 127] = img[(i >> 7) * DD + k0 + (i & 127)];
    __syncthreads();
    float a0 = 0, a1 = 0, a2 = 0, a3 = 0;
    const float* wp = W + (size_t)k0 * INNER + col;
#pragma unroll 4
    for (int k = 0; k < 128; k++) {
        float wv = wp[(size_t)k * INNER];
        a0 += xs[0][k] * wv; a1 += xs[1][k] * wv;
        a2 += xs[2][k] * wv; a3 += xs[3][k] * wv;
    }
    atomicAdd(&O[col], a0);
    atomicAdd(&O[INNER + col], a1);
    atomicAdd(&O[2 * INNER + col], a2);
    atomicAdd(&O[3 * INNER + col], a3);
}

// ---------------------------------------------------------------------------
// wq[b*H+h, d] = sum_e ctx_qk_w[d, h*1024+e] * qkimg[b, h*1024+e]
// One warp per (d,h): coalesced 4KB row-segment read. grid 2048 x 256thr.
__global__ __launch_bounds__(256) void wq_kernel(const float* __restrict__ Wc,
                                                 const float* __restrict__ qkimg,
                                                 float* __restrict__ wq) {
    int gwarp = (blockIdx.x * 256 + threadIdx.x) >> 5;
    int lane = threadIdx.x & 31;
    int d = gwarp >> 4, h = gwarp & 15;
    const float* row = Wc + (size_t)d * INNER + h * 1024;
    const float* qb = qkimg + h * 1024;
    float a0 = 0, a1 = 0, a2 = 0, a3 = 0;
    for (int e = lane; e < 1024; e += 32) {
        float wv = row[e];
        a0 += wv * qb[e];
        a1 += wv * qb[INNER + e];
        a2 += wv * qb[2 * INNER + e];
        a3 += wv * qb[3 * INNER + e];
    }
#pragma unroll
    for (int o = 16; o; o >>= 1) {
        a0 += __shfl_xor_sync(0xffffffffu, a0, o);
        a1 += __shfl_xor_sync(0xffffffffu, a1, o);
        a2 += __shfl_xor_sync(0xffffffffu, a2, o);
        a3 += __shfl_xor_sync(0xffffffffu, a3, o);
    }
    if (lane == 0) {
        wq[(0 * HH + h) * DD + d] = a0;
        wq[(1 * HH + h) * DD + d] = a1;
        wq[(2 * HH + h) * DD + d] = a2;
        wq[(3 * HH + h) * DD + d] = a3;
    }
}

// ---------------------------------------------------------------------------
// NT GEMM for small M: C[i,j] = alpha * sum_k A[i*lda+k] * B[j*ldb+k]
// grid (N/8, batch); 8 warps/block, one j per warp. K multiple of 128.
template <int MT>
__global__ __launch_bounds__(256) void gemm_nt(const float* __restrict__ A, int lda, long sA,
                                               const float* __restrict__ Bm, int ldb, long sB,
                                               float* __restrict__ C, int ldc, long sC,
                                               int M, int N, int K, float alpha) {
    int batch = blockIdx.y;
    A += (size_t)batch * sA; Bm += (size_t)batch * sB; C += (size_t)batch * sC;
    int warp = threadIdx.x >> 5, lane = threadIdx.x & 31;
    int j = blockIdx.x * 8 + warp;
    __shared__ float As[MT][128];
    float acc[MT];
#pragma unroll
    for (int i = 0; i < MT; i++) acc[i] = 0.f;
    for (int k0 = 0; k0 < K; k0 += 128) {
        __syncthreads();
        for (int i = threadIdx.x; i < MT * 128; i += 256) {
            int r = i >> 7, c = i & 127;
            As[r][c] = (r < M) ? A[(size_t)r * lda + k0 + c] : 0.f;
        }
        __syncthreads();
        const float* bp = Bm + (size_t)j * ldb + k0;
        for (int k = lane; k < 128; k += 32) {
            float bv = bp[k];
#pragma unroll
            for (int i = 0; i < MT; i++) acc[i] += As[i][k] * bv;
        }
    }
#pragma unroll
    for (int i = 0; i < MT; i++) {
        float v = acc[i];
#pragma unroll
        for (int o = 16; o; o >>= 1) v += __shfl_xor_sync(0xffffffffu, v, o);
        if (lane == 0 && i < M) C[(size_t)i * ldc + j] = alpha * v;
    }
}

// ---------------------------------------------------------------------------
// NN GEMM for small M: C[i,j] (+)= alpha * sum_k A[i*lda+k]*B[k*ldb+j] (+bias,act)
// grid (N/256, batch, ksplit). ksplit>1 -> atomicAdd into pre-inited C.
template <int MT>
__global__ __launch_bounds__(256) void gemm_nn(const float* __restrict__ A, int lda, long sA,
                                               const float* __restrict__ Bm, int ldb, long sB,
                                               const float* __restrict__ bias,
                                               float* __restrict__ C, int ldc, long sC,
                                               int M, int N, int K, float alpha, int act) {
    int batch = blockIdx.y;
    A += (size_t)batch * sA; Bm += (size_t)batch * sB; C += (size_t)batch * sC;
    int j = blockIdx.x * 256 + threadIdx.x;
    int kChunk = K / gridDim.z;
    int kBeg = blockIdx.z * kChunk;
    float acc[MT];
#pragma unroll
    for (int i = 0; i < MT; i++) acc[i] = 0.f;
    __shared__ float As[MT][32];
    for (int k0 = kBeg; k0 < kBeg + kChunk; k0 += 32) {
        __syncthreads();
        for (int i = threadIdx.x; i < MT * 32; i += 256) {
            int r = i >> 5, c = i & 31;
            As[r][c] = (r < M) ? A[(size_t)r * lda + k0 + c] : 0.f;
        }
        __syncthreads();
#pragma unroll 4
        for (int k = 0; k < 32; k++) {
            float bv = Bm[(size_t)(k0 + k) * ldb + j];
#pragma unroll
            for (int i = 0; i < MT; i++) acc[i] += As[i][k] * bv;
        }
    }
    if (gridDim.z == 1) {
        float bb = bias ? bias[j] : 0.f;
        for (int i = 0; i < MT && i < M; i++) {
            float v = alpha * acc[i] + bb;
            if (act) v = tanhf(v);
            C[(size_t)i * ldc + j] = v;
        }
    } else {
        for (int i = 0; i < MT && i < M; i++)
            atomicAdd(&C[(size_t)i * ldc + j], alpha * acc[i]);
    }
}

// ---------------------------------------------------------------------------
__global__ void softmax_rows(float* __restrict__ base, int n) {
    float* p = base + (size_t)blockIdx.x * n;
    __shared__ float red[8];
    __shared__ float red2[8];
    int tid = threadIdx.x;
    float m = -1e30f;
    for (int j = tid; j < n; j += 256) m = fmaxf(m, p[j]);
#pragma unroll
    for (int o = 16; o; o >>= 1) m = fmaxf(m, __shfl_xor_sync(0xffffffffu, m, o));
    if ((tid & 31) == 0) red[tid >> 5] = m;
    __syncthreads();
    float mm = red[0];
#pragma unroll
    for (int w = 1; w < 8; w++) mm = fmaxf(mm, red[w]);
    float sum = 0.f;
    for (int j = tid; j < n; j += 256) {
        float e = __expf(p[j] - mm);
        p[j] = e;
        sum += e;
    }
#pragma unroll
    for (int o = 16; o; o >>= 1) sum += __shfl_xor_sync(0xffffffffu, sum, o);
    if ((tid & 31) == 0) red2[tid >> 5] = sum;
    __syncthreads();
    float tot = 0.f;
#pragma unroll
    for (int w = 0; w < 8; w++) tot += red2[w];
    float inv = 1.f / tot;
    for (int j = tid; j < n; j += 256) p[j] *= inv;
}

// ---------------------------------------------------------------------------
// text_out[b,s,:] = trow[b,:]  (broadcast, float4)
__global__ void bcast_text(const float* __restrict__ trow, float* __restrict__ out) {
    size_t idx = (size_t)blockIdx.x * 256 + threadIdx.x;
    size_t e = idx * 4;
    int b = (int)(e / ((size_t)SS * DD));
    int d = (int)(e % DD);
    *(float4*)&out[e] = *(const float4*)&trow[b * DD + d];
}

// ---------------------------------------------------------------------------
extern "C" void kernel_launch(void* const* d_in, const int* in_sizes, int n_in,
                              void* d_out, int out_size) {
    (void)in_sizes; (void)n_in; (void)out_size;
    const float* img      = (const float*)d_in[0];
    const float* text_emb = (const float*)d_in[1];
    const float* qkv_w    = (const float*)d_in[2];
    const float* qkv_b    = (const float*)d_in[3];
    const float* o_w      = (const float*)d_in[4];
    const float* o_b      = (const float*)d_in[5];
    const float* qk_w     = (const float*)d_in[6];
    const float* ctx_qk_w = (const float*)d_in[7];
    const float* v_w      = (const float*)d_in[8];
    const float* ctx_v_w  = (const float*)d_in[9];
    const float* out_w    = (const float*)d_in[10];
    const float* out_b    = (const float*)d_in[11];
    const float* ctx_out_w= (const float*)d_in[12];
    const float* ctx_out_b= (const float*)d_in[13];
    const float* w1 = (const float*)d_in[14];
    const float* b1 = (const float*)d_in[15];
    const float* w2 = (const float*)d_in[16];
    const float* b2 = (const float*)d_in[17];
    const float* w3 = (const float*)d_in[18];
    const float* b3 = (const float*)d_in[19];

    float* out_head = (float*)d_out;          // [4,1024]
    float* out_text = (float*)d_out + BB * DD; // [4,1024,1024]

    float *p_qkv, *p_vals, *p_qkimg, *p_vv, *p_wq, *p_uq, *p_sim, *p_wvals,
          *p_wtext, *p_outpre, *p_ctxrow, *p_h1, *p_h2, *p_trow;
    cudaGetSymbolAddress((void**)&p_qkv, g_qkv);
    cudaGetSymbolAddress((void**)&p_vals, g_vals);
    cudaGetSymbolAddress((void**)&p_qkimg, g_qkimg);
    cudaGetSymbolAddress((void**)&p_vv, g_vv);
    cudaGetSymbolAddress((void**)&p_wq, g_wq);
    cudaGetSymbolAddress((void**)&p_uq, g_uq);
    cudaGetSymbolAddress((void**)&p_sim, g_sim);
    cudaGetSymbolAddress((void**)&p_wvals, g_wvals);
    cudaGetSymbolAddress((void**)&p_wtext, g_wtext);
    cudaGetSymbolAddress((void**)&p_outpre, g_outpre);
    cudaGetSymbolAddress((void**)&p_ctxrow, g_ctxrow);
    cudaGetSymbolAddress((void**)&p_h1, g_h1);
    cudaGetSymbolAddress((void**)&p_h2, g_h2);
    cudaGetSymbolAddress((void**)&p_trow, g_trow);

    // ---- init atomic targets / bias-seeded outputs ----
    init_bias_k<<<(BB * INNER + 255) / 256, 256>>>(p_qkimg, nullptr, INNER, BB * INNER);
    init_bias_k<<<(BB * INNER + 255) / 256, 256>>>(p_vv, nullptr, INNER, BB * INNER);
    init_bias_k<<<(BB * INNER + 255) / 256, 256>>>(p_outpre, nullptr, INNER, BB * INNER);
    init_bias_k<<<(BB * DD + 255) / 256, 256>>>(out_head, out_b, DD, BB * DD);
    init_bias_k<<<(BB * DD + 255) / 256, 256>>>(p_ctxrow, ctx_out_b, DD, BB * DD);
    init_bias_k<<<(BB * HH * DD + 255) / 256, 256>>>(p_wtext, o_b, DD, BB * HH * DD);

    // ---- self-attention ----
    sgemm128<<<dim3(3072 / 128, 4096 / 128), 256>>>(text_emb, qkv_w, qkv_b, p_qkv,
                                                    BB * SS, 3 * DD, DD);
    attn_kernel<<<dim3(BB * HH, SS / 128), 128>>>(p_qkv, p_vals);

    // ---- img projections (qk_w, v_w streams) ----
    img_proj<<<dim3(INNER / 256, 8, 2), 256>>>(img, qk_w, v_w, p_qkimg, p_vv);

    // ---- wq = per-head ctx_qk_w^T @ qk_img (ctx_qk_w stream) ----
    wq_kernel<<<2048, 256>>>(ctx_qk_w, p_qkimg, p_wq);

    // ---- uq[bh,m] = sum_n wq[bh,n] * o_w[m,n] ----
    gemm_nt<64><<<dim3(DD / 8, 1), 256>>>(p_wq, DD, 0, o_w, DD, 0, p_uq, DD, 0,
                                          64, DD, DD, 1.0f);
    // ---- sim[b][h,j] = (1/32) * sum_m uq[bh,m] * vals[b,j,m] ----
    gemm_nt<16><<<dim3(SS / 8, BB), 256>>>(p_uq, DD, (long)HH * DD,
                                           p_vals, DD, (long)SS * DD,
                                           p_sim, SS, (long)HH * SS,
                                           HH, SS, DD, 1.0f / 32.0f);
    // ---- row softmax over j ----
    softmax_rows<<<BB * HH, 256>>>(p_sim, SS);

    // ---- wvals[b][h,m] = sum_j attn[h,j] * vals[b,j,m] ----
    gemm_nn<16><<<dim3(DD / 256, BB, 1), 256>>>(p_sim, SS, (long)HH * SS,
                                                p_vals, DD, (long)SS * DD,
                                                nullptr, p_wvals, DD, (long)HH * DD,
                                                HH, DD, SS, 1.0f, 0);
    // ---- wtext = wvals @ o_w (+ o_b via init), ksplit atomic ----
    gemm_nn<64><<<dim3(DD / 256, 1, 4), 256>>>(p_wvals, DD, 0, o_w, DD, 0,
                                               nullptr, p_wtext, DD, 0,
                                               64, DD, DD, 1.0f, 0);
    // ---- out_pre[b, h*1024+e] = sum_d wtext[bh,d]*ctx_v_w[d,h*1024+e] (stream) ----
    gemm_nn<4><<<dim3(1024 / 256, HH, 4), 256>>>(p_wtext, HH * DD, (long)DD,
                                                 ctx_v_w, INNER, 1024L,
                                                 nullptr, p_outpre, INNER, 1024L,
                                                 BB, 1024, DD, 1.0f, 0);
    // ---- out = out_pre @ out_w (+ out_b via init) (stream) ----
    gemm_nn<4><<<dim3(DD / 256, 1, 32), 256>>>(p_outpre, INNER, 0, out_w, DD, 0,
                                               nullptr, out_head, DD, 0,
                                               BB, DD, INNER, 1.0f, 0);
    // ---- ctx_row = vv @ ctx_out_w (+ ctx_out_b via init) (stream) ----
    gemm_nn<4><<<dim3(DD / 256, 1, 32), 256>>>(p_vv, INNER, 0, ctx_out_w, DD, 0,
                                               nullptr, p_ctxrow, DD, 0,
                                               BB, DD, INNER, 1.0f, 0);
    // ---- tiny MLP on 4 rows ----
    gemm_nn<4><<<dim3(DI2 / 256, 1, 1), 256>>>(p_ctxrow, DD, 0, w1, DI2, 0, b1,
                                               p_h1, DI2, 0, BB, DI2, DD, 1.0f, 1);
    gemm_nn<4><<<dim3(DI2 / 256, 1, 1), 256>>>(p_h1, DI2, 0, w2, DI2, 0, b2,
                                               p_h2, DI2, 0, BB, DI2, DI2, 1.0f, 1);
    gemm_nn<4><<<dim3(DD / 256, 1, 1), 256>>>(p_h2, DI2, 0, w3, DD, 0, b3,
                                              p_trow, DD, 0, BB, DD, DI2, 1.0f, 0);
    // ---- broadcast text_out ----
    bcast_text<<<(BB * SS * DD / 4) / 256, 256>>>(p_trow, out_text);
}

// round 2
// speedup vs baseline: 1.9355x; 1.9355x over previous
#include <cuda_runtime.h>
#include <cuda_bf16.h>
#include <math.h>

#define BB 4
#define SS 1024
#define DD 1024
#define HH 16
#define INNER 16384
#define DI2 2048
#define PAD 68

// ---- scratch (static device globals; no allocation in kernel_launch) ----
__device__ float g_qkv[BB * SS * 3 * DD];   // 48 MB
__device__ float g_vals[BB * SS * DD];      // 16 MB
__device__ float g_qkimg[BB * INNER];
__device__ float g_vv[BB * INNER];
__device__ float g_wq[BB * HH * DD];
__device__ float g_uq[BB * HH * DD];
__device__ float g_sim[BB * HH * SS];
__device__ float g_wvals[BB * HH * DD];
__device__ float g_wtext[BB * HH * DD];
__device__ float g_outpre[BB * INNER];
__device__ float g_ctxrow[BB * DD];
__device__ float g_h1[BB * DI2];
__device__ float g_h2[BB * DI2];
__device__ float g_trow[BB * DD];

// ---------------------------------------------------------------------------
// Fused init: zeros + bias-seeded buffers. grid 256x256 covers 65536.
__global__ void init_all(float* __restrict__ qkimg, float* __restrict__ vv,
                         float* __restrict__ outpre, float* __restrict__ wvals,
                         float* __restrict__ h1, float* __restrict__ h2,
                         float* __restrict__ trow,
                         float* __restrict__ outh, const float* __restrict__ out_b,
                         float* __restrict__ ctxrow, const float* __restrict__ ctx_out_b,
                         float* __restrict__ wtext, const float* __restrict__ o_b) {
    int i = blockIdx.x * 256 + threadIdx.x;
    qkimg[i] = 0.f; vv[i] = 0.f; outpre[i] = 0.f; wvals[i] = 0.f;
    wtext[i] = o_b[i & 1023];
    if (i < BB * DI2) { h1[i] = 0.f; h2[i] = 0.f; }
    if (i < BB * DD) {
        trow[i] = 0.f;
        outh[i] = out_b[i & 1023];
        ctxrow[i] = ctx_out_b[i & 1023];
    }
}

// ---------------------------------------------------------------------------
// 128x128x8 SGEMM, software-pipelined gmem prefetch. C = A@B + bias.
__global__ __launch_bounds__(256) void sgemm128(const float* __restrict__ A,
                                                const float* __restrict__ Bm,
                                                const float* __restrict__ bias,
                                                float* __restrict__ C,
                                                int M, int N, int K) {
    __shared__ float As[8][128];
    __shared__ float Bs[8][128];
    const int tid = threadIdx.x;
    const int rowBase = blockIdx.y * 128;
    const int colBase = blockIdx.x * 128;
    const int aRow = tid >> 1, aCol = (tid & 1) * 4;
    const int bRowL = tid >> 5, bColL = (tid & 31) * 4;
    const int tx = tid & 15, ty = tid >> 4;
    float acc[8][8];
#pragma unroll
    for (int i = 0; i < 8; i++)
#pragma unroll
        for (int j = 0; j < 8; j++) acc[i][j] = 0.f;

    const float* aPtr = &A[(size_t)(rowBase + aRow) * K + aCol];
    const float* bPtr = &Bm[(size_t)bRowL * N + colBase + bColL];
    float4 a4 = *(const float4*)aPtr;
    float4 b4 = *(const float4*)bPtr;

    for (int k0 = 0; k0 < K; k0 += 8) {
        As[aCol + 0][aRow] = a4.x;
        As[aCol + 1][aRow] = a4.y;
        As[aCol + 2][aRow] = a4.z;
        As[aCol + 3][aRow] = a4.w;
        *(float4*)&Bs[bRowL][bColL] = b4;
        __syncthreads();
        if (k0 + 8 < K) {
            a4 = *(const float4*)(aPtr + k0 + 8);
            b4 = *(const float4*)(bPtr + (size_t)(k0 + 8) * N);
        }
#pragma unroll
        for (int k = 0; k < 8; k++) {
            float ar[8], br[8];
#pragma unroll
            for (int i = 0; i < 8; i++) ar[i] = As[k][ty * 8 + i];
#pragma unroll
            for (int j = 0; j < 8; j++) br[j] = Bs[k][tx * 8 + j];
#pragma unroll
            for (int i = 0; i < 8; i++)
#pragma unroll
                for (int j = 0; j < 8; j++) acc[i][j] += ar[i] * br[j];
        }
        __syncthreads();
    }
#pragma unroll
    for (int i = 0; i < 8; i++) {
        int row = rowBase + ty * 8 + i;
#pragma unroll
        for (int j = 0; j < 8; j += 4) {
            int col = colBase + tx * 8 + j;
            float4 r;
            r.x = acc[i][j + 0] + bias[col + 0];
            r.y = acc[i][j + 1] + bias[col + 1];
            r.z = acc[i][j + 2] + bias[col + 2];
            r.w = acc[i][j + 3] + bias[col + 3];
            *(float4*)&C[(size_t)row * N + col] = r;
        }
    }
}

// ---------------------------------------------------------------------------
// Register-tiled flash attention.
// Block = 64 queries of one (b,h); 128 threads; 8q x 4(k|d) micro-tiles.
// smem: Qs [d][q] (scaled), KP [d][k] -> reused as P [k][q], Vs [k][d]; pad 68.
__global__ __launch_bounds__(128) void attn2(const float* __restrict__ qkv,
                                             float* __restrict__ vals) {
    extern __shared__ float sm[];
    float* Qs = sm;                 // 64*PAD
    float* KP = sm + 64 * PAD;      // 64*PAD
    float* Vs = sm + 128 * PAD;     // 64*PAD
    const int bh = blockIdx.x;
    const int b = bh >> 4, h = bh & 15;
    const int qbase = blockIdx.y * 64;
    const float* base = qkv + (size_t)b * SS * 3072 + h * 192;
    const int tid = threadIdx.x;
    const int tx = tid & 15, ty = tid >> 4;
    const int q8 = ty * 8, c4 = tx * 4;   // c4: k-cols in GEMM1, d-cols in GEMM2

    // load Q transposed + scaled
#pragma unroll
    for (int it = 0; it < 8; it++) {
        int idx = it * 128 + tid;
        int q = idx >> 4, d4 = (idx & 15) << 2;
        float4 t = *(const float4*)&base[(size_t)(qbase + q) * 3072 + d4];
        Qs[(d4 + 0) * PAD + q] = t.x * 0.125f;
        Qs[(d4 + 1) * PAD + q] = t.y * 0.125f;
        Qs[(d4 + 2) * PAD + q] = t.z * 0.125f;
        Qs[(d4 + 3) * PAD + q] = t.w * 0.125f;
    }

    float acc[8][4], m[8], l[8];
#pragma unroll
    for (int i = 0; i < 8; i++) {
        m[i] = -1e30f; l[i] = 0.f;
#pragma unroll
        for (int j = 0; j < 4; j++) acc[i][j] = 0.f;
    }

    for (int k0 = 0; k0 < SS; k0 += 64) {
        __syncthreads();  // prev-iter readers done (also covers Q store on iter 0)
#pragma unroll
        for (int it = 0; it < 8; it++) {
            int idx = it * 128 + tid;
            int k = idx >> 4, d4 = (idx & 15) << 2;
            const float* kp = base + (size_t)(k0 + k) * 3072;
            float4 kk = *(const float4*)&kp[64 + d4];
            KP[(d4 + 0) * PAD + k] = kk.x;
            KP[(d4 + 1) * PAD + k] = kk.y;
            KP[(d4 + 2) * PAD + k] = kk.z;
            KP[(d4 + 3) * PAD + k] = kk.w;
            *(float4*)&Vs[k * PAD + d4] = *(const float4*)&kp[128 + d4];
        }
        __syncthreads();

        // scores S[8q][4k]
        float s[8][4];
#pragma unroll
        for (int i = 0; i < 8; i++) { s[i][0] = s[i][1] = s[i][2] = s[i][3] = 0.f; }
#pragma unroll 8
        for (int d = 0; d < 64; d++) {
            float4 qa = *(float4*)&Qs[d * PAD + q8];
            float4 qb = *(float4*)&Qs[d * PAD + q8 + 4];
            float4 kk = *(float4*)&KP[d * PAD + c4];
            float qv[8] = {qa.x, qa.y, qa.z, qa.w, qb.x, qb.y, qb.z, qb.w};
            float kv[4] = {kk.x, kk.y, kk.z, kk.w};
#pragma unroll
            for (int i = 0; i < 8; i++)
#pragma unroll
                for (int j = 0; j < 4; j++) s[i][j] += qv[i] * kv[j];
        }

        // online softmax per row (row = 16 lanes sharing ty)
#pragma unroll
        for (int i = 0; i < 8; i++) {
            float mt = fmaxf(fmaxf(s[i][0], s[i][1]), fmaxf(s[i][2], s[i][3]));
#pragma unroll
            for (int o = 1; o < 16; o <<= 1)
                mt = fmaxf(mt, __shfl_xor_sync(0xffffffffu, mt, o));
            float mn = fmaxf(m[i], mt);
            float corr = __expf(m[i] - mn);
            float ps = 0.f;
#pragma unroll
            for (int j = 0; j < 4; j++) {
                s[i][j] = __expf(s[i][j] - mn);
                ps += s[i][j];
            }
#pragma unroll
            for (int o = 1; o < 16; o <<= 1)
                ps += __shfl_xor_sync(0xffffffffu, ps, o);
            l[i] = l[i] * corr + ps;
            m[i] = mn;
#pragma unroll
            for (int j = 0; j < 4; j++) acc[i][j] *= corr;
        }

        __syncthreads();  // everyone done reading KP as K
        // store P as [k][q]
#pragma unroll
        for (int i = 0; i < 8; i++)
#pragma unroll
            for (int j = 0; j < 4; j++)
                KP[(c4 + j) * PAD + q8 + i] = s[i][j];
        __syncthreads();

        // O[8q][4d] += P @ V
#pragma unroll 8
        for (int k = 0; k < 64; k++) {
            float4 pa = *(float4*)&KP[k * PAD + q8];
            float4 pb = *(float4*)&KP[k * PAD + q8 + 4];
            float4 vv = *(float4*)&Vs[k * PAD + c4];
            float pv[8] = {pa.x, pa.y, pa.z, pa.w, pb.x, pb.y, pb.z, pb.w};
            float vw[4] = {vv.x, vv.y, vv.z, vv.w};
#pragma unroll
            for (int i = 0; i < 8; i++)
#pragma unroll
                for (int j = 0; j < 4; j++) acc[i][j] += pv[i] * vw[j];
        }
    }

#pragma unroll
    for (int i = 0; i < 8; i++) {
        float inv = 1.f / l[i];
        float4 r;
        r.x = acc[i][0] * inv; r.y = acc[i][1] * inv;
        r.z = acc[i][2] * inv; r.w = acc[i][3] * inv;
        *(float4*)&vals[(size_t)(b * SS + qbase + q8 + i) * DD + h * 64 + c4] = r;
    }
}

// ---------------------------------------------------------------------------
// img [4,1024] projections through two [1024,16384] matrices (memory stream).
__global__ void img_proj(const float* __restrict__ img,
                         const float* __restrict__ W1, const float* __restrict__ W2,
                         float* __restrict__ O1, float* __restrict__ O2) {
    const float* W = blockIdx.z ? W2 : W1;
    float* O = blockIdx.z ? O2 : O1;
    int col = blockIdx.x * 256 + threadIdx.x;
    int k0 = blockIdx.y * 128;
    __shared__ float xs[4][128];
    for (int i = threadIdx.x; i < 512; i += 256)
        xs[i >> 7][i & 127] = img[(i >> 7) * DD + k0 + (i & 127)];
    __syncthreads();
    float a0 = 0, a1 = 0, a2 = 0, a3 = 0;
    const float* wp = W + (size_t)k0 * INNER + col;
#pragma unroll 4
    for (int k = 0; k < 128; k++) {
        float wv = wp[(size_t)k * INNER];
        a0 += xs[0][k] * wv; a1 += xs[1][k] * wv;
        a2 += xs[2][k] * wv; a3 += xs[3][k] * wv;
    }
    atomicAdd(&O[col], a0);
    atomicAdd(&O[INNER + col], a1);
    atomicAdd(&O[2 * INNER + col], a2);
    atomicAdd(&O[3 * INNER + col], a3);
}

// ---------------------------------------------------------------------------
// wq[b*H+h, d] = sum_e ctx_qk_w[d, h*1024+e] * qkimg[b, h*1024+e]
__global__ __launch_bounds__(256) void wq_kernel(const float* __restrict__ Wc,
                                                 const float* __restrict__ qkimg,
                                                 float* __restrict__ wq) {
    int gwarp = (blockIdx.x * 256 + threadIdx.x) >> 5;
    int lane = threadIdx.x & 31;
    int d = gwarp >> 4, h = gwarp & 15;
    const float* row = Wc + (size_t)d * INNER + h * 1024;
    const float* qb = qkimg + h * 1024;
    float a0 = 0, a1 = 0, a2 = 0, a3 = 0;
    for (int e = lane; e < 1024; e += 32) {
        float wv = row[e];
        a0 += wv * qb[e];
        a1 += wv * qb[INNER + e];
        a2 += wv * qb[2 * INNER + e];
        a3 += wv * qb[3 * INNER + e];
    }
#pragma unroll
    for (int o = 16; o; o >>= 1) {
        a0 += __shfl_xor_sync(0xffffffffu, a0, o);
        a1 += __shfl_xor_sync(0xffffffffu, a1, o);
        a2 += __shfl_xor_sync(0xffffffffu, a2, o);
        a3 += __shfl_xor_sync(0xffffffffu, a3, o);
    }
    if (lane == 0) {
        wq[(0 * HH + h) * DD + d] = a0;
        wq[(1 * HH + h) * DD + d] = a1;
        wq[(2 * HH + h) * DD + d] = a2;
        wq[(3 * HH + h) * DD + d] = a3;
    }
}

// ---------------------------------------------------------------------------
// NT GEMM for small M: C[i,j] = alpha * sum_k A[i*lda+k] * B[j*ldb+k]
template <int MT>
__global__ __launch_bounds__(256) void gemm_nt(const float* __restrict__ A, int lda, long sA,
                                               const float* __restrict__ Bm, int ldb, long sB,
                                               float* __restrict__ C, int ldc, long sC,
                                               int M, int N, int K, float alpha) {
    int batch = blockIdx.y;
    A += (size_t)batch * sA; Bm += (size_t)batch * sB; C += (size_t)batch * sC;
    int warp = threadIdx.x >> 5, lane = threadIdx.x & 31;
    int j = blockIdx.x * 8 + warp;
    __shared__ float As[MT][128];
    float acc[MT];
#pragma unroll
    for (int i = 0; i < MT; i++) acc[i] = 0.f;
    for (int k0 = 0; k0 < K; k0 += 128) {
        __syncthreads();
        for (int i = threadIdx.x; i < MT * 128; i += 256) {
            int r = i >> 7, c = i & 127;
            As[r][c] = (r < M) ? A[(size_t)r * lda + k0 + c] : 0.f;
        }
        __syncthreads();
        const float* bp = Bm + (size_t)j * ldb + k0;
        for (int k = lane; k < 128; k += 32) {
            float bv = bp[k];
#pragma unroll
            for (int i = 0; i < MT; i++) acc[i] += As[i][k] * bv;
        }
    }
#pragma unroll
    for (int i = 0; i < MT; i++) {
        float v = acc[i];
#pragma unroll
        for (int o = 16; o; o >>= 1) v += __shfl_xor_sync(0xffffffffu, v, o);
        if (lane == 0 && i < M) C[(size_t)i * ldc + j] = alpha * v;
    }
}

// ---------------------------------------------------------------------------
// NN GEMM for small M: C[i,j] (+)= alpha*sum_k A[i*lda+k]*B[k*ldb+j] (+bias,act)
template <int MT>
__global__ __launch_bounds__(256) void gemm_nn(const float* __restrict__ A, int lda, long sA,
                                               const float* __restrict__ Bm, int ldb, long sB,
                                               const float* __restrict__ bias,
                                               float* __restrict__ C, int ldc, long sC,
                                               int M, int N, int K, float alpha, int act) {
    int batch = blockIdx.y;
    A += (size_t)batch * sA; Bm += (size_t)batch * sB; C += (size_t)batch * sC;
    int j = blockIdx.x * 256 + threadIdx.x;
    int kChunk = K / gridDim.z;
    int kBeg = blockIdx.z * kChunk;
    float acc[MT];
#pragma unroll
    for (int i = 0; i < MT; i++) acc[i] = 0.f;
    __shared__ float As[MT][32];
    for (int k0 = kBeg; k0 < kBeg + kChunk; k0 += 32) {
        __syncthreads();
        for (int i = threadIdx.x; i < MT * 32; i += 256) {
            int r = i >> 5, c = i & 31;
            As[r][c] = (r < M) ? A[(size_t)r * lda + k0 + c] : 0.f;
        }
        __syncthreads();
#pragma unroll 4
        for (int k = 0; k < 32; k++) {
            float bv = Bm[(size_t)(k0 + k) * ldb + j];
#pragma unroll
            for (int i = 0; i < MT; i++) acc[i] += As[i][k] * bv;
        }
    }
    if (gridDim.z == 1) {
        float bb = bias ? bias[j] : 0.f;
        for (int i = 0; i < MT && i < M; i++) {
            float v = alpha * acc[i] + bb;
            if (act) v = tanhf(v);
            C[(size_t)i * ldc + j] = v;
        }
    } else {
        for (int i = 0; i < MT && i < M; i++)
            atomicAdd(&C[(size_t)i * ldc + j], alpha * acc[i]);
    }
}

// ---------------------------------------------------------------------------
__global__ void softmax_rows(float* __restrict__ base, int n) {
    float* p = base + (size_t)blockIdx.x * n;
    __shared__ float red[8];
    __shared__ float red2[8];
    int tid = threadIdx.x;
    float m = -1e30f;
    for (int j = tid; j < n; j += 256) m = fmaxf(m, p[j]);
#pragma unroll
    for (int o = 16; o; o >>= 1) m = fmaxf(m, __shfl_xor_sync(0xffffffffu, m, o));
    if ((tid & 31) == 0) red[tid >> 5] = m;
    __syncthreads();
    float mm = red[0];
#pragma unroll
    for (int w = 1; w < 8; w++) mm = fmaxf(mm, red[w]);
    float sum = 0.f;
    for (int j = tid; j < n; j += 256) {
        float e = __expf(p[j] - mm);
        p[j] = e;
        sum += e;
    }
#pragma unroll
    for (int o = 16; o; o >>= 1) sum += __shfl_xor_sync(0xffffffffu, sum, o);
    if ((tid & 31) == 0) red2[tid >> 5] = sum;
    __syncthreads();
    float tot = 0.f;
#pragma unroll
    for (int w = 0; w < 8; w++) tot += red2[w];
    float inv = 1.f / tot;
    for (int j = tid; j < n; j += 256) p[j] *= inv;
}

// ---------------------------------------------------------------------------
__global__ void tanh_bias_k(float* __restrict__ x, const float* __restrict__ bias,
                            int n, int total) {
    int i = blockIdx.x * 256 + threadIdx.x;
    if (i < total) x[i] = tanhf(x[i] + bias[i % n]);
}

// text_out[b,s,:] = trow[b,:] + b3[:]
__global__ void bcast_text(const float* __restrict__ trow, const float* __restrict__ b3,
                           float* __restrict__ out) {
    size_t idx = (size_t)blockIdx.x * 256 + threadIdx.x;
    size_t e = idx * 4;
    int b = (int)(e / ((size_t)SS * DD));
    int d = (int)(e % DD);
    float4 t = *(const float4*)&trow[b * DD + d];
    float4 bb = *(const float4*)&b3[d];
    t.x += bb.x; t.y += bb.y; t.z += bb.z; t.w += bb.w;
    *(float4*)&out[e] = t;
}

// ---------------------------------------------------------------------------
extern "C" void kernel_launch(void* const* d_in, const int* in_sizes, int n_in,
                              void* d_out, int out_size) {
    (void)in_sizes; (void)n_in; (void)out_size;
    const float* img      = (const float*)d_in[0];
    const float* text_emb = (const float*)d_in[1];
    const float* qkv_w    = (const float*)d_in[2];
    const float* qkv_b    = (const float*)d_in[3];
    const float* o_w      = (const float*)d_in[4];
    const float* o_b      = (const float*)d_in[5];
    const float* qk_w     = (const float*)d_in[6];
    const float* ctx_qk_w = (const float*)d_in[7];
    const float* v_w      = (const float*)d_in[8];
    const float* ctx_v_w  = (const float*)d_in[9];
    const float* out_w    = (const float*)d_in[10];
    const float* out_b    = (const float*)d_in[11];
    const float* ctx_out_w= (const float*)d_in[12];
    const float* ctx_out_b= (const float*)d_in[13];
    const float* w1 = (const float*)d_in[14];
    const float* b1 = (const float*)d_in[15];
    const float* w2 = (const float*)d_in[16];
    const float* b2 = (const float*)d_in[17];
    const float* w3 = (const float*)d_in[18];
    const float* b3 = (const float*)d_in[19];

    float* out_head = (float*)d_out;            // [4,1024]
    float* out_text = (float*)d_out + BB * DD;  // [4,1024,1024]

    float *p_qkv, *p_vals, *p_qkimg, *p_vv, *p_wq, *p_uq, *p_sim, *p_wvals,
          *p_wtext, *p_outpre, *p_ctxrow, *p_h1, *p_h2, *p_trow;
    cudaGetSymbolAddress((void**)&p_qkv, g_qkv);
    cudaGetSymbolAddress((void**)&p_vals, g_vals);
    cudaGetSymbolAddress((void**)&p_qkimg, g_qkimg);
    cudaGetSymbolAddress((void**)&p_vv, g_vv);
    cudaGetSymbolAddress((void**)&p_wq, g_wq);
    cudaGetSymbolAddress((void**)&p_uq, g_uq);
    cudaGetSymbolAddress((void**)&p_sim, g_sim);
    cudaGetSymbolAddress((void**)&p_wvals, g_wvals);
    cudaGetSymbolAddress((void**)&p_wtext, g_wtext);
    cudaGetSymbolAddress((void**)&p_outpre, g_outpre);
    cudaGetSymbolAddress((void**)&p_ctxrow, g_ctxrow);
    cudaGetSymbolAddress((void**)&p_h1, g_h1);
    cudaGetSymbolAddress((void**)&p_h2, g_h2);
    cudaGetSymbolAddress((void**)&p_trow, g_trow);

    static bool attr_set = false;
    if (!attr_set) {
        cudaFuncSetAttribute((const void*)attn2,
                             cudaFuncAttributeMaxDynamicSharedMemorySize,
                             3 * 64 * PAD * (int)sizeof(float));
        attr_set = true;
    }

    // 0: self-attn QKV GEMM
    sgemm128<<<dim3(3072 / 128, 4096 / 128), 256>>>(text_emb, qkv_w, qkv_b, p_qkv,
                                                    BB * SS, 3 * DD, DD);
    // 1: fused inits
    init_all<<<256, 256>>>(p_qkimg, p_vv, p_outpre, p_wvals, p_h1, p_h2, p_trow,
                           out_head, out_b, p_ctxrow, ctx_out_b, p_wtext, o_b);
    // 2: img projections (qk_w, v_w streams)
    img_proj<<<dim3(INNER / 256, 8, 2), 256>>>(img, qk_w, v_w, p_qkimg, p_vv);
    // 3: wq = per-head ctx_qk_w^T @ qk_img
    wq_kernel<<<2048, 256>>>(ctx_qk_w, p_qkimg, p_wq);
    // 4: uq[bh,m] = sum_n wq[bh,n] * o_w[m,n]
    gemm_nt<64><<<dim3(DD / 8, 1), 256>>>(p_wq, DD, 0, o_w, DD, 0, p_uq, DD, 0,
                                          64, DD, DD, 1.0f);
    // 5: flash attention (profiled launch)
    attn2<<<dim3(BB * HH, SS / 64), 128, 3 * 64 * PAD * sizeof(float)>>>(p_qkv, p_vals);
    // 6: sim[b][h,j] = (1/32) * sum_m uq[bh,m] * vals[b,j,m]
    gemm_nt<16><<<dim3(SS / 8, BB), 256>>>(p_uq, DD, (long)HH * DD,
                                           p_vals, DD, (long)SS * DD,
                                           p_sim, SS, (long)HH * SS,
                                           HH, SS, DD, 1.0f / 32.0f);
    // 7: row softmax over j
    softmax_rows<<<BB * HH, 256>>>(p_sim, SS);
    // 8: wvals[b][h,m] = sum_j attn[h,j] * vals[b,j,m]  (ksplit atomic)
    gemm_nn<16><<<dim3(DD / 256, BB, 8), 256>>>(p_sim, SS, (long)HH * SS,
                                                p_vals, DD, (long)SS * DD,
                                                nullptr, p_wvals, DD, (long)HH * DD,
                                                HH, DD, SS, 1.0f, 0);
    // 9: wtext = wvals @ o_w (+ o_b via init)
    gemm_nn<64><<<dim3(DD / 256, 1, 4), 256>>>(p_wvals, DD, 0, o_w, DD, 0,
                                               nullptr, p_wtext, DD, 0,
                                               64, DD, DD, 1.0f, 0);
    // 10: out_pre[b, h*1024+e] = sum_d wtext[bh,d]*ctx_v_w[d,h*1024+e]
    gemm_nn<4><<<dim3(1024 / 256, HH, 4), 256>>>(p_wtext, HH * DD, (long)DD,
                                                 ctx_v_w, INNER, 1024L,
                                                 nullptr, p_outpre, INNER, 1024L,
                                                 BB, 1024, DD, 1.0f, 0);
    // 11: out = out_pre @ out_w (+ out_b via init)
    gemm_nn<4><<<dim3(DD / 256, 1, 32), 256>>>(p_outpre, INNER, 0, out_w, DD, 0,
                                               nullptr, out_head, DD, 0,
                                               BB, DD, INNER, 1.0f, 0);
    // 12: ctx_row = vv @ ctx_out_w (+ ctx_out_b via init)
    gemm_nn<4><<<dim3(DD / 256, 1, 32), 256>>>(p_vv, INNER, 0, ctx_out_w, DD, 0,
                                               nullptr, p_ctxrow, DD, 0,
                                               BB, DD, INNER, 1.0f, 0);
    // 13-17: tiny MLP on 4 rows (ksplit + tanh/bias epilogues)
    gemm_nn<4><<<dim3(DI2 / 256, 1, 8), 256>>>(p_ctxrow, DD, 0, w1, DI2, 0, nullptr,
                                               p_h1, DI2, 0, BB, DI2, DD, 1.0f, 0);
    tanh_bias_k<<<(BB * DI2 + 255) / 256, 256>>>(p_h1, b1, DI2, BB * DI2);
    gemm_nn<4><<<dim3(DI2 / 256, 1, 16), 256>>>(p_h1, DI2, 0, w2, DI2, 0, nullptr,
                                                p_h2, DI2, 0, BB, DI2, DI2, 1.0f, 0);
    tanh_bias_k<<<(BB * DI2 + 255) / 256, 256>>>(p_h2, b2, DI2, BB * DI2);
    gemm_nn<4><<<dim3(DD / 256, 1, 16), 256>>>(p_h2, DI2, 0, w3, DD, 0, nullptr,
                                               p_trow, DD, 0, BB, DD, DI2, 1.0f, 0);
    // 18: broadcast text_out (+ b3)
    bcast_text<<<(BB * SS * DD / 4) / 256, 256>>>(p_trow, b3, out_text);
}

// round 4
// speedup vs baseline: 2.4256x; 1.2532x over previous
#include <cuda_runtime.h>
#include <cuda_bf16.h>
#include <cstdint>
#include <math.h>

#define BB 4
#define SS 1024
#define DD 1024
#define HH 16
#define INNER 16384
#define DI2 2048
#define PAD 68

// ---- scratch (static device globals; no allocation in kernel_launch) ----
__device__ float g_qkv[BB * SS * 3 * DD];   // 48 MB
__device__ float g_vals[BB * SS * DD];      // 16 MB
__device__ float g_qkimg[BB * INNER];
__device__ float g_vv[BB * INNER];
__device__ float g_wq[BB * HH * DD];
__device__ float g_uq[BB * HH * DD];
__device__ float g_sim[BB * HH * SS];
__device__ float g_wvals[BB * HH * DD];
__device__ float g_wtext[BB * HH * DD];
__device__ float g_outpre[BB * INNER];
__device__ float g_ctxrow[BB * DD];
__device__ float g_h1[BB * DI2];
__device__ float g_h2[BB * DI2];
__device__ float g_trow[BB * DD];
// bf16 split buffers for QKV GEMM
__device__ __nv_bfloat16 g_Ahi[BB * SS * DD];
__device__ __nv_bfloat16 g_Alo[BB * SS * DD];
__device__ __nv_bfloat16 g_Bhi[DD * 3 * DD];
__device__ __nv_bfloat16 g_Blo[DD * 3 * DD];

// ---------------------------------------------------------------------------
__device__ __forceinline__ unsigned s2u(const void* p) {
    return (unsigned)__cvta_generic_to_shared(p);
}
__device__ __forceinline__ void ldsm_x4(unsigned* r, unsigned addr) {
    asm volatile("ldmatrix.sync.aligned.m8n8.x4.shared.b16 {%0,%1,%2,%3}, [%4];"
                 : "=r"(r[0]), "=r"(r[1]), "=r"(r[2]), "=r"(r[3]) : "r"(addr));
}
__device__ __forceinline__ void ldsm_x4t(unsigned* r, unsigned addr) {
    asm volatile("ldmatrix.sync.aligned.m8n8.x4.trans.shared.b16 {%0,%1,%2,%3}, [%4];"
                 : "=r"(r[0]), "=r"(r[1]), "=r"(r[2]), "=r"(r[3]) : "r"(addr));
}
__device__ __forceinline__ void mma_bf16(float* c, const unsigned* a, const unsigned* b) {
    asm volatile(
        "mma.sync.aligned.m16n8k16.row.col.f32.bf16.bf16.f32 "
        "{%0,%1,%2,%3}, {%4,%5,%6,%7}, {%8,%9}, {%0,%1,%2,%3};"
        : "+f"(c[0]), "+f"(c[1]), "+f"(c[2]), "+f"(c[3])
        : "r"(a[0]), "r"(a[1]), "r"(a[2]), "r"(a[3]), "r"(b[0]), "r"(b[1]));
}
__device__ __forceinline__ void cp16(unsigned dst, const void* src) {
    asm volatile("cp.async.cg.shared.global [%0], [%1], 16;" :: "r"(dst), "l"(src));
}
__device__ __forceinline__ void cp_commit() { asm volatile("cp.async.commit_group;"); }
__device__ __forceinline__ void cp_wait1() { asm volatile("cp.async.wait_group 1;"); }
__device__ __forceinline__ void cp_wait0() { asm volatile("cp.async.wait_group 0;"); }

// ---------------------------------------------------------------------------
// split fp32 -> bf16 hi + bf16 lo (residual)
__global__ void split2bf16(const float* __restrict__ x,
                           __nv_bfloat16* __restrict__ hi,
                           __nv_bfloat16* __restrict__ lo, int n4) {
    int i = blockIdx.x * 256 + threadIdx.x;
    if (i >= n4) return;
    float4 v = *(const float4*)&x[i * 4];
    __nv_bfloat16 h0 = __float2bfloat16(v.x);
    __nv_bfloat16 h1 = __float2bfloat16(v.y);
    __nv_bfloat16 h2 = __float2bfloat16(v.z);
    __nv_bfloat16 h3 = __float2bfloat16(v.w);
    __nv_bfloat162 hh0 = __halves2bfloat162(h0, h1);
    __nv_bfloat162 hh1 = __halves2bfloat162(h2, h3);
    *(__nv_bfloat162*)&hi[i * 4] = hh0;
    *(__nv_bfloat162*)&hi[i * 4 + 2] = hh1;
    __nv_bfloat162 ll0 = __halves2bfloat162(
        __float2bfloat16(v.x - __bfloat162float(h0)),
        __float2bfloat16(v.y - __bfloat162float(h1)));
    __nv_bfloat162 ll1 = __halves2bfloat162(
        __float2bfloat16(v.z - __bfloat162float(h2)),
        __float2bfloat16(v.w - __bfloat162float(h3)));
    *(__nv_bfloat162*)&lo[i * 4] = ll0;
    *(__nv_bfloat162*)&lo[i * 4 + 2] = ll1;
}

// ---------------------------------------------------------------------------
// bf16x3 tensor-core GEMM: C[M,N] = Ahi@Bhi + Ahi@Blo + Alo@Bhi + bias
// Tiles: 128x128x32, 256 threads (8 warps, 2x4), warp tile 64x32.
// 2-stage cp.async double buffer.
#define LDA_S 40
#define LDB_S 136
#define STAGE_ELEMS (128 * LDA_S * 2 + 32 * LDB_S * 2)   // Ah,Al,Bh,Bl

__global__ __launch_bounds__(256) void gemm_bf16x3(
    const __nv_bfloat16* __restrict__ Ahi, const __nv_bfloat16* __restrict__ Alo,
    const __nv_bfloat16* __restrict__ Bhi, const __nv_bfloat16* __restrict__ Blo,
    const float* __restrict__ bias, float* __restrict__ C,
    int M, int N, int K) {
    extern __shared__ char dynsm[];
    __nv_bfloat16* smem = (__nv_bfloat16*)dynsm;
    const int tid = threadIdx.x;
    const int warp = tid >> 5, lane = tid & 31;
    const int wm = (warp >> 2) * 64, wn = (warp & 3) * 32;
    const int rowBase = blockIdx.y * 128, colBase = blockIdx.x * 128;

    __nv_bfloat16* sAh[2];
    __nv_bfloat16* sAl[2];
    __nv_bfloat16* sBh[2];
    __nv_bfloat16* sBl[2];
#pragma unroll
    for (int s = 0; s < 2; s++) {
        __nv_bfloat16* base = smem + s * STAGE_ELEMS;
        sAh[s] = base;
        sAl[s] = base + 128 * LDA_S;
        sBh[s] = base + 256 * LDA_S;
        sBl[s] = base + 256 * LDA_S + 32 * LDB_S;
    }

    const int aR0 = (tid * 2) >> 2, aC0 = ((tid * 2) & 3) << 3;
    const int aR1 = (tid * 2 + 1) >> 2, aC1 = ((tid * 2 + 1) & 3) << 3;
    const int bR0 = (tid * 2) >> 4, bC0 = ((tid * 2) & 15) << 3;
    const int bR1 = (tid * 2 + 1) >> 4, bC1 = ((tid * 2 + 1) & 15) << 3;

    float cacc[4][4][4];
#pragma unroll
    for (int i = 0; i < 4; i++)
#pragma unroll
        for (int j = 0; j < 4; j++)
#pragma unroll
            for (int v = 0; v < 4; v++) cacc[i][j][v] = 0.f;

    const int nIter = K / 32;

    // prologue load (stage 0, k0 = 0)
    {
        cp16(s2u(sAh[0] + aR0 * LDA_S + aC0), Ahi + (size_t)(rowBase + aR0) * K + aC0);
        cp16(s2u(sAh[0] + aR1 * LDA_S + aC1), Ahi + (size_t)(rowBase + aR1) * K + aC1);
        cp16(s2u(sAl[0] + aR0 * LDA_S + aC0), Alo + (size_t)(rowBase + aR0) * K + aC0);
        cp16(s2u(sAl[0] + aR1 * LDA_S + aC1), Alo + (size_t)(rowBase + aR1) * K + aC1);
        cp16(s2u(sBh[0] + bR0 * LDB_S + bC0), Bhi + (size_t)bR0 * N + colBase + bC0);
        cp16(s2u(sBh[0] + bR1 * LDB_S + bC1), Bhi + (size_t)bR1 * N + colBase + bC1);
        cp16(s2u(sBl[0] + bR0 * LDB_S + bC0), Blo + (size_t)bR0 * N + colBase + bC0);
        cp16(s2u(sBl[0] + bR1 * LDB_S + bC1), Blo + (size_t)bR1 * N + colBase + bC1);
        cp_commit();
    }

    for (int it = 0; it < nIter; it++) {
        const int cur = it & 1;
        if (it + 1 < nIter) {
            const int nxt = cur ^ 1;
            const int k0 = (it + 1) * 32;
            cp16(s2u(sAh[nxt] + aR0 * LDA_S + aC0), Ahi + (size_t)(rowBase + aR0) * K + k0 + aC0);
            cp16(s2u(sAh[nxt] + aR1 * LDA_S + aC1), Ahi + (size_t)(rowBase + aR1) * K + k0 + aC1);
            cp16(s2u(sAl[nxt] + aR0 * LDA_S + aC0), Alo + (size_t)(rowBase + aR0) * K + k0 + aC0);
            cp16(s2u(sAl[nxt] + aR1 * LDA_S + aC1), Alo + (size_t)(rowBase + aR1) * K + k0 + aC1);
            cp16(s2u(sBh[nxt] + bR0 * LDB_S + bC0), Bhi + (size_t)(k0 + bR0) * N + colBase + bC0);
            cp16(s2u(sBh[nxt] + bR1 * LDB_S + bC1), Bhi + (size_t)(k0 + bR1) * N + colBase + bC1);
            cp16(s2u(sBl[nxt] + bR0 * LDB_S + bC0), Blo + (size_t)(k0 + bR0) * N + colBase + bC0);
            cp16(s2u(sBl[nxt] + bR1 * LDB_S + bC1), Blo + (size_t)(k0 + bR1) * N + colBase + bC1);
            cp_commit();
            cp_wait1();
        } else {
            cp_wait0();
        }
        __syncthreads();

#pragma unroll
        for (int ks = 0; ks < 32; ks += 16) {
            unsigned ah[4][4], al[4][4], bh[2][4], bl[2][4];
            const int arow = (lane & 15);
            const int acol = ks + ((lane >> 4) << 3);
#pragma unroll
            for (int mt = 0; mt < 4; mt++) {
                int off = (wm + mt * 16 + arow) * LDA_S + acol;
                ldsm_x4(ah[mt], s2u(sAh[cur] + off));
                ldsm_x4(al[mt], s2u(sAl[cur] + off));
            }
            const int brow = ks + (lane & 15);
            const int bcol0 = wn + ((lane >> 4) << 3);
#pragma unroll
            for (int nt = 0; nt < 2; nt++) {
                int off = brow * LDB_S + bcol0 + nt * 16;
                ldsm_x4t(bh[nt], s2u(sBh[cur] + off));
                ldsm_x4t(bl[nt], s2u(sBl[cur] + off));
            }
#pragma unroll
            for (int mt = 0; mt < 4; mt++) {
#pragma unroll
                for (int j = 0; j < 4; j++) {
                    const unsigned* bfh = &bh[j >> 1][(j & 1) * 2];
                    const unsigned* bfl = &bl[j >> 1][(j & 1) * 2];
                    mma_bf16(cacc[mt][j], ah[mt], bfh);
                    mma_bf16(cacc[mt][j], ah[mt], bfl);
                    mma_bf16(cacc[mt][j], al[mt], bfh);
                }
            }
        }
        __syncthreads();
    }

    // epilogue
#pragma unroll
    for (int mt = 0; mt < 4; mt++) {
#pragma unroll
        for (int j = 0; j < 4; j++) {
            int r0 = rowBase + wm + mt * 16 + (lane >> 2);
            int c0 = colBase + wn + j * 8 + (lane & 3) * 2;
            float b0 = bias[c0], b1 = bias[c0 + 1];
            float2 v0; v0.x = cacc[mt][j][0] + b0; v0.y = cacc[mt][j][1] + b1;
            float2 v1; v1.x = cacc[mt][j][2] + b0; v1.y = cacc[mt][j][3] + b1;
            *(float2*)&C[(size_t)r0 * N + c0] = v0;
            *(float2*)&C[(size_t)(r0 + 8) * N + c0] = v1;
        }
    }
}

// ---------------------------------------------------------------------------
// Fused init: zeros + bias-seeded buffers. grid 256x256 covers 65536.
__global__ void init_all(float* __restrict__ qkimg, float* __restrict__ vv,
                         float* __restrict__ outpre, float* __restrict__ wvals,
                         float* __restrict__ h1, float* __restrict__ h2,
                         float* __restrict__ trow,
                         float* __restrict__ outh, const float* __restrict__ out_b,
                         float* __restrict__ ctxrow, const float* __restrict__ ctx_out_b,
                         float* __restrict__ wtext, const float* __restrict__ o_b) {
    int i = blockIdx.x * 256 + threadIdx.x;
    qkimg[i] = 0.f; vv[i] = 0.f; outpre[i] = 0.f; wvals[i] = 0.f;
    wtext[i] = o_b[i & 1023];
    if (i < BB * DI2) { h1[i] = 0.f; h2[i] = 0.f; }
    if (i < BB * DD) {
        trow[i] = 0.f;
        outh[i] = out_b[i & 1023];
        ctxrow[i] = ctx_out_b[i & 1023];
    }
}

// ---------------------------------------------------------------------------
// Register-tiled flash attention (fp32).
__global__ __launch_bounds__(128) void attn2(const float* __restrict__ qkv,
                                             float* __restrict__ vals) {
    extern __shared__ char dynsm[];
    float* sm = (float*)dynsm;
    float* Qs = sm;
    float* KP = sm + 64 * PAD;
    float* Vs = sm + 128 * PAD;
    const int bh = blockIdx.x;
    const int b = bh >> 4, h = bh & 15;
    const int qbase = blockIdx.y * 64;
    const float* base = qkv + (size_t)b * SS * 3072 + h * 192;
    const int tid = threadIdx.x;
    const int tx = tid & 15, ty = tid >> 4;
    const int q8 = ty * 8, c4 = tx * 4;

#pragma unroll
    for (int it = 0; it < 8; it++) {
        int idx = it * 128 + tid;
        int q = idx >> 4, d4 = (idx & 15) << 2;
        float4 t = *(const float4*)&base[(size_t)(qbase + q) * 3072 + d4];
        Qs[(d4 + 0) * PAD + q] = t.x * 0.125f;
        Qs[(d4 + 1) * PAD + q] = t.y * 0.125f;
        Qs[(d4 + 2) * PAD + q] = t.z * 0.125f;
        Qs[(d4 + 3) * PAD + q] = t.w * 0.125f;
    }

    float acc[8][4], m[8], l[8];
#pragma unroll
    for (int i = 0; i < 8; i++) {
        m[i] = -1e30f; l[i] = 0.f;
#pragma unroll
        for (int j = 0; j < 4; j++) acc[i][j] = 0.f;
    }

    for (int k0 = 0; k0 < SS; k0 += 64) {
        __syncthreads();
#pragma unroll
        for (int it = 0; it < 8; it++) {
            int idx = it * 128 + tid;
            int k = idx >> 4, d4 = (idx & 15) << 2;
            const float* kp = base + (size_t)(k0 + k) * 3072;
            float4 kk = *(const float4*)&kp[64 + d4];
            KP[(d4 + 0) * PAD + k] = kk.x;
            KP[(d4 + 1) * PAD + k] = kk.y;
            KP[(d4 + 2) * PAD + k] = kk.z;
            KP[(d4 + 3) * PAD + k] = kk.w;
            *(float4*)&Vs[k * PAD + d4] = *(const float4*)&kp[128 + d4];
        }
        __syncthreads();

        float s[8][4];
#pragma unroll
        for (int i = 0; i < 8; i++) { s[i][0] = s[i][1] = s[i][2] = s[i][3] = 0.f; }
#pragma unroll 8
        for (int d = 0; d < 64; d++) {
            float4 qa = *(float4*)&Qs[d * PAD + q8];
            float4 qb = *(float4*)&Qs[d * PAD + q8 + 4];
            float4 kk = *(float4*)&KP[d * PAD + c4];
            float qv[8] = {qa.x, qa.y, qa.z, qa.w, qb.x, qb.y, qb.z, qb.w};
            float kv[4] = {kk.x, kk.y, kk.z, kk.w};
#pragma unroll
            for (int i = 0; i < 8; i++)
#pragma unroll
                for (int j = 0; j < 4; j++) s[i][j] += qv[i] * kv[j];
        }

#pragma unroll
        for (int i = 0; i < 8; i++) {
            float mt = fmaxf(fmaxf(s[i][0], s[i][1]), fmaxf(s[i][2], s[i][3]));
#pragma unroll
            for (int o = 1; o < 16; o <<= 1)
                mt = fmaxf(mt, __shfl_xor_sync(0xffffffffu, mt, o));
            float mn = fmaxf(m[i], mt);
            float corr = __expf(m[i] - mn);
            float ps = 0.f;
#pragma unroll
            for (int j = 0; j < 4; j++) {
                s[i][j] = __expf(s[i][j] - mn);
                ps += s[i][j];
            }
#pragma unroll
            for (int o = 1; o < 16; o <<= 1)
                ps += __shfl_xor_sync(0xffffffffu, ps, o);
            l[i] = l[i] * corr + ps;
            m[i] = mn;
#pragma unroll
            for (int j = 0; j < 4; j++) acc[i][j] *= corr;
        }

        __syncthreads();
#pragma unroll
        for (int i = 0; i < 8; i++)
#pragma unroll
            for (int j = 0; j < 4; j++)
                KP[(c4 + j) * PAD + q8 + i] = s[i][j];
        __syncthreads();

#pragma unroll 8
        for (int k = 0; k < 64; k++) {
            float4 pa = *(float4*)&KP[k * PAD + q8];
            float4 pb = *(float4*)&KP[k * PAD + q8 + 4];
            float4 vv = *(float4*)&Vs[k * PAD + c4];
            float pv[8] = {pa.x, pa.y, pa.z, pa.w, pb.x, pb.y, pb.z, pb.w};
            float vw[4] = {vv.x, vv.y, vv.z, vv.w};
#pragma unroll
            for (int i = 0; i < 8; i++)
#pragma unroll
                for (int j = 0; j < 4; j++) acc[i][j] += pv[i] * vw[j];
        }
    }

#pragma unroll
    for (int i = 0; i < 8; i++) {
        float inv = 1.f / l[i];
        float4 r;
        r.x = acc[i][0] * inv; r.y = acc[i][1] * inv;
        r.z = acc[i][2] * inv; r.w = acc[i][3] * inv;
        *(float4*)&vals[(size_t)(b * SS + qbase + q8 + i) * DD + h * 64 + c4] = r;
    }
}

// ---------------------------------------------------------------------------
__global__ void img_proj(const float* __restrict__ img,
                         const float* __restrict__ W1, const float* __restrict__ W2,
                         float* __restrict__ O1, float* __restrict__ O2) {
    const float* W = blockIdx.z ? W2 : W1;
    float* O = blockIdx.z ? O2 : O1;
    int col = blockIdx.x * 256 + threadIdx.x;
    int k0 = blockIdx.y * 128;
    __shared__ float xs[4][128];
    for (int i = threadIdx.x; i < 512; i += 256)
        xs[i >> 7][i & 127] = img[(i >> 7) * DD + k0 + (i & 127)];
    __syncthreads();
    float a0 = 0, a1 = 0, a2 = 0, a3 = 0;
    const float* wp = W + (size_t)k0 * INNER + col;
#pragma unroll 4
    for (int k = 0; k < 128; k++) {
        float wv = wp[(size_t)k * INNER];
        a0 += xs[0][k] * wv; a1 += xs[1][k] * wv;
        a2 += xs[2][k] * wv; a3 += xs[3][k] * wv;
    }
    atomicAdd(&O[col], a0);
    atomicAdd(&O[INNER + col], a1);
    atomicAdd(&O[2 * INNER + col], a2);
    atomicAdd(&O[3 * INNER + col], a3);
}

// ---------------------------------------------------------------------------
__global__ __launch_bounds__(256) void wq_kernel(const float* __restrict__ Wc,
                                                 const float* __restrict__ qkimg,
                                                 float* __restrict__ wq) {
    int gwarp = (blockIdx.x * 256 + threadIdx.x) >> 5;
    int lane = threadIdx.x & 31;
    int d = gwarp >> 4, h = gwarp & 15;
    const float* row = Wc + (size_t)d * INNER + h * 1024;
    const float* qb = qkimg + h * 1024;
    float a0 = 0, a1 = 0, a2 = 0, a3 = 0;
    for (int e = lane; e < 1024; e += 32) {
        float wv = row[e];
        a0 += wv * qb[e];
        a1 += wv * qb[INNER + e];
        a2 += wv * qb[2 * INNER + e];
        a3 += wv * qb[3 * INNER + e];
    }
#pragma unroll
    for (int o = 16; o; o >>= 1) {
        a0 += __shfl_xor_sync(0xffffffffu, a0, o);
        a1 += __shfl_xor_sync(0xffffffffu, a1, o);
        a2 += __shfl_xor_sync(0xffffffffu, a2, o);
        a3 += __shfl_xor_sync(0xffffffffu, a3, o);
    }
    if (lane == 0) {
        wq[(0 * HH + h) * DD + d] = a0;
        wq[(1 * HH + h) * DD + d] = a1;
        wq[(2 * HH + h) * DD + d] = a2;
        wq[(3 * HH + h) * DD + d] = a3;
    }
}

// ---------------------------------------------------------------------------
template <int MT>
__global__ __launch_bounds__(256) void gemm_nt(const float* __restrict__ A, int lda, long sA,
                                               const float* __restrict__ Bm, int ldb, long sB,
                                               float* __restrict__ C, int ldc, long sC,
                                               int M, int N, int K, float alpha) {
    int batch = blockIdx.y;
    A += (size_t)batch * sA; Bm += (size_t)batch * sB; C += (size_t)batch * sC;
    int warp = threadIdx.x >> 5, lane = threadIdx.x & 31;
    int j = blockIdx.x * 8 + warp;
    __shared__ float As[MT][128];
    float acc[MT];
#pragma unroll
    for (int i = 0; i < MT; i++) acc[i] = 0.f;
    for (int k0 = 0; k0 < K; k0 += 128) {
        __syncthreads();
        for (int i = threadIdx.x; i < MT * 128; i += 256) {
            int r = i >> 7, c = i & 127;
            As[r][c] = (r < M) ? A[(size_t)r * lda + k0 + c] : 0.f;
        }
        __syncthreads();
        const float* bp = Bm + (size_t)j * ldb + k0;
        for (int k = lane; k < 128; k += 32) {
            float bv = bp[k];
#pragma unroll
            for (int i = 0; i < MT; i++) acc[i] += As[i][k] * bv;
        }
    }
#pragma unroll
    for (int i = 0; i < MT; i++) {
        float v = acc[i];
#pragma unroll
        for (int o = 16; o; o >>= 1) v += __shfl_xor_sync(0xffffffffu, v, o);
        if (lane == 0 && i < M) C[(size_t)i * ldc + j] = alpha * v;
    }
}

// ---------------------------------------------------------------------------
template <int MT>
__global__ __launch_bounds__(256) void gemm_nn(const float* __restrict__ A, int lda, long sA,
                                               const float* __restrict__ Bm, int ldb, long sB,
                                               const float* __restrict__ bias,
                                               float* __restrict__ C, int ldc, long sC,
                                               int M, int N, int K, float alpha, int act) {
    int batch = blockIdx.y;
    A += (size_t)batch * sA; Bm += (size_t)batch * sB; C += (size_t)batch * sC;
    int j = blockIdx.x * 256 + threadIdx.x;
    int kChunk = K / gridDim.z;
    int kBeg = blockIdx.z * kChunk;
    float acc[MT];
#pragma unroll
    for (int i = 0; i < MT; i++) acc[i] = 0.f;
    __shared__ float As[MT][32];
    for (int k0 = kBeg; k0 < kBeg + kChunk; k0 += 32) {
        __syncthreads();
        for (int i = threadIdx.x; i < MT * 32; i += 256) {
            int r = i >> 5, c = i & 31;
            As[r][c] = (r < M) ? A[(size_t)r * lda + k0 + c] : 0.f;
        }
        __syncthreads();
#pragma unroll 4
        for (int k = 0; k < 32; k++) {
            float bv = Bm[(size_t)(k0 + k) * ldb + j];
#pragma unroll
            for (int i = 0; i < MT; i++) acc[i] += As[i][k] * bv;
        }
    }
    if (gridDim.z == 1) {
        float bb = bias ? bias[j] : 0.f;
        for (int i = 0; i < MT && i < M; i++) {
            float v = alpha * acc[i] + bb;
            if (act) v = tanhf(v);
            C[(size_t)i * ldc + j] = v;
        }
    } else {
        for (int i = 0; i < MT && i < M; i++)
            atomicAdd(&C[(size_t)i * ldc + j], alpha * acc[i]);
    }
}

// ---------------------------------------------------------------------------
__global__ void softmax_rows(float* __restrict__ base, int n) {
    float* p = base + (size_t)blockIdx.x * n;
    __shared__ float red[8];
    __shared__ float red2[8];
    int tid = threadIdx.x;
    float m = -1e30f;
    for (int j = tid; j < n; j += 256) m = fmaxf(m, p[j]);
#pragma unroll
    for (int o = 16; o; o >>= 1) m = fmaxf(m, __shfl_xor_sync(0xffffffffu, m, o));
    if ((tid & 31) == 0) red[tid >> 5] = m;
    __syncthreads();
    float mm = red[0];
#pragma unroll
    for (int w = 1; w < 8; w++) mm = fmaxf(mm, red[w]);
    float sum = 0.f;
    for (int j = tid; j < n; j += 256) {
        float e = __expf(p[j] - mm);
        p[j] = e;
        sum += e;
    }
#pragma unroll
    for (int o = 16; o; o >>= 1) sum += __shfl_xor_sync(0xffffffffu, sum, o);
    if ((tid & 31) == 0) red2[tid >> 5] = sum;
    __syncthreads();
    float tot = 0.f;
#pragma unroll
    for (int w = 0; w < 8; w++) tot += red2[w];
    float inv = 1.f / tot;
    for (int j = tid; j < n; j += 256) p[j] *= inv;
}

// ---------------------------------------------------------------------------
__global__ void tanh_bias_k(float* __restrict__ x, const float* __restrict__ bias,
                            int n, int total) {
    int i = blockIdx.x * 256 + threadIdx.x;
    if (i < total) x[i] = tanhf(x[i] + bias[i % n]);
}

__global__ void bcast_text(const float* __restrict__ trow, const float* __restrict__ b3,
                           float* __restrict__ out) {
    size_t idx = (size_t)blockIdx.x * 256 + threadIdx.x;
    size_t e = idx * 4;
    int b = (int)(e / ((size_t)SS * DD));
    int d = (int)(e % DD);
    float4 t = *(const float4*)&trow[b * DD + d];
    float4 bb = *(const float4*)&b3[d];
    t.x += bb.x; t.y += bb.y; t.z += bb.z; t.w += bb.w;
    *(float4*)&out[e] = t;
}

// ---------------------------------------------------------------------------
extern "C" void kernel_launch(void* const* d_in, const int* in_sizes, int n_in,
                              void* d_out, int out_size) {
    (void)in_sizes; (void)n_in; (void)out_size;
    const float* img      = (const float*)d_in[0];
    const float* text_emb = (const float*)d_in[1];
    const float* qkv_w    = (const float*)d_in[2];
    const float* qkv_b    = (const float*)d_in[3];
    const float* o_w      = (const float*)d_in[4];
    const float* o_b      = (const float*)d_in[5];
    const float* qk_w     = (const float*)d_in[6];
    const float* ctx_qk_w = (const float*)d_in[7];
    const float* v_w      = (const float*)d_in[8];
    const float* ctx_v_w  = (const float*)d_in[9];
    const float* out_w    = (const float*)d_in[10];
    const float* out_b    = (const float*)d_in[11];
    const float* ctx_out_w= (const float*)d_in[12];
    const float* ctx_out_b= (const float*)d_in[13];
    const float* w1 = (const float*)d_in[14];
    const float* b1 = (const float*)d_in[15];
    const float* w2 = (const float*)d_in[16];
    const float* b2 = (const float*)d_in[17];
    const float* w3 = (const float*)d_in[18];
    const float* b3 = (const float*)d_in[19];

    float* out_head = (float*)d_out;
    float* out_text = (float*)d_out + BB * DD;

    float* p_qkv;    cudaGetSymbolAddress((void**)&p_qkv, g_qkv);
    float* p_vals;   cudaGetSymbolAddress((void**)&p_vals, g_vals);
    float* p_qkimg;  cudaGetSymbolAddress((void**)&p_qkimg, g_qkimg);
    float* p_vv;     cudaGetSymbolAddress((void**)&p_vv, g_vv);
    float* p_wq;     cudaGetSymbolAddress((void**)&p_wq, g_wq);
    float* p_uq;     cudaGetSymbolAddress((void**)&p_uq, g_uq);
    float* p_sim;    cudaGetSymbolAddress((void**)&p_sim, g_sim);
    float* p_wvals;  cudaGetSymbolAddress((void**)&p_wvals, g_wvals);
    float* p_wtext;  cudaGetSymbolAddress((void**)&p_wtext, g_wtext);
    float* p_outpre; cudaGetSymbolAddress((void**)&p_outpre, g_outpre);
    float* p_ctxrow; cudaGetSymbolAddress((void**)&p_ctxrow, g_ctxrow);
    float* p_h1;     cudaGetSymbolAddress((void**)&p_h1, g_h1);
    float* p_h2;     cudaGetSymbolAddress((void**)&p_h2, g_h2);
    float* p_trow;   cudaGetSymbolAddress((void**)&p_trow, g_trow);
    __nv_bfloat16* p_Ahi; cudaGetSymbolAddress((void**)&p_Ahi, g_Ahi);
    __nv_bfloat16* p_Alo; cudaGetSymbolAddress((void**)&p_Alo, g_Alo);
    __nv_bfloat16* p_Bhi; cudaGetSymbolAddress((void**)&p_Bhi, g_Bhi);
    __nv_bfloat16* p_Blo; cudaGetSymbolAddress((void**)&p_Blo, g_Blo);

    static bool attr_set = false;
    if (!attr_set) {
        cudaFuncSetAttribute((const void*)attn2,
                             cudaFuncAttributeMaxDynamicSharedMemorySize,
                             3 * 64 * PAD * (int)sizeof(float));
        cudaFuncSetAttribute((const void*)gemm_bf16x3,
                             cudaFuncAttributeMaxDynamicSharedMemorySize,
                             2 * STAGE_ELEMS * (int)sizeof(__nv_bfloat16));
        attr_set = true;
    }

    // 0-1: split inputs to bf16 hi/lo
    split2bf16<<<(BB * SS * DD / 4 + 255) / 256, 256>>>(text_emb, p_Ahi, p_Alo,
                                                        BB * SS * DD / 4);
    split2bf16<<<(DD * 3 * DD / 4 + 255) / 256, 256>>>(qkv_w, p_Bhi, p_Blo,
                                                       DD * 3 * DD / 4);
    // 2: QKV GEMM on tensor cores (bf16x3)
    gemm_bf16x3<<<dim3(3072 / 128, 4096 / 128), 256,
                  2 * STAGE_ELEMS * sizeof(__nv_bfloat16)>>>(
        p_Ahi, p_Alo, p_Bhi, p_Blo, qkv_b, p_qkv, BB * SS, 3 * DD, DD);
    // 3: fused inits
    init_all<<<256, 256>>>(p_qkimg, p_vv, p_outpre, p_wvals, p_h1, p_h2, p_trow,
                           out_head, out_b, p_ctxrow, ctx_out_b, p_wtext, o_b);
    // 4: img projections
    img_proj<<<dim3(INNER / 256, 8, 2), 256>>>(img, qk_w, v_w, p_qkimg, p_vv);
    // 5: flash attention
    attn2<<<dim3(BB * HH, SS / 64), 128, 3 * 64 * PAD * sizeof(float)>>>(p_qkv, p_vals);
    // 6: wq = per-head ctx_qk_w^T @ qk_img
    wq_kernel<<<2048, 256>>>(ctx_qk_w, p_qkimg, p_wq);
    // 7: uq
    gemm_nt<64><<<dim3(DD / 8, 1), 256>>>(p_wq, DD, 0, o_w, DD, 0, p_uq, DD, 0,
                                          64, DD, DD, 1.0f);
    // 8: sim
    gemm_nt<16><<<dim3(SS / 8, BB), 256>>>(p_uq, DD, (long)HH * DD,
                                           p_vals, DD, (long)SS * DD,
                                           p_sim, SS, (long)HH * SS,
                                           HH, SS, DD, 1.0f / 32.0f);
    // 9: row softmax
    softmax_rows<<<BB * HH, 256>>>(p_sim, SS);
    // 10: wvals (ksplit atomic)
    gemm_nn<16><<<dim3(DD / 256, BB, 8), 256>>>(p_sim, SS, (long)HH * SS,
                                                p_vals, DD, (long)SS * DD,
                                                nullptr, p_wvals, DD, (long)HH * DD,
                                                HH, DD, SS, 1.0f, 0);
    // 11: wtext = wvals @ o_w (+ o_b via init)
    gemm_nn<64><<<dim3(DD / 256, 1, 4), 256>>>(p_wvals, DD, 0, o_w, DD, 0,
                                               nullptr, p_wtext, DD, 0,
                                               64, DD, DD, 1.0f, 0);
    // 12: out_pre
    gemm_nn<4><<<dim3(1024 / 256, HH, 4), 256>>>(p_wtext, HH * DD, (long)DD,
                                                 ctx_v_w, INNER, 1024L,
                                                 nullptr, p_outpre, INNER, 1024L,
                                                 BB, 1024, DD, 1.0f, 0);
    // 13: out head
    gemm_nn<4><<<dim3(DD / 256, 1, 32), 256>>>(p_outpre, INNER, 0, out_w, DD, 0,
                                               nullptr, out_head, DD, 0,
                                               BB, DD, INNER, 1.0f, 0);
    // 14: ctx_row
    gemm_nn<4><<<dim3(DD / 256, 1, 32), 256>>>(p_vv, INNER, 0, ctx_out_w, DD, 0,
                                               nullptr, p_ctxrow, DD, 0,
                                               BB, DD, INNER, 1.0f, 0);
    // 15-19: tiny MLP
    gemm_nn<4><<<dim3(DI2 / 256, 1, 8), 256>>>(p_ctxrow, DD, 0, w1, DI2, 0, nullptr,
                                               p_h1, DI2, 0, BB, DI2, DD, 1.0f, 0);
    tanh_bias_k<<<(BB * DI2 + 255) / 256, 256>>>(p_h1, b1, DI2, BB * DI2);
    gemm_nn<4><<<dim3(DI2 / 256, 1, 16), 256>>>(p_h1, DI2, 0, w2, DI2, 0, nullptr,
                                                p_h2, DI2, 0, BB, DI2, DI2, 1.0f, 0);
    tanh_bias_k<<<(BB * DI2 + 255) / 256, 256>>>(p_h2, b2, DI2, BB * DI2);
    gemm_nn<4><<<dim3(DD / 256, 1, 16), 256>>>(p_h2, DI2, 0, w3, DD, 0, nullptr,
                                               p_trow, DD, 0, BB, DD, DI2, 1.0f, 0);
    // 20: broadcast text_out (+ b3)
    bcast_text<<<(BB * SS * DD / 4) / 256, 256>>>(p_trow, b3, out_text);
}

// round 5
// speedup vs baseline: 2.9247x; 1.2057x over previous
#include <cuda_runtime.h>
#include <cuda_bf16.h>
#include <cstdint>
#include <math.h>

#define BB 4
#define SS 1024
#define DD 1024
#define HH 16
#define INNER 16384
#define DI2 2048
#define PAD 68

// ---- scratch (static device globals; no allocation in kernel_launch) ----
__device__ float g_vals[BB * SS * DD];      // 16 MB
__device__ float g_qkimg[BB * INNER];
__device__ float g_vv[BB * INNER];
__device__ float g_wq[BB * HH * DD];
__device__ float g_uq[BB * HH * DD];
__device__ float g_sim[BB * HH * SS];
__device__ float g_wvals[BB * HH * DD];
__device__ float g_wtext[BB * HH * DD];
__device__ float g_outpre[BB * INNER];
__device__ float g_ctxrow[BB * DD];
__device__ float g_h1[BB * DI2];
__device__ float g_h2[BB * DI2];
__device__ float g_trow[BB * DD];
// bf16 split buffers
__device__ __nv_bfloat16 g_Ahi[BB * SS * DD];
__device__ __nv_bfloat16 g_Alo[BB * SS * DD];
__device__ __nv_bfloat16 g_Bhi[DD * 3 * DD];
__device__ __nv_bfloat16 g_Blo[DD * 3 * DD];
__device__ __nv_bfloat16 g_qkvhi[BB * SS * 3 * DD];   // GEMM output hi
__device__ __nv_bfloat16 g_qkvlo[BB * SS * 3 * DD];   // GEMM output lo

// ---------------------------------------------------------------------------
__device__ __forceinline__ unsigned s2u(const void* p) {
    return (unsigned)__cvta_generic_to_shared(p);
}
__device__ __forceinline__ void ldsm_x4(unsigned* r, unsigned addr) {
    asm volatile("ldmatrix.sync.aligned.m8n8.x4.shared.b16 {%0,%1,%2,%3}, [%4];"
                 : "=r"(r[0]), "=r"(r[1]), "=r"(r[2]), "=r"(r[3]) : "r"(addr));
}
__device__ __forceinline__ void ldsm_x4t(unsigned* r, unsigned addr) {
    asm volatile("ldmatrix.sync.aligned.m8n8.x4.trans.shared.b16 {%0,%1,%2,%3}, [%4];"
                 : "=r"(r[0]), "=r"(r[1]), "=r"(r[2]), "=r"(r[3]) : "r"(addr));
}
__device__ __forceinline__ void mma_bf16(float* c, const unsigned* a,
                                         unsigned b0, unsigned b1) {
    asm volatile(
        "mma.sync.aligned.m16n8k16.row.col.f32.bf16.bf16.f32 "
        "{%0,%1,%2,%3}, {%4,%5,%6,%7}, {%8,%9}, {%0,%1,%2,%3};"
        : "+f"(c[0]), "+f"(c[1]), "+f"(c[2]), "+f"(c[3])
        : "r"(a[0]), "r"(a[1]), "r"(a[2]), "r"(a[3]), "r"(b0), "r"(b1));
}
__device__ __forceinline__ void cp16(unsigned dst, const void* src) {
    asm volatile("cp.async.cg.shared.global [%0], [%1], 16;" :: "r"(dst), "l"(src));
}
__device__ __forceinline__ void cp_commit() { asm volatile("cp.async.commit_group;"); }
__device__ __forceinline__ void cp_wait1() { asm volatile("cp.async.wait_group 1;"); }
__device__ __forceinline__ void cp_wait0() { asm volatile("cp.async.wait_group 0;"); }
__device__ __forceinline__ unsigned packbf(float x, float y) {
    unsigned short a = __bfloat16_as_ushort(__float2bfloat16(x));
    unsigned short b = __bfloat16_as_ushort(__float2bfloat16(y));
    return (unsigned)a | ((unsigned)b << 16);
}

// ---------------------------------------------------------------------------
// split fp32 -> bf16 hi + bf16 lo (residual)
__global__ void split2bf16(const float* __restrict__ x,
                           __nv_bfloat16* __restrict__ hi,
                           __nv_bfloat16* __restrict__ lo, int n4) {
    int i = blockIdx.x * 256 + threadIdx.x;
    if (i >= n4) return;
    float4 v = *(const float4*)&x[i * 4];
    __nv_bfloat16 h0 = __float2bfloat16(v.x);
    __nv_bfloat16 h1 = __float2bfloat16(v.y);
    __nv_bfloat16 h2 = __float2bfloat16(v.z);
    __nv_bfloat16 h3 = __float2bfloat16(v.w);
    *(__nv_bfloat162*)&hi[i * 4] = __halves2bfloat162(h0, h1);
    *(__nv_bfloat162*)&hi[i * 4 + 2] = __halves2bfloat162(h2, h3);
    *(__nv_bfloat162*)&lo[i * 4] = __halves2bfloat162(
        __float2bfloat16(v.x - __bfloat162float(h0)),
        __float2bfloat16(v.y - __bfloat162float(h1)));
    *(__nv_bfloat162*)&lo[i * 4 + 2] = __halves2bfloat162(
        __float2bfloat16(v.z - __bfloat162float(h2)),
        __float2bfloat16(v.w - __bfloat162float(h3)));
}

// ---------------------------------------------------------------------------
// bf16x3 tensor-core GEMM; epilogue emits bf16 hi/lo split of (acc + bias).
#define LDA_S 40
#define LDB_S 136
#define STAGE_ELEMS (128 * LDA_S * 2 + 32 * LDB_S * 2)

__global__ __launch_bounds__(256) void gemm_bf16x3(
    const __nv_bfloat16* __restrict__ Ahi, const __nv_bfloat16* __restrict__ Alo,
    const __nv_bfloat16* __restrict__ Bhi, const __nv_bfloat16* __restrict__ Blo,
    const float* __restrict__ bias,
    __nv_bfloat16* __restrict__ Chi, __nv_bfloat16* __restrict__ Clo,
    int M, int N, int K) {
    extern __shared__ char dynsm[];
    __nv_bfloat16* smem = (__nv_bfloat16*)dynsm;
    const int tid = threadIdx.x;
    const int warp = tid >> 5, lane = tid & 31;
    const int wm = (warp >> 2) * 64, wn = (warp & 3) * 32;
    const int rowBase = blockIdx.y * 128, colBase = blockIdx.x * 128;

    __nv_bfloat16* sAh[2];
    __nv_bfloat16* sAl[2];
    __nv_bfloat16* sBh[2];
    __nv_bfloat16* sBl[2];
#pragma unroll
    for (int s = 0; s < 2; s++) {
        __nv_bfloat16* base = smem + s * STAGE_ELEMS;
        sAh[s] = base;
        sAl[s] = base + 128 * LDA_S;
        sBh[s] = base + 256 * LDA_S;
        sBl[s] = base + 256 * LDA_S + 32 * LDB_S;
    }

    const int aR0 = (tid * 2) >> 2, aC0 = ((tid * 2) & 3) << 3;
    const int aR1 = (tid * 2 + 1) >> 2, aC1 = ((tid * 2 + 1) & 3) << 3;
    const int bR0 = (tid * 2) >> 4, bC0 = ((tid * 2) & 15) << 3;
    const int bR1 = (tid * 2 + 1) >> 4, bC1 = ((tid * 2 + 1) & 15) << 3;

    float cacc[4][4][4];
#pragma unroll
    for (int i = 0; i < 4; i++)
#pragma unroll
        for (int j = 0; j < 4; j++)
#pragma unroll
            for (int v = 0; v < 4; v++) cacc[i][j][v] = 0.f;

    const int nIter = K / 32;
    {
        cp16(s2u(sAh[0] + aR0 * LDA_S + aC0), Ahi + (size_t)(rowBase + aR0) * K + aC0);
        cp16(s2u(sAh[0] + aR1 * LDA_S + aC1), Ahi + (size_t)(rowBase + aR1) * K + aC1);
        cp16(s2u(sAl[0] + aR0 * LDA_S + aC0), Alo + (size_t)(rowBase + aR0) * K + aC0);
        cp16(s2u(sAl[0] + aR1 * LDA_S + aC1), Alo + (size_t)(rowBase + aR1) * K + aC1);
        cp16(s2u(sBh[0] + bR0 * LDB_S + bC0), Bhi + (size_t)bR0 * N + colBase + bC0);
        cp16(s2u(sBh[0] + bR1 * LDB_S + bC1), Bhi + (size_t)bR1 * N + colBase + bC1);
        cp16(s2u(sBl[0] + bR0 * LDB_S + bC0), Blo + (size_t)bR0 * N + colBase + bC0);
        cp16(s2u(sBl[0] + bR1 * LDB_S + bC1), Blo + (size_t)bR1 * N + colBase + bC1);
        cp_commit();
    }

    for (int it = 0; it < nIter; it++) {
        const int cur = it & 1;
        if (it + 1 < nIter) {
            const int nxt = cur ^ 1;
            const int k0 = (it + 1) * 32;
            cp16(s2u(sAh[nxt] + aR0 * LDA_S + aC0), Ahi + (size_t)(rowBase + aR0) * K + k0 + aC0);
            cp16(s2u(sAh[nxt] + aR1 * LDA_S + aC1), Ahi + (size_t)(rowBase + aR1) * K + k0 + aC1);
            cp16(s2u(sAl[nxt] + aR0 * LDA_S + aC0), Alo + (size_t)(rowBase + aR0) * K + k0 + aC0);
            cp16(s2u(sAl[nxt] + aR1 * LDA_S + aC1), Alo + (size_t)(rowBase + aR1) * K + k0 + aC1);
            cp16(s2u(sBh[nxt] + bR0 * LDB_S + bC0), Bhi + (size_t)(k0 + bR0) * N + colBase + bC0);
            cp16(s2u(sBh[nxt] + bR1 * LDB_S + bC1), Bhi + (size_t)(k0 + bR1) * N + colBase + bC1);
            cp16(s2u(sBl[nxt] + bR0 * LDB_S + bC0), Blo + (size_t)(k0 + bR0) * N + colBase + bC0);
            cp16(s2u(sBl[nxt] + bR1 * LDB_S + bC1), Blo + (size_t)(k0 + bR1) * N + colBase + bC1);
            cp_commit();
            cp_wait1();
        } else {
            cp_wait0();
        }
        __syncthreads();

#pragma unroll
        for (int ks = 0; ks < 32; ks += 16) {
            unsigned ah[4][4], al[4][4], bh[2][4], bl[2][4];
            const int arow = (lane & 15);
            const int acol = ks + ((lane >> 4) << 3);
#pragma unroll
            for (int mt = 0; mt < 4; mt++) {
                int off = (wm + mt * 16 + arow) * LDA_S + acol;
                ldsm_x4(ah[mt], s2u(sAh[cur] + off));
                ldsm_x4(al[mt], s2u(sAl[cur] + off));
            }
            const int brow = ks + (lane & 15);
            const int bcol0 = wn + ((lane >> 4) << 3);
#pragma unroll
            for (int nt = 0; nt < 2; nt++) {
                int off = brow * LDB_S + bcol0 + nt * 16;
                ldsm_x4t(bh[nt], s2u(sBh[cur] + off));
                ldsm_x4t(bl[nt], s2u(sBl[cur] + off));
            }
#pragma unroll
            for (int mt = 0; mt < 4; mt++) {
#pragma unroll
                for (int j = 0; j < 4; j++) {
                    unsigned bh0 = bh[j >> 1][(j & 1) * 2], bh1 = bh[j >> 1][(j & 1) * 2 + 1];
                    unsigned bl0 = bl[j >> 1][(j & 1) * 2], bl1 = bl[j >> 1][(j & 1) * 2 + 1];
                    mma_bf16(cacc[mt][j], ah[mt], bh0, bh1);
                    mma_bf16(cacc[mt][j], ah[mt], bl0, bl1);
                    mma_bf16(cacc[mt][j], al[mt], bh0, bh1);
                }
            }
        }
        __syncthreads();
    }

    // epilogue: hi/lo bf16 split of acc+bias
#pragma unroll
    for (int mt = 0; mt < 4; mt++) {
#pragma unroll
        for (int j = 0; j < 4; j++) {
            int r0 = rowBase + wm + mt * 16 + (lane >> 2);
            int c0 = colBase + wn + j * 8 + (lane & 3) * 2;
            float b0 = bias[c0], b1 = bias[c0 + 1];
#pragma unroll
            for (int half = 0; half < 2; half++) {
                int r = r0 + half * 8;
                float x = cacc[mt][j][half * 2 + 0] + b0;
                float y = cacc[mt][j][half * 2 + 1] + b1;
                __nv_bfloat16 hx = __float2bfloat16(x);
                __nv_bfloat16 hy = __float2bfloat16(y);
                *(__nv_bfloat162*)&Chi[(size_t)r * N + c0] = __halves2bfloat162(hx, hy);
                *(__nv_bfloat162*)&Clo[(size_t)r * N + c0] = __halves2bfloat162(
                    __float2bfloat16(x - __bfloat162float(hx)),
                    __float2bfloat16(y - __bfloat162float(hy)));
            }
        }
    }
}

// ---------------------------------------------------------------------------
// Tensor-core flash attention (bf16x3). Block: 64 q rows of one (b,h);
// 128 threads (4 warps x 16 q rows). K/V tiles 64, cp.async double buffered.
#define SA 72
#define ATT_STAGE (4 * 64 * SA)      // Khi,Klo,Vhi,Vlo
#define ATT_SMEM ((2 * 64 * SA + 2 * ATT_STAGE) * 2)   // bytes

__global__ __launch_bounds__(128) void attn3(const __nv_bfloat16* __restrict__ qkvhi,
                                             const __nv_bfloat16* __restrict__ qkvlo,
                                             float* __restrict__ vals) {
    extern __shared__ char dynsm[];
    __nv_bfloat16* SM = (__nv_bfloat16*)dynsm;
    __nv_bfloat16* Qhi = SM;
    __nv_bfloat16* Qlo = SM + 64 * SA;
    const int tid = threadIdx.x;
    const int warp = tid >> 5, lane = tid & 31;
    const int b = blockIdx.x >> 4, h = blockIdx.x & 15;
    const int qbase = blockIdx.y * 64;
    const size_t gbase = (size_t)b * SS * 3072 + h * 192;

    // prologue: Q chunks + stage0 K/V chunks (one group)
    {
#pragma unroll
        for (int i = 0; i < 4; i++) {
            int c = i * 128 + tid;               // 0..511
            int row = c >> 3, col = (c & 7) << 3;
            size_t src = gbase + (size_t)(qbase + row) * 3072 + col;
            cp16(s2u(Qhi + row * SA + col), qkvhi + src);
            cp16(s2u(Qlo + row * SA + col), qkvlo + src);
        }
        __nv_bfloat16* st = SM + 2 * 64 * SA;     // stage 0
#pragma unroll
        for (int i = 0; i < 4; i++) {
            int c = i * 128 + tid;
            int row = c >> 3, col = (c & 7) << 3;
            size_t srcK = gbase + (size_t)row * 3072 + 64 + col;
            size_t srcV = gbase + (size_t)row * 3072 + 128 + col;
            cp16(s2u(st + row * SA + col), qkvhi + srcK);
            cp16(s2u(st + 64 * SA + row * SA + col), qkvlo + srcK);
            cp16(s2u(st + 2 * 64 * SA + row * SA + col), qkvhi + srcV);
            cp16(s2u(st + 3 * 64 * SA + row * SA + col), qkvlo + srcV);
        }
        cp_commit();
    }

    unsigned qh[4][4], ql[4][4];
    float o[8][4];
    float m0 = -1e30f, m1 = -1e30f, l0 = 0.f, l1 = 0.f;
#pragma unroll
    for (int i = 0; i < 8; i++)
#pragma unroll
        for (int j = 0; j < 4; j++) o[i][j] = 0.f;

    const int NT = SS / 64;
    for (int t = 0; t < NT; t++) {
        const int cur = t & 1;
        if (t + 1 < NT) {
            __nv_bfloat16* st = SM + 2 * 64 * SA + (cur ^ 1) * ATT_STAGE;
            const int kv0 = (t + 1) * 64;
#pragma unroll
            for (int i = 0; i < 4; i++) {
                int c = i * 128 + tid;
                int row = c >> 3, col = (c & 7) << 3;
                size_t srcK = gbase + (size_t)(kv0 + row) * 3072 + 64 + col;
                size_t srcV = gbase + (size_t)(kv0 + row) * 3072 + 128 + col;
                cp16(s2u(st + row * SA + col), qkvhi + srcK);
                cp16(s2u(st + 64 * SA + row * SA + col), qkvlo + srcK);
                cp16(s2u(st + 2 * 64 * SA + row * SA + col), qkvhi + srcV);
                cp16(s2u(st + 3 * 64 * SA + row * SA + col), qkvlo + srcV);
            }
            cp_commit();
            cp_wait1();
        } else {
            cp_wait0();
        }
        __syncthreads();

        if (t == 0) {
            // Q fragments (constant across kv tiles)
#pragma unroll
            for (int kt = 0; kt < 4; kt++) {
                int off = (warp * 16 + (lane & 15)) * SA + kt * 16 + ((lane >> 4) << 3);
                ldsm_x4(qh[kt], s2u(Qhi + off));
                ldsm_x4(ql[kt], s2u(Qlo + off));
            }
        }

        __nv_bfloat16* sKh = SM + 2 * 64 * SA + cur * ATT_STAGE;
        __nv_bfloat16* sKl = sKh + 64 * SA;
        __nv_bfloat16* sVh = sKh + 2 * 64 * SA;
        __nv_bfloat16* sVl = sKh + 3 * 64 * SA;

        // ---- scores S = (Q . K^T) * 0.125, bf16x3 ----
        float sc[8][4];
#pragma unroll
        for (int n = 0; n < 8; n++)
#pragma unroll
            for (int v = 0; v < 4; v++) sc[n][v] = 0.f;
#pragma unroll
        for (int kt = 0; kt < 4; kt++) {
            unsigned kh[4][4], kl[4][4];
#pragma unroll
            for (int nt = 0; nt < 4; nt++) {
                int off = (nt * 16 + (lane & 15)) * SA + kt * 16 + ((lane >> 4) << 3);
                ldsm_x4(kh[nt], s2u(sKh + off));
                ldsm_x4(kl[nt], s2u(sKl + off));
            }
#pragma unroll
            for (int nt = 0; nt < 4; nt++) {
#pragma unroll
                for (int sub = 0; sub < 2; sub++) {
                    int n = nt * 2 + sub;
                    mma_bf16(sc[n], qh[kt], kh[nt][sub], kh[nt][sub + 2]);
                    mma_bf16(sc[n], qh[kt], kl[nt][sub], kl[nt][sub + 2]);
                    mma_bf16(sc[n], ql[kt], kh[nt][sub], kh[nt][sub + 2]);
                }
            }
        }
#pragma unroll
        for (int n = 0; n < 8; n++)
#pragma unroll
            for (int v = 0; v < 4; v++) sc[n][v] *= 0.125f;

        // ---- online softmax (rows: r0 = lane>>2, r1 = r0+8; quad = lane&3) ----
        float mt0 = -1e30f, mt1 = -1e30f;
#pragma unroll
        for (int n = 0; n < 8; n++) {
            mt0 = fmaxf(mt0, fmaxf(sc[n][0], sc[n][1]));
            mt1 = fmaxf(mt1, fmaxf(sc[n][2], sc[n][3]));
        }
        mt0 = fmaxf(mt0, __shfl_xor_sync(0xffffffffu, mt0, 1));
        mt0 = fmaxf(mt0, __shfl_xor_sync(0xffffffffu, mt0, 2));
        mt1 = fmaxf(mt1, __shfl_xor_sync(0xffffffffu, mt1, 1));
        mt1 = fmaxf(mt1, __shfl_xor_sync(0xffffffffu, mt1, 2));
        float mn0 = fmaxf(m0, mt0), mn1 = fmaxf(m1, mt1);
        float cr0 = __expf(m0 - mn0), cr1 = __expf(m1 - mn1);
        float s0 = 0.f, s1 = 0.f;
#pragma unroll
        for (int n = 0; n < 8; n++) {
            sc[n][0] = __expf(sc[n][0] - mn0);
            sc[n][1] = __expf(sc[n][1] - mn0);
            sc[n][2] = __expf(sc[n][2] - mn1);
            sc[n][3] = __expf(sc[n][3] - mn1);
            s0 += sc[n][0] + sc[n][1];
            s1 += sc[n][2] + sc[n][3];
        }
        s0 += __shfl_xor_sync(0xffffffffu, s0, 1);
        s0 += __shfl_xor_sync(0xffffffffu, s0, 2);
        s1 += __shfl_xor_sync(0xffffffffu, s1, 1);
        s1 += __shfl_xor_sync(0xffffffffu, s1, 2);
        l0 = l0 * cr0 + s0; l1 = l1 * cr1 + s1;
        m0 = mn0; m1 = mn1;
#pragma unroll
        for (int d = 0; d < 8; d++) {
            o[d][0] *= cr0; o[d][1] *= cr0;
            o[d][2] *= cr1; o[d][3] *= cr1;
        }

        // ---- P hi/lo fragments (C-frag layout == A-frag layout) ----
        unsigned ph[4][4], pl[4][4];
#pragma unroll
        for (int kt2 = 0; kt2 < 4; kt2++) {
#pragma unroll
            for (int part = 0; part < 4; part++) {
                int n = kt2 * 2 + (part >> 1);
                int i0 = (part & 1) * 2;
                float x = sc[n][i0], y = sc[n][i0 + 1];
                __nv_bfloat16 hx = __float2bfloat16(x);
                __nv_bfloat16 hy = __float2bfloat16(y);
                ph[kt2][part] = (unsigned)__bfloat16_as_ushort(hx) |
                                ((unsigned)__bfloat16_as_ushort(hy) << 16);
                pl[kt2][part] = packbf(x - __bfloat162float(hx),
                                       y - __bfloat162float(hy));
            }
        }
        // wait: part order must be a0=(n even, regs 0,1), a1=(n even, 2,3),
        // a2=(n odd, 0,1), a3=(n odd, 2,3). part>>1 gives 0,0,1,1 (n sel) and
        // part&1 gives 0,1,0,1 (reg pair) -> a1=(even,2,3) OK matches.

        // ---- O += P @ V, bf16x3 ----
#pragma unroll
        for (int kt2 = 0; kt2 < 4; kt2++) {
            unsigned vh[4][4], vl[4][4];
#pragma unroll
            for (int dt = 0; dt < 4; dt++) {
                int off = (kt2 * 16 + (lane & 15)) * SA + dt * 16 + ((lane >> 4) << 3);
                ldsm_x4t(vh[dt], s2u(sVh + off));
                ldsm_x4t(vl[dt], s2u(sVl + off));
            }
#pragma unroll
            for (int dt = 0; dt < 4; dt++) {
#pragma unroll
                for (int sub = 0; sub < 2; sub++) {
                    int d = dt * 2 + sub;
                    mma_bf16(o[d], ph[kt2], vh[dt][sub * 2], vh[dt][sub * 2 + 1]);
                    mma_bf16(o[d], ph[kt2], vl[dt][sub * 2], vl[dt][sub * 2 + 1]);
                    mma_bf16(o[d], pl[kt2], vh[dt][sub * 2], vh[dt][sub * 2 + 1]);
                }
            }
        }
        __syncthreads();
    }

    // ---- epilogue ----
    float inv0 = 1.f / l0, inv1 = 1.f / l1;
    int row0 = qbase + warp * 16 + (lane >> 2);
    int row1 = row0 + 8;
#pragma unroll
    for (int d = 0; d < 8; d++) {
        int c0 = h * 64 + d * 8 + (lane & 3) * 2;
        float2 v0; v0.x = o[d][0] * inv0; v0.y = o[d][1] * inv0;
        float2 v1; v1.x = o[d][2] * inv1; v1.y = o[d][3] * inv1;
        *(float2*)&vals[(size_t)(b * SS + row0) * DD + c0] = v0;
        *(float2*)&vals[(size_t)(b * SS + row1) * DD + c0] = v1;
    }
}

// ---------------------------------------------------------------------------
__global__ void init_all(float* __restrict__ qkimg, float* __restrict__ vv,
                         float* __restrict__ outpre, float* __restrict__ wvals,
                         float* __restrict__ h1, float* __restrict__ h2,
                         float* __restrict__ trow,
                         float* __restrict__ outh, const float* __restrict__ out_b,
                         float* __restrict__ ctxrow, const float* __restrict__ ctx_out_b,
                         float* __restrict__ wtext, const float* __restrict__ o_b) {
    int i = blockIdx.x * 256 + threadIdx.x;
    qkimg[i] = 0.f; vv[i] = 0.f; outpre[i] = 0.f; wvals[i] = 0.f;
    wtext[i] = o_b[i & 1023];
    if (i < BB * DI2) { h1[i] = 0.f; h2[i] = 0.f; }
    if (i < BB * DD) {
        trow[i] = 0.f;
        outh[i] = out_b[i & 1023];
        ctxrow[i] = ctx_out_b[i & 1023];
    }
}

// ---------------------------------------------------------------------------
__global__ void img_proj(const float* __restrict__ img,
                         const float* __restrict__ W1, const float* __restrict__ W2,
                         float* __restrict__ O1, float* __restrict__ O2) {
    const float* W = blockIdx.z ? W2 : W1;
    float* O = blockIdx.z ? O2 : O1;
    int col = blockIdx.x * 256 + threadIdx.x;
    int k0 = blockIdx.y * 128;
    __shared__ float xs[4][128];
    for (int i = threadIdx.x; i < 512; i += 256)
        xs[i >> 7][i & 127] = img[(i >> 7) * DD + k0 + (i & 127)];
    __syncthreads();
    float a0 = 0, a1 = 0, a2 = 0, a3 = 0;
    const float* wp = W + (size_t)k0 * INNER + col;
#pragma unroll 4
    for (int k = 0; k < 128; k++) {
        float wv = wp[(size_t)k * INNER];
        a0 += xs[0][k] * wv; a1 += xs[1][k] * wv;
        a2 += xs[2][k] * wv; a3 += xs[3][k] * wv;
    }
    atomicAdd(&O[col], a0);
    atomicAdd(&O[INNER + col], a1);
    atomicAdd(&O[2 * INNER + col], a2);
    atomicAdd(&O[3 * INNER + col], a3);
}

// ---------------------------------------------------------------------------
__global__ __launch_bounds__(256) void wq_kernel(const float* __restrict__ Wc,
                                                 const float* __restrict__ qkimg,
                                                 float* __restrict__ wq) {
    int gwarp = (blockIdx.x * 256 + threadIdx.x) >> 5;
    int lane = threadIdx.x & 31;
    int d = gwarp >> 4, h = gwarp & 15;
    const float* row = Wc + (size_t)d * INNER + h * 1024;
    const float* qb = qkimg + h * 1024;
    float a0 = 0, a1 = 0, a2 = 0, a3 = 0;
    for (int e = lane; e < 1024; e += 32) {
        float wv = row[e];
        a0 += wv * qb[e];
        a1 += wv * qb[INNER + e];
        a2 += wv * qb[2 * INNER + e];
        a3 += wv * qb[3 * INNER + e];
    }
#pragma unroll
    for (int o = 16; o; o >>= 1) {
        a0 += __shfl_xor_sync(0xffffffffu, a0, o);
        a1 += __shfl_xor_sync(0xffffffffu, a1, o);
        a2 += __shfl_xor_sync(0xffffffffu, a2, o);
        a3 += __shfl_xor_sync(0xffffffffu, a3, o);
    }
    if (lane == 0) {
        wq[(0 * HH + h) * DD + d] = a0;
        wq[(1 * HH + h) * DD + d] = a1;
        wq[(2 * HH + h) * DD + d] = a2;
        wq[(3 * HH + h) * DD + d] = a3;
    }
}

// ---------------------------------------------------------------------------
template <int MT>
__global__ __launch_bounds__(256) void gemm_nt(const float* __restrict__ A, int lda, long sA,
                                               const float* __restrict__ Bm, int ldb, long sB,
                                               float* __restrict__ C, int ldc, long sC,
                                               int M, int N, int K, float alpha) {
    int batch = blockIdx.y;
    A += (size_t)batch * sA; Bm += (size_t)batch * sB; C += (size_t)batch * sC;
    int warp = threadIdx.x >> 5, lane = threadIdx.x & 31;
    int j = blockIdx.x * 8 + warp;
    __shared__ float As[MT][128];
    float acc[MT];
#pragma unroll
    for (int i = 0; i < MT; i++) acc[i] = 0.f;
    for (int k0 = 0; k0 < K; k0 += 128) {
        __syncthreads();
        for (int i = threadIdx.x; i < MT * 128; i += 256) {
            int r = i >> 7, c = i & 127;
            As[r][c] = (r < M) ? A[(size_t)r * lda + k0 + c] : 0.f;
        }
        __syncthreads();
        const float* bp = Bm + (size_t)j * ldb + k0;
        for (int k = lane; k < 128; k += 32) {
            float bv = bp[k];
#pragma unroll
            for (int i = 0; i < MT; i++) acc[i] += As[i][k] * bv;
        }
    }
#pragma unroll
    for (int i = 0; i < MT; i++) {
        float v = acc[i];
#pragma unroll
        for (int o = 16; o; o >>= 1) v += __shfl_xor_sync(0xffffffffu, v, o);
        if (lane == 0 && i < M) C[(size_t)i * ldc + j] = alpha * v;
    }
}

// ---------------------------------------------------------------------------
template <int MT>
__global__ __launch_bounds__(256) void gemm_nn(const float* __restrict__ A, int lda, long sA,
                                               const float* __restrict__ Bm, int ldb, long sB,
                                               const float* __restrict__ bias,
                                               float* __restrict__ C, int ldc, long sC,
                                               int M, int N, int K, float alpha, int act) {
    int batch = blockIdx.y;
    A += (size_t)batch * sA; Bm += (size_t)batch * sB; C += (size_t)batch * sC;
    int j = blockIdx.x * 256 + threadIdx.x;
    int kChunk = K / gridDim.z;
    int kBeg = blockIdx.z * kChunk;
    float acc[MT];
#pragma unroll
    for (int i = 0; i < MT; i++) acc[i] = 0.f;
    __shared__ float As[MT][32];
    for (int k0 = kBeg; k0 < kBeg + kChunk; k0 += 32) {
        __syncthreads();
        for (int i = threadIdx.x; i < MT * 32; i += 256) {
            int r = i >> 5, c = i & 31;
            As[r][c] = (r < M) ? A[(size_t)r * lda + k0 + c] : 0.f;
        }
        __syncthreads();
#pragma unroll 4
        for (int k = 0; k < 32; k++) {
            float bv = Bm[(size_t)(k0 + k) * ldb + j];
#pragma unroll
            for (int i = 0; i < MT; i++) acc[i] += As[i][k] * bv;
        }
    }
    if (gridDim.z == 1) {
        float bb = bias ? bias[j] : 0.f;
        for (int i = 0; i < MT && i < M; i++) {
            float v = alpha * acc[i] + bb;
            if (act) v = tanhf(v);
            C[(size_t)i * ldc + j] = v;
        }
    } else {
        for (int i = 0; i < MT && i < M; i++)
            atomicAdd(&C[(size_t)i * ldc + j], alpha * acc[i]);
    }
}

// ---------------------------------------------------------------------------
__global__ void softmax_rows(float* __restrict__ base, int n) {
    float* p = base + (size_t)blockIdx.x * n;
    __shared__ float red[8];
    __shared__ float red2[8];
    int tid = threadIdx.x;
    float m = -1e30f;
    for (int j = tid; j < n; j += 256) m = fmaxf(m, p[j]);
#pragma unroll
    for (int o = 16; o; o >>= 1) m = fmaxf(m, __shfl_xor_sync(0xffffffffu, m, o));
    if ((tid & 31) == 0) red[tid >> 5] = m;
    __syncthreads();
    float mm = red[0];
#pragma unroll
    for (int w = 1; w < 8; w++) mm = fmaxf(mm, red[w]);
    float sum = 0.f;
    for (int j = tid; j < n; j += 256) {
        float e = __expf(p[j] - mm);
        p[j] = e;
        sum += e;
    }
#pragma unroll
    for (int o = 16; o; o >>= 1) sum += __shfl_xor_sync(0xffffffffu, sum, o);
    if ((tid & 31) == 0) red2[tid >> 5] = sum;
    __syncthreads();
    float tot = 0.f;
#pragma unroll
    for (int w = 0; w < 8; w++) tot += red2[w];
    float inv = 1.f / tot;
    for (int j = tid; j < n; j += 256) p[j] *= inv;
}

// ---------------------------------------------------------------------------
__global__ void tanh_bias_k(float* __restrict__ x, const float* __restrict__ bias,
                            int n, int total) {
    int i = blockIdx.x * 256 + threadIdx.x;
    if (i < total) x[i] = tanhf(x[i] + bias[i % n]);
}

__global__ void bcast_text(const float* __restrict__ trow, const float* __restrict__ b3,
                           float* __restrict__ out) {
    size_t idx = (size_t)blockIdx.x * 256 + threadIdx.x;
    size_t e = idx * 4;
    int b = (int)(e / ((size_t)SS * DD));
    int d = (int)(e % DD);
    float4 t = *(const float4*)&trow[b * DD + d];
    float4 bb = *(const float4*)&b3[d];
    t.x += bb.x; t.y += bb.y; t.z += bb.z; t.w += bb.w;
    *(float4*)&out[e] = t;
}

// ---------------------------------------------------------------------------
extern "C" void kernel_launch(void* const* d_in, const int* in_sizes, int n_in,
                              void* d_out, int out_size) {
    (void)in_sizes; (void)n_in; (void)out_size;
    const float* img      = (const float*)d_in[0];
    const float* text_emb = (const float*)d_in[1];
    const float* qkv_w    = (const float*)d_in[2];
    const float* qkv_b    = (const float*)d_in[3];
    const float* o_w      = (const float*)d_in[4];
    const float* o_b      = (const float*)d_in[5];
    const float* qk_w     = (const float*)d_in[6];
    const float* ctx_qk_w = (const float*)d_in[7];
    const float* v_w      = (const float*)d_in[8];
    const float* ctx_v_w  = (const float*)d_in[9];
    const float* out_w    = (const float*)d_in[10];
    const float* out_b    = (const float*)d_in[11];
    const float* ctx_out_w= (const float*)d_in[12];
    const float* ctx_out_b= (const float*)d_in[13];
    const float* w1 = (const float*)d_in[14];
    const float* b1 = (const float*)d_in[15];
    const float* w2 = (const float*)d_in[16];
    const float* b2 = (const float*)d_in[17];
    const float* w3 = (const float*)d_in[18];
    const float* b3 = (const float*)d_in[19];

    float* out_head = (float*)d_out;
    float* out_text = (float*)d_out + BB * DD;

    float* p_vals;   cudaGetSymbolAddress((void**)&p_vals, g_vals);
    float* p_qkimg;  cudaGetSymbolAddress((void**)&p_qkimg, g_qkimg);
    float* p_vv;     cudaGetSymbolAddress((void**)&p_vv, g_vv);
    float* p_wq;     cudaGetSymbolAddress((void**)&p_wq, g_wq);
    float* p_uq;     cudaGetSymbolAddress((void**)&p_uq, g_uq);
    float* p_sim;    cudaGetSymbolAddress((void**)&p_sim, g_sim);
    float* p_wvals;  cudaGetSymbolAddress((void**)&p_wvals, g_wvals);
    float* p_wtext;  cudaGetSymbolAddress((void**)&p_wtext, g_wtext);
    float* p_outpre; cudaGetSymbolAddress((void**)&p_outpre, g_outpre);
    float* p_ctxrow; cudaGetSymbolAddress((void**)&p_ctxrow, g_ctxrow);
    float* p_h1;     cudaGetSymbolAddress((void**)&p_h1, g_h1);
    float* p_h2;     cudaGetSymbolAddress((void**)&p_h2, g_h2);
    float* p_trow;   cudaGetSymbolAddress((void**)&p_trow, g_trow);
    __nv_bfloat16* p_Ahi; cudaGetSymbolAddress((void**)&p_Ahi, g_Ahi);
    __nv_bfloat16* p_Alo; cudaGetSymbolAddress((void**)&p_Alo, g_Alo);
    __nv_bfloat16* p_Bhi; cudaGetSymbolAddress((void**)&p_Bhi, g_Bhi);
    __nv_bfloat16* p_Blo; cudaGetSymbolAddress((void**)&p_Blo, g_Blo);
    __nv_bfloat16* p_Qkvhi; cudaGetSymbolAddress((void**)&p_Qkvhi, g_qkvhi);
    __nv_bfloat16* p_Qkvlo; cudaGetSymbolAddress((void**)&p_Qkvlo, g_qkvlo);

    static bool attr_set = false;
    if (!attr_set) {
        cudaFuncSetAttribute((const void*)attn3,
                             cudaFuncAttributeMaxDynamicSharedMemorySize, ATT_SMEM);
        cudaFuncSetAttribute((const void*)gemm_bf16x3,
                             cudaFuncAttributeMaxDynamicSharedMemorySize,
                             2 * STAGE_ELEMS * (int)sizeof(__nv_bfloat16));
        attr_set = true;
    }

    // 0-1: split inputs to bf16 hi/lo
    split2bf16<<<(BB * SS * DD / 4 + 255) / 256, 256>>>(text_emb, p_Ahi, p_Alo,
                                                        BB * SS * DD / 4);
    split2bf16<<<(DD * 3 * DD / 4 + 255) / 256, 256>>>(qkv_w, p_Bhi, p_Blo,
                                                       DD * 3 * DD / 4);
    // 2: QKV GEMM on tensor cores, bf16 hi/lo output
    gemm_bf16x3<<<dim3(3072 / 128, 4096 / 128), 256,
                  2 * STAGE_ELEMS * sizeof(__nv_bfloat16)>>>(
        p_Ahi, p_Alo, p_Bhi, p_Blo, qkv_b, p_Qkvhi, p_Qkvlo, BB * SS, 3 * DD, DD);
    // 3: fused inits
    init_all<<<256, 256>>>(p_qkimg, p_vv, p_outpre, p_wvals, p_h1, p_h2, p_trow,
                           out_head, out_b, p_ctxrow, ctx_out_b, p_wtext, o_b);
    // 4: img projections
    img_proj<<<dim3(INNER / 256, 8, 2), 256>>>(img, qk_w, v_w, p_qkimg, p_vv);
    // 5: tensor-core flash attention (profiled launch)
    attn3<<<dim3(BB * HH, SS / 64), 128, ATT_SMEM>>>(p_Qkvhi, p_Qkvlo, p_vals);
    // 6: wq = per-head ctx_qk_w^T @ qk_img
    wq_kernel<<<2048, 256>>>(ctx_qk_w, p_qkimg, p_wq);
    // 7: uq
    gemm_nt<64><<<dim3(DD / 8, 1), 256>>>(p_wq, DD, 0, o_w, DD, 0, p_uq, DD, 0,
                                          64, DD, DD, 1.0f);
    // 8: sim
    gemm_nt<16><<<dim3(SS / 8, BB), 256>>>(p_uq, DD, (long)HH * DD,
                                           p_vals, DD, (long)SS * DD,
                                           p_sim, SS, (long)HH * SS,
                                           HH, SS, DD, 1.0f / 32.0f);
    // 9: row softmax
    softmax_rows<<<BB * HH, 256>>>(p_sim, SS);
    // 10: wvals (ksplit atomic)
    gemm_nn<16><<<dim3(DD / 256, BB, 8), 256>>>(p_sim, SS, (long)HH * SS,
                                                p_vals, DD, (long)SS * DD,
                                                nullptr, p_wvals, DD, (long)HH * DD,
                                                HH, DD, SS, 1.0f, 0);
    // 11: wtext = wvals @ o_w (+ o_b via init)
    gemm_nn<64><<<dim3(DD / 256, 1, 4), 256>>>(p_wvals, DD, 0, o_w, DD, 0,
                                               nullptr, p_wtext, DD, 0,
                                               64, DD, DD, 1.0f, 0);
    // 12: out_pre
    gemm_nn<4><<<dim3(1024 / 256, HH, 4), 256>>>(p_wtext, HH * DD, (long)DD,
                                                 ctx_v_w, INNER, 1024L,
                                                 nullptr, p_outpre, INNER, 1024L,
                                                 BB, 1024, DD, 1.0f, 0);
    // 13: out head
    gemm_nn<4><<<dim3(DD / 256, 1, 32), 256>>>(p_outpre, INNER, 0, out_w, DD, 0,
                                               nullptr, out_head, DD, 0,
                                               BB, DD, INNER, 1.0f, 0);
    // 14: ctx_row
    gemm_nn<4><<<dim3(DD / 256, 1, 32), 256>>>(p_vv, INNER, 0, ctx_out_w, DD, 0,
                                               nullptr, p_ctxrow, DD, 0,
                                               BB, DD, INNER, 1.0f, 0);
    // 15-19: tiny MLP
    gemm_nn<4><<<dim3(DI2 / 256, 1, 8), 256>>>(p_ctxrow, DD, 0, w1, DI2, 0, nullptr,
                                               p_h1, DI2, 0, BB, DI2, DD, 1.0f, 0);
    tanh_bias_k<<<(BB * DI2 + 255) / 256, 256>>>(p_h1, b1, DI2, BB * DI2);
    gemm_nn<4><<<dim3(DI2 / 256, 1, 16), 256>>>(p_h1, DI2, 0, w2, DI2, 0, nullptr,
                                                p_h2, DI2, 0, BB, DI2, DI2, 1.0f, 0);
    tanh_bias_k<<<(BB * DI2 + 255) / 256, 256>>>(p_h2, b2, DI2, BB * DI2);
    gemm_nn<4><<<dim3(DD / 256, 1, 16), 256>>>(p_h2, DI2, 0, w3, DD, 0, nullptr,
                                               p_trow, DD, 0, BB, DD, DI2, 1.0f, 0);
    // 20: broadcast text_out (+ b3)
    bcast_text<<<(BB * SS * DD / 4) / 256, 256>>>(p_trow, b3, out_text);
}

// round 6
// speedup vs baseline: 2.9631x; 1.0132x over previous
#include <cuda_runtime.h>
#include <cuda_bf16.h>
#include <cstdint>
#include <math.h>

#define BB 4
#define SS 1024
#define DD 1024
#define HH 16
#define INNER 16384
#define DI2 2048

// ---- scratch (static device globals; no allocation in kernel_launch) ----
__device__ float g_vals[BB * SS * DD];      // 16 MB
__device__ float g_qkimg[BB * INNER];
__device__ float g_vv[BB * INNER];
__device__ float g_wq[BB * HH * DD];
__device__ float g_uq[BB * HH * DD];
__device__ float g_sim[BB * HH * SS];
__device__ float g_wvals[BB * HH * DD];
__device__ float g_wtext[BB * HH * DD];
__device__ float g_outpre[BB * INNER];
__device__ float g_ctxrow[BB * DD];
__device__ float g_h1[BB * DI2];
__device__ float g_h2[BB * DI2];
__device__ float g_trow[BB * DD];
// bf16 split buffers
__device__ __nv_bfloat16 g_Ahi[BB * SS * DD];
__device__ __nv_bfloat16 g_Alo[BB * SS * DD];
__device__ __nv_bfloat16 g_Bhi[DD * 3 * DD];
__device__ __nv_bfloat16 g_Blo[DD * 3 * DD];
__device__ __nv_bfloat16 g_qkvhi[BB * SS * 3 * DD];
__device__ __nv_bfloat16 g_qkvlo[BB * SS * 3 * DD];

// ---------------------------------------------------------------------------
__device__ __forceinline__ unsigned s2u(const void* p) {
    return (unsigned)__cvta_generic_to_shared(p);
}
__device__ __forceinline__ void ldsm_x4(unsigned* r, unsigned addr) {
    asm volatile("ldmatrix.sync.aligned.m8n8.x4.shared.b16 {%0,%1,%2,%3}, [%4];"
                 : "=r"(r[0]), "=r"(r[1]), "=r"(r[2]), "=r"(r[3]) : "r"(addr));
}
__device__ __forceinline__ void ldsm_x4t(unsigned* r, unsigned addr) {
    asm volatile("ldmatrix.sync.aligned.m8n8.x4.trans.shared.b16 {%0,%1,%2,%3}, [%4];"
                 : "=r"(r[0]), "=r"(r[1]), "=r"(r[2]), "=r"(r[3]) : "r"(addr));
}
__device__ __forceinline__ void mma_bf16(float* c, const unsigned* a,
                                         unsigned b0, unsigned b1) {
    asm volatile(
        "mma.sync.aligned.m16n8k16.row.col.f32.bf16.bf16.f32 "
        "{%0,%1,%2,%3}, {%4,%5,%6,%7}, {%8,%9}, {%0,%1,%2,%3};"
        : "+f"(c[0]), "+f"(c[1]), "+f"(c[2]), "+f"(c[3])
        : "r"(a[0]), "r"(a[1]), "r"(a[2]), "r"(a[3]), "r"(b0), "r"(b1));
}
__device__ __forceinline__ void cp16(unsigned dst, const void* src) {
    asm volatile("cp.async.cg.shared.global [%0], [%1], 16;" :: "r"(dst), "l"(src));
}
__device__ __forceinline__ void cp_commit() { asm volatile("cp.async.commit_group;"); }
__device__ __forceinline__ void cp_wait1() { asm volatile("cp.async.wait_group 1;"); }
__device__ __forceinline__ void cp_wait0() { asm volatile("cp.async.wait_group 0;"); }
__device__ __forceinline__ unsigned packbf(float x, float y) {
    unsigned short a = __bfloat16_as_ushort(__float2bfloat16(x));
    unsigned short b = __bfloat16_as_ushort(__float2bfloat16(y));
    return (unsigned)a | ((unsigned)b << 16);
}

// ---------------------------------------------------------------------------
__global__ void split2bf16(const float* __restrict__ x,
                           __nv_bfloat16* __restrict__ hi,
                           __nv_bfloat16* __restrict__ lo, int n4) {
    int i = blockIdx.x * 256 + threadIdx.x;
    if (i >= n4) return;
    float4 v = *(const float4*)&x[i * 4];
    __nv_bfloat16 h0 = __float2bfloat16(v.x);
    __nv_bfloat16 h1 = __float2bfloat16(v.y);
    __nv_bfloat16 h2 = __float2bfloat16(v.z);
    __nv_bfloat16 h3 = __float2bfloat16(v.w);
    *(__nv_bfloat162*)&hi[i * 4] = __halves2bfloat162(h0, h1);
    *(__nv_bfloat162*)&hi[i * 4 + 2] = __halves2bfloat162(h2, h3);
    *(__nv_bfloat162*)&lo[i * 4] = __halves2bfloat162(
        __float2bfloat16(v.x - __bfloat162float(h0)),
        __float2bfloat16(v.y - __bfloat162float(h1)));
    *(__nv_bfloat162*)&lo[i * 4 + 2] = __halves2bfloat162(
        __float2bfloat16(v.z - __bfloat162float(h2)),
        __float2bfloat16(v.w - __bfloat162float(h3)));
}

// ---------------------------------------------------------------------------
// bf16x3 tensor-core GEMM, 3-stage cp.async ring, 1 barrier per K-iter.
#define LDA_S 40
#define LDB_S 136
#define STAGE_ELEMS (128 * LDA_S * 2 + 32 * LDB_S * 2)
#define GEMM_SMEM (3 * STAGE_ELEMS * 2)

#define LOAD_STAGE(S, K0)                                                              \
    do {                                                                               \
        __nv_bfloat16* _b = smem + (S) * STAGE_ELEMS;                                  \
        cp16(s2u(_b + aR0 * LDA_S + aC0), Ahi + (size_t)(rowBase + aR0) * K + (K0) + aC0); \
        cp16(s2u(_b + aR1 * LDA_S + aC1), Ahi + (size_t)(rowBase + aR1) * K + (K0) + aC1); \
        cp16(s2u(_b + 128 * LDA_S + aR0 * LDA_S + aC0), Alo + (size_t)(rowBase + aR0) * K + (K0) + aC0); \
        cp16(s2u(_b + 128 * LDA_S + aR1 * LDA_S + aC1), Alo + (size_t)(rowBase + aR1) * K + (K0) + aC1); \
        cp16(s2u(_b + 256 * LDA_S + bR0 * LDB_S + bC0), Bhi + (size_t)((K0) + bR0) * N + colBase + bC0); \
        cp16(s2u(_b + 256 * LDA_S + bR1 * LDB_S + bC1), Bhi + (size_t)((K0) + bR1) * N + colBase + bC1); \
        cp16(s2u(_b + 256 * LDA_S + 32 * LDB_S + bR0 * LDB_S + bC0), Blo + (size_t)((K0) + bR0) * N + colBase + bC0); \
        cp16(s2u(_b + 256 * LDA_S + 32 * LDB_S + bR1 * LDB_S + bC1), Blo + (size_t)((K0) + bR1) * N + colBase + bC1); \
        cp_commit();                                                                   \
    } while (0)

__global__ __launch_bounds__(256) void gemm_bf16x3(
    const __nv_bfloat16* __restrict__ Ahi, const __nv_bfloat16* __restrict__ Alo,
    const __nv_bfloat16* __restrict__ Bhi, const __nv_bfloat16* __restrict__ Blo,
    const float* __restrict__ bias,
    __nv_bfloat16* __restrict__ Chi, __nv_bfloat16* __restrict__ Clo,
    int M, int N, int K) {
    extern __shared__ char dynsm[];
    __nv_bfloat16* smem = (__nv_bfloat16*)dynsm;
    const int tid = threadIdx.x;
    const int warp = tid >> 5, lane = tid & 31;
    const int wm = (warp >> 2) * 64, wn = (warp & 3) * 32;
    const int rowBase = blockIdx.y * 128, colBase = blockIdx.x * 128;

    const int aR0 = (tid * 2) >> 2, aC0 = ((tid * 2) & 3) << 3;
    const int aR1 = (tid * 2 + 1) >> 2, aC1 = ((tid * 2 + 1) & 3) << 3;
    const int bR0 = (tid * 2) >> 4, bC0 = ((tid * 2) & 15) << 3;
    const int bR1 = (tid * 2 + 1) >> 4, bC1 = ((tid * 2 + 1) & 15) << 3;

    float cacc[4][4][4];
#pragma unroll
    for (int i = 0; i < 4; i++)
#pragma unroll
        for (int j = 0; j < 4; j++)
#pragma unroll
            for (int v = 0; v < 4; v++) cacc[i][j][v] = 0.f;

    const int nIter = K / 32;
    LOAD_STAGE(0, 0);
    LOAD_STAGE(1, 32);

    for (int it = 0; it < nIter; it++) {
        if (it + 1 < nIter) cp_wait1(); else cp_wait0();
        __syncthreads();
        if (it + 2 < nIter) {
            LOAD_STAGE((it + 2) % 3, (it + 2) * 32);
        }
        const int cur = it % 3;
        __nv_bfloat16* sAh = smem + cur * STAGE_ELEMS;
        __nv_bfloat16* sAl = sAh + 128 * LDA_S;
        __nv_bfloat16* sBh = sAh + 256 * LDA_S;
        __nv_bfloat16* sBl = sAh + 256 * LDA_S + 32 * LDB_S;

#pragma unroll
        for (int ks = 0; ks < 32; ks += 16) {
            unsigned ah[4][4], al[4][4], bh[2][4], bl[2][4];
            const int arow = (lane & 15);
            const int acol = ks + ((lane >> 4) << 3);
#pragma unroll
            for (int mt = 0; mt < 4; mt++) {
                int off = (wm + mt * 16 + arow) * LDA_S + acol;
                ldsm_x4(ah[mt], s2u(sAh + off));
                ldsm_x4(al[mt], s2u(sAl + off));
            }
            const int brow = ks + (lane & 15);
            const int bcol0 = wn + ((lane >> 4) << 3);
#pragma unroll
            for (int nt = 0; nt < 2; nt++) {
                int off = brow * LDB_S + bcol0 + nt * 16;
                ldsm_x4t(bh[nt], s2u(sBh + off));
                ldsm_x4t(bl[nt], s2u(sBl + off));
            }
#pragma unroll
            for (int mt = 0; mt < 4; mt++) {
#pragma unroll
                for (int j = 0; j < 4; j++) {
                    unsigned bh0 = bh[j >> 1][(j & 1) * 2], bh1 = bh[j >> 1][(j & 1) * 2 + 1];
                    unsigned bl0 = bl[j >> 1][(j & 1) * 2], bl1 = bl[j >> 1][(j & 1) * 2 + 1];
                    mma_bf16(cacc[mt][j], ah[mt], bh0, bh1);
                    mma_bf16(cacc[mt][j], ah[mt], bl0, bl1);
                    mma_bf16(cacc[mt][j], al[mt], bh0, bh1);
                }
            }
        }
    }

#pragma unroll
    for (int mt = 0; mt < 4; mt++) {
#pragma unroll
        for (int j = 0; j < 4; j++) {
            int r0 = rowBase + wm + mt * 16 + (lane >> 2);
            int c0 = colBase + wn + j * 8 + (lane & 3) * 2;
            float b0 = bias[c0], b1 = bias[c0 + 1];
#pragma unroll
            for (int half = 0; half < 2; half++) {
                int r = r0 + half * 8;
                float x = cacc[mt][j][half * 2 + 0] + b0;
                float y = cacc[mt][j][half * 2 + 1] + b1;
                __nv_bfloat16 hx = __float2bfloat16(x);
                __nv_bfloat16 hy = __float2bfloat16(y);
                *(__nv_bfloat162*)&Chi[(size_t)r * N + c0] = __halves2bfloat162(hx, hy);
                *(__nv_bfloat162*)&Clo[(size_t)r * N + c0] = __halves2bfloat162(
                    __float2bfloat16(x - __bfloat162float(hx)),
                    __float2bfloat16(y - __bfloat162float(hy)));
            }
        }
    }
}

// ---------------------------------------------------------------------------
// Tensor-core flash attention (bf16x3), 128 thr, double-buffered K/V.
#define SA 72
#define ATT_STAGE (4 * 64 * SA)
#define ATT_SMEM ((2 * 64 * SA + 2 * ATT_STAGE) * 2)

__global__ __launch_bounds__(128) void attn3(const __nv_bfloat16* __restrict__ qkvhi,
                                             const __nv_bfloat16* __restrict__ qkvlo,
                                             float* __restrict__ vals) {
    extern __shared__ char dynsm[];
    __nv_bfloat16* SM = (__nv_bfloat16*)dynsm;
    __nv_bfloat16* Qhi = SM;
    __nv_bfloat16* Qlo = SM + 64 * SA;
    const int tid = threadIdx.x;
    const int warp = tid >> 5, lane = tid & 31;
    const int b = blockIdx.x >> 4, h = blockIdx.x & 15;
    const int qbase = blockIdx.y * 64;
    const size_t gbase = (size_t)b * SS * 3072 + h * 192;

    {
#pragma unroll
        for (int i = 0; i < 4; i++) {
            int c = i * 128 + tid;
            int row = c >> 3, col = (c & 7) << 3;
            size_t src = gbase + (size_t)(qbase + row) * 3072 + col;
            cp16(s2u(Qhi + row * SA + col), qkvhi + src);
            cp16(s2u(Qlo + row * SA + col), qkvlo + src);
        }
        __nv_bfloat16* st = SM + 2 * 64 * SA;
#pragma unroll
        for (int i = 0; i < 4; i++) {
            int c = i * 128 + tid;
            int row = c >> 3, col = (c & 7) << 3;
            size_t srcK = gbase + (size_t)row * 3072 + 64 + col;
            size_t srcV = gbase + (size_t)row * 3072 + 128 + col;
            cp16(s2u(st + row * SA + col), qkvhi + srcK);
            cp16(s2u(st + 64 * SA + row * SA + col), qkvlo + srcK);
            cp16(s2u(st + 2 * 64 * SA + row * SA + col), qkvhi + srcV);
            cp16(s2u(st + 3 * 64 * SA + row * SA + col), qkvlo + srcV);
        }
        cp_commit();
    }

    unsigned qh[4][4], ql[4][4];
    float o[8][4];
    float m0 = -1e30f, m1 = -1e30f, l0 = 0.f, l1 = 0.f;
#pragma unroll
    for (int i = 0; i < 8; i++)
#pragma unroll
        for (int j = 0; j < 4; j++) o[i][j] = 0.f;

    const int NT = SS / 64;
    for (int t = 0; t < NT; t++) {
        const int cur = t & 1;
        if (t + 1 < NT) {
            __nv_bfloat16* st = SM + 2 * 64 * SA + (cur ^ 1) * ATT_STAGE;
            const int kv0 = (t + 1) * 64;
#pragma unroll
            for (int i = 0; i < 4; i++) {
                int c = i * 128 + tid;
                int row = c >> 3, col = (c & 7) << 3;
                size_t srcK = gbase + (size_t)(kv0 + row) * 3072 + 64 + col;
                size_t srcV = gbase + (size_t)(kv0 + row) * 3072 + 128 + col;
                cp16(s2u(st + row * SA + col), qkvhi + srcK);
                cp16(s2u(st + 64 * SA + row * SA + col), qkvlo + srcK);
                cp16(s2u(st + 2 * 64 * SA + row * SA + col), qkvhi + srcV);
                cp16(s2u(st + 3 * 64 * SA + row * SA + col), qkvlo + srcV);
            }
            cp_commit();
            cp_wait1();
        } else {
            cp_wait0();
        }
        __syncthreads();

        if (t == 0) {
#pragma unroll
            for (int kt = 0; kt < 4; kt++) {
                int off = (warp * 16 + (lane & 15)) * SA + kt * 16 + ((lane >> 4) << 3);
                ldsm_x4(qh[kt], s2u(Qhi + off));
                ldsm_x4(ql[kt], s2u(Qlo + off));
            }
        }

        __nv_bfloat16* sKh = SM + 2 * 64 * SA + cur * ATT_STAGE;
        __nv_bfloat16* sKl = sKh + 64 * SA;
        __nv_bfloat16* sVh = sKh + 2 * 64 * SA;
        __nv_bfloat16* sVl = sKh + 3 * 64 * SA;

        float sc[8][4];
#pragma unroll
        for (int n = 0; n < 8; n++)
#pragma unroll
            for (int v = 0; v < 4; v++) sc[n][v] = 0.f;
#pragma unroll
        for (int kt = 0; kt < 4; kt++) {
            unsigned kh[4][4], kl[4][4];
#pragma unroll
            for (int nt = 0; nt < 4; nt++) {
                int off = (nt * 16 + (lane & 15)) * SA + kt * 16 + ((lane >> 4) << 3);
                ldsm_x4(kh[nt], s2u(sKh + off));
                ldsm_x4(kl[nt], s2u(sKl + off));
            }
#pragma unroll
            for (int nt = 0; nt < 4; nt++) {
#pragma unroll
                for (int sub = 0; sub < 2; sub++) {
                    int n = nt * 2 + sub;
                    mma_bf16(sc[n], qh[kt], kh[nt][sub], kh[nt][sub + 2]);
                    mma_bf16(sc[n], qh[kt], kl[nt][sub], kl[nt][sub + 2]);
                    mma_bf16(sc[n], ql[kt], kh[nt][sub], kh[nt][sub + 2]);
                }
            }
        }
#pragma unroll
        for (int n = 0; n < 8; n++)
#pragma unroll
            for (int v = 0; v < 4; v++) sc[n][v] *= 0.125f;

        float mt0 = -1e30f, mt1 = -1e30f;
#pragma unroll
        for (int n = 0; n < 8; n++) {
            mt0 = fmaxf(mt0, fmaxf(sc[n][0], sc[n][1]));
            mt1 = fmaxf(mt1, fmaxf(sc[n][2], sc[n][3]));
        }
        mt0 = fmaxf(mt0, __shfl_xor_sync(0xffffffffu, mt0, 1));
        mt0 = fmaxf(mt0, __shfl_xor_sync(0xffffffffu, mt0, 2));
        mt1 = fmaxf(mt1, __shfl_xor_sync(0xffffffffu, mt1, 1));
        mt1 = fmaxf(mt1, __shfl_xor_sync(0xffffffffu, mt1, 2));
        float mn0 = fmaxf(m0, mt0), mn1 = fmaxf(m1, mt1);
        float cr0 = __expf(m0 - mn0), cr1 = __expf(m1 - mn1);
        float s0 = 0.f, s1 = 0.f;
#pragma unroll
        for (int n = 0; n < 8; n++) {
            sc[n][0] = __expf(sc[n][0] - mn0);
            sc[n][1] = __expf(sc[n][1] - mn0);
            sc[n][2] = __expf(sc[n][2] - mn1);
            sc[n][3] = __expf(sc[n][3] - mn1);
            s0 += sc[n][0] + sc[n][1];
            s1 += sc[n][2] + sc[n][3];
        }
        s0 += __shfl_xor_sync(0xffffffffu, s0, 1);
        s0 += __shfl_xor_sync(0xffffffffu, s0, 2);
        s1 += __shfl_xor_sync(0xffffffffu, s1, 1);
        s1 += __shfl_xor_sync(0xffffffffu, s1, 2);
        l0 = l0 * cr0 + s0; l1 = l1 * cr1 + s1;
        m0 = mn0; m1 = mn1;
#pragma unroll
        for (int d = 0; d < 8; d++) {
            o[d][0] *= cr0; o[d][1] *= cr0;
            o[d][2] *= cr1; o[d][3] *= cr1;
        }

        unsigned ph[4][4], pl[4][4];
#pragma unroll
        for (int kt2 = 0; kt2 < 4; kt2++) {
#pragma unroll
            for (int part = 0; part < 4; part++) {
                int n = kt2 * 2 + (part >> 1);
                int i0 = (part & 1) * 2;
                float x = sc[n][i0], y = sc[n][i0 + 1];
                __nv_bfloat16 hx = __float2bfloat16(x);
                __nv_bfloat16 hy = __float2bfloat16(y);
                ph[kt2][part] = (unsigned)__bfloat16_as_ushort(hx) |
                                ((unsigned)__bfloat16_as_ushort(hy) << 16);
                pl[kt2][part] = packbf(x - __bfloat162float(hx),
                                       y - __bfloat162float(hy));
            }
        }

#pragma unroll
        for (int kt2 = 0; kt2 < 4; kt2++) {
            unsigned vh[4][4], vl[4][4];
#pragma unroll
            for (int dt = 0; dt < 4; dt++) {
                int off = (kt2 * 16 + (lane & 15)) * SA + dt * 16 + ((lane >> 4) << 3);
                ldsm_x4t(vh[dt], s2u(sVh + off));
                ldsm_x4t(vl[dt], s2u(sVl + off));
            }
#pragma unroll
            for (int dt = 0; dt < 4; dt++) {
#pragma unroll
                for (int sub = 0; sub < 2; sub++) {
                    int d = dt * 2 + sub;
                    mma_bf16(o[d], ph[kt2], vh[dt][sub * 2], vh[dt][sub * 2 + 1]);
                    mma_bf16(o[d], ph[kt2], vl[dt][sub * 2], vl[dt][sub * 2 + 1]);
                    mma_bf16(o[d], pl[kt2], vh[dt][sub * 2], vh[dt][sub * 2 + 1]);
                }
            }
        }
        __syncthreads();
    }

    float inv0 = 1.f / l0, inv1 = 1.f / l1;
    int row0 = qbase + warp * 16 + (lane >> 2);
    int row1 = row0 + 8;
#pragma unroll
    for (int d = 0; d < 8; d++) {
        int c0 = h * 64 + d * 8 + (lane & 3) * 2;
        float2 v0; v0.x = o[d][0] * inv0; v0.y = o[d][1] * inv0;
        float2 v1; v1.x = o[d][2] * inv1; v1.y = o[d][3] * inv1;
        *(float2*)&vals[(size_t)(b * SS + row0) * DD + c0] = v0;
        *(float2*)&vals[(size_t)(b * SS + row1) * DD + c0] = v1;
    }
}

// ---------------------------------------------------------------------------
__global__ void init_all(float* __restrict__ qkimg, float* __restrict__ vv,
                         float* __restrict__ outpre, float* __restrict__ wvals,
                         float* __restrict__ h1, float* __restrict__ h2,
                         float* __restrict__ trow,
                         float* __restrict__ outh, const float* __restrict__ out_b,
                         float* __restrict__ ctxrow, const float* __restrict__ ctx_out_b,
                         float* __restrict__ wtext, const float* __restrict__ o_b) {
    int i = blockIdx.x * 256 + threadIdx.x;
    qkimg[i] = 0.f; vv[i] = 0.f; outpre[i] = 0.f; wvals[i] = 0.f;
    wtext[i] = o_b[i & 1023];
    if (i < BB * DI2) { h1[i] = 0.f; h2[i] = 0.f; }
    if (i < BB * DD) {
        trow[i] = 0.f;
        outh[i] = out_b[i & 1023];
        ctxrow[i] = ctx_out_b[i & 1023];
    }
}

// ---------------------------------------------------------------------------
__global__ void img_proj(const float* __restrict__ img,
                         const float* __restrict__ W1, const float* __restrict__ W2,
                         float* __restrict__ O1, float* __restrict__ O2) {
    const float* W = blockIdx.z ? W2 : W1;
    float* O = blockIdx.z ? O2 : O1;
    int col = blockIdx.x * 256 + threadIdx.x;
    int k0 = blockIdx.y * 128;
    __shared__ float xs[4][128];
    for (int i = threadIdx.x; i < 512; i += 256)
        xs[i >> 7][i & 127] = img[(i >> 7) * DD + k0 + (i & 127)];
    __syncthreads();
    float a0 = 0, a1 = 0, a2 = 0, a3 = 0;
    const float* wp = W + (size_t)k0 * INNER + col;
#pragma unroll 4
    for (int k = 0; k < 128; k++) {
        float wv = wp[(size_t)k * INNER];
        a0 += xs[0][k] * wv; a1 += xs[1][k] * wv;
        a2 += xs[2][k] * wv; a3 += xs[3][k] * wv;
    }
    atomicAdd(&O[col], a0);
    atomicAdd(&O[INNER + col], a1);
    atomicAdd(&O[2 * INNER + col], a2);
    atomicAdd(&O[3 * INNER + col], a3);
}

// ---------------------------------------------------------------------------
__global__ __launch_bounds__(256) void wq_kernel(const float* __restrict__ Wc,
                                                 const float* __restrict__ qkimg,
                                                 float* __restrict__ wq) {
    int gwarp = (blockIdx.x * 256 + threadIdx.x) >> 5;
    int lane = threadIdx.x & 31;
    int d = gwarp >> 4, h = gwarp & 15;
    const float* row = Wc + (size_t)d * INNER + h * 1024;
    const float* qb = qkimg + h * 1024;
    float a0 = 0, a1 = 0, a2 = 0, a3 = 0;
    for (int e = lane; e < 1024; e += 32) {
        float wv = row[e];
        a0 += wv * qb[e];
        a1 += wv * qb[INNER + e];
        a2 += wv * qb[2 * INNER + e];
        a3 += wv * qb[3 * INNER + e];
    }
#pragma unroll
    for (int o = 16; o; o >>= 1) {
        a0 += __shfl_xor_sync(0xffffffffu, a0, o);
        a1 += __shfl_xor_sync(0xffffffffu, a1, o);
        a2 += __shfl_xor_sync(0xffffffffu, a2, o);
        a3 += __shfl_xor_sync(0xffffffffu, a3, o);
    }
    if (lane == 0) {
        wq[(0 * HH + h) * DD + d] = a0;
        wq[(1 * HH + h) * DD + d] = a1;
        wq[(2 * HH + h) * DD + d] = a2;
        wq[(3 * HH + h) * DD + d] = a3;
    }
}

// ---------------------------------------------------------------------------
template <int MT>
__global__ __launch_bounds__(256) void gemm_nt(const float* __restrict__ A, int lda, long sA,
                                               const float* __restrict__ Bm, int ldb, long sB,
                                               float* __restrict__ C, int ldc, long sC,
                                               int M, int N, int K, float alpha) {
    int batch = blockIdx.y;
    A += (size_t)batch * sA; Bm += (size_t)batch * sB; C += (size_t)batch * sC;
    int warp = threadIdx.x >> 5, lane = threadIdx.x & 31;
    int j = blockIdx.x * 8 + warp;
    __shared__ float As[MT][128];
    float acc[MT];
#pragma unroll
    for (int i = 0; i < MT; i++) acc[i] = 0.f;
    for (int k0 = 0; k0 < K; k0 += 128) {
        __syncthreads();
        for (int i = threadIdx.x; i < MT * 128; i += 256) {
            int r = i >> 7, c = i & 127;
            As[r][c] = (r < M) ? A[(size_t)r * lda + k0 + c] : 0.f;
        }
        __syncthreads();
        const float* bp = Bm + (size_t)j * ldb + k0;
        for (int k = lane; k < 128; k += 32) {
            float bv = bp[k];
#pragma unroll
            for (int i = 0; i < MT; i++) acc[i] += As[i][k] * bv;
        }
    }
#pragma unroll
    for (int i = 0; i < MT; i++) {
        float v = acc[i];
#pragma unroll
        for (int o = 16; o; o >>= 1) v += __shfl_xor_sync(0xffffffffu, v, o);
        if (lane == 0 && i < M) C[(size_t)i * ldc + j] = alpha * v;
    }
}

// ---------------------------------------------------------------------------
template <int MT>
__global__ __launch_bounds__(256) void gemm_nn(const float* __restrict__ A, int lda, long sA,
                                               const float* __restrict__ Bm, int ldb, long sB,
                                               const float* __restrict__ bias,
                                               float* __restrict__ C, int ldc, long sC,
                                               int M, int N, int K, float alpha, int act) {
    int batch = blockIdx.y;
    A += (size_t)batch * sA; Bm += (size_t)batch * sB; C += (size_t)batch * sC;
    int j = blockIdx.x * 256 + threadIdx.x;
    int kChunk = K / gridDim.z;
    int kBeg = blockIdx.z * kChunk;
    float acc[MT];
#pragma unroll
    for (int i = 0; i < MT; i++) acc[i] = 0.f;
    __shared__ float As[MT][32];
    for (int k0 = kBeg; k0 < kBeg + kChunk; k0 += 32) {
        __syncthreads();
        for (int i = threadIdx.x; i < MT * 32; i += 256) {
            int r = i >> 5, c = i & 31;
            As[r][c] = (r < M) ? A[(size_t)r * lda + k0 + c] : 0.f;
        }
        __syncthreads();
#pragma unroll 4
        for (int k = 0; k < 32; k++) {
            float bv = Bm[(size_t)(k0 + k) * ldb + j];
#pragma unroll
            for (int i = 0; i < MT; i++) acc[i] += As[i][k] * bv;
        }
    }
    if (gridDim.z == 1) {
        float bb = bias ? bias[j] : 0.f;
        for (int i = 0; i < MT && i < M; i++) {
            float v = alpha * acc[i] + bb;
            if (act) v = tanhf(v);
            C[(size_t)i * ldc + j] = v;
        }
    } else {
        for (int i = 0; i < MT && i < M; i++)
            atomicAdd(&C[(size_t)i * ldc + j], alpha * acc[i]);
    }
}

// ---------------------------------------------------------------------------
__global__ void softmax_rows(float* __restrict__ base, int n) {
    float* p = base + (size_t)blockIdx.x * n;
    __shared__ float red[8];
    __shared__ float red2[8];
    int tid = threadIdx.x;
    float m = -1e30f;
    for (int j = tid; j < n; j += 256) m = fmaxf(m, p[j]);
#pragma unroll
    for (int o = 16; o; o >>= 1) m = fmaxf(m, __shfl_xor_sync(0xffffffffu, m, o));
    if ((tid & 31) == 0) red[tid >> 5] = m;
    __syncthreads();
    float mm = red[0];
#pragma unroll
    for (int w = 1; w < 8; w++) mm = fmaxf(mm, red[w]);
    float sum = 0.f;
    for (int j = tid; j < n; j += 256) {
        float e = __expf(p[j] - mm);
        p[j] = e;
        sum += e;
    }
#pragma unroll
    for (int o = 16; o; o >>= 1) sum += __shfl_xor_sync(0xffffffffu, sum, o);
    if ((tid & 31) == 0) red2[tid >> 5] = sum;
    __syncthreads();
    float tot = 0.f;
#pragma unroll
    for (int w = 0; w < 8; w++) tot += red2[w];
    float inv = 1.f / tot;
    for (int j = tid; j < n; j += 256) p[j] *= inv;
}

// ---------------------------------------------------------------------------
__global__ void tanh_bias_k(float* __restrict__ x, const float* __restrict__ bias,
                            int n, int total) {
    int i = blockIdx.x * 256 + threadIdx.x;
    if (i < total) x[i] = tanhf(x[i] + bias[i % n]);
}

__global__ void bcast_text(const float* __restrict__ trow, const float* __restrict__ b3,
                           float* __restrict__ out) {
    size_t idx = (size_t)blockIdx.x * 256 + threadIdx.x;
    size_t e = idx * 4;
    int b = (int)(e / ((size_t)SS * DD));
    int d = (int)(e % DD);
    float4 t = *(const float4*)&trow[b * DD + d];
    float4 bb = *(const float4*)&b3[d];
    t.x += bb.x; t.y += bb.y; t.z += bb.z; t.w += bb.w;
    *(float4*)&out[e] = t;
}

// ---------------------------------------------------------------------------
extern "C" void kernel_launch(void* const* d_in, const int* in_sizes, int n_in,
                              void* d_out, int out_size) {
    (void)in_sizes; (void)n_in; (void)out_size;
    const float* img      = (const float*)d_in[0];
    const float* text_emb = (const float*)d_in[1];
    const float* qkv_w    = (const float*)d_in[2];
    const float* qkv_b    = (const float*)d_in[3];
    const float* o_w      = (const float*)d_in[4];
    const float* o_b      = (const float*)d_in[5];
    const float* qk_w     = (const float*)d_in[6];
    const float* ctx_qk_w = (const float*)d_in[7];
    const float* v_w      = (const float*)d_in[8];
    const float* ctx_v_w  = (const float*)d_in[9];
    const float* out_w    = (const float*)d_in[10];
    const float* out_b    = (const float*)d_in[11];
    const float* ctx_out_w= (const float*)d_in[12];
    const float* ctx_out_b= (const float*)d_in[13];
    const float* w1 = (const float*)d_in[14];
    const float* b1 = (const float*)d_in[15];
    const float* w2 = (const float*)d_in[16];
    const float* b2 = (const float*)d_in[17];
    const float* w3 = (const float*)d_in[18];
    const float* b3 = (const float*)d_in[19];

    float* out_head = (float*)d_out;
    float* out_text = (float*)d_out + BB * DD;

    float* p_vals;   cudaGetSymbolAddress((void**)&p_vals, g_vals);
    float* p_qkimg;  cudaGetSymbolAddress((void**)&p_qkimg, g_qkimg);
    float* p_vv;     cudaGetSymbolAddress((void**)&p_vv, g_vv);
    float* p_wq;     cudaGetSymbolAddress((void**)&p_wq, g_wq);
    float* p_uq;     cudaGetSymbolAddress((void**)&p_uq, g_uq);
    float* p_sim;    cudaGetSymbolAddress((void**)&p_sim, g_sim);
    float* p_wvals;  cudaGetSymbolAddress((void**)&p_wvals, g_wvals);
    float* p_wtext;  cudaGetSymbolAddress((void**)&p_wtext, g_wtext);
    float* p_outpre; cudaGetSymbolAddress((void**)&p_outpre, g_outpre);
    float* p_ctxrow; cudaGetSymbolAddress((void**)&p_ctxrow, g_ctxrow);
    float* p_h1;     cudaGetSymbolAddress((void**)&p_h1, g_h1);
    float* p_h2;     cudaGetSymbolAddress((void**)&p_h2, g_h2);
    float* p_trow;   cudaGetSymbolAddress((void**)&p_trow, g_trow);
    __nv_bfloat16* p_Ahi; cudaGetSymbolAddress((void**)&p_Ahi, g_Ahi);
    __nv_bfloat16* p_Alo; cudaGetSymbolAddress((void**)&p_Alo, g_Alo);
    __nv_bfloat16* p_Bhi; cudaGetSymbolAddress((void**)&p_Bhi, g_Bhi);
    __nv_bfloat16* p_Blo; cudaGetSymbolAddress((void**)&p_Blo, g_Blo);
    __nv_bfloat16* p_Qkvhi; cudaGetSymbolAddress((void**)&p_Qkvhi, g_qkvhi);
    __nv_bfloat16* p_Qkvlo; cudaGetSymbolAddress((void**)&p_Qkvlo, g_qkvlo);

    static bool attr_set = false;
    if (!attr_set) {
        cudaFuncSetAttribute((const void*)attn3,
                             cudaFuncAttributeMaxDynamicSharedMemorySize, ATT_SMEM);
        cudaFuncSetAttribute((const void*)gemm_bf16x3,
                             cudaFuncAttributeMaxDynamicSharedMemorySize, GEMM_SMEM);
        attr_set = true;
    }

    // 0-1: splits
    split2bf16<<<(BB * SS * DD / 4 + 255) / 256, 256>>>(text_emb, p_Ahi, p_Alo,
                                                        BB * SS * DD / 4);
    split2bf16<<<(DD * 3 * DD / 4 + 255) / 256, 256>>>(qkv_w, p_Bhi, p_Blo,
                                                       DD * 3 * DD / 4);
    // 2: fused inits
    init_all<<<256, 256>>>(p_qkimg, p_vv, p_outpre, p_wvals, p_h1, p_h2, p_trow,
                           out_head, out_b, p_ctxrow, ctx_out_b, p_wtext, o_b);
    // 3: QKV GEMM (PROFILED: launch index 3)
    gemm_bf16x3<<<dim3(3072 / 128, 4096 / 128), 256, GEMM_SMEM>>>(
        p_Ahi, p_Alo, p_Bhi, p_Blo, qkv_b, p_Qkvhi, p_Qkvlo, BB * SS, 3 * DD, DD);
    // 4: img projections
    img_proj<<<dim3(INNER / 256, 8, 2), 256>>>(img, qk_w, v_w, p_qkimg, p_vv);
    // 5: tensor-core flash attention
    attn3<<<dim3(BB * HH, SS / 64), 128, ATT_SMEM>>>(p_Qkvhi, p_Qkvlo, p_vals);
    // 6: wq
    wq_kernel<<<2048, 256>>>(ctx_qk_w, p_qkimg, p_wq);
    // 7: uq
    gemm_nt<64><<<dim3(DD / 8, 1), 256>>>(p_wq, DD, 0, o_w, DD, 0, p_uq, DD, 0,
                                          64, DD, DD, 1.0f);
    // 8: sim
    gemm_nt<16><<<dim3(SS / 8, BB), 256>>>(p_uq, DD, (long)HH * DD,
                                           p_vals, DD, (long)SS * DD,
                                           p_sim, SS, (long)HH * SS,
                                           HH, SS, DD, 1.0f / 32.0f);
    // 9: row softmax
    softmax_rows<<<BB * HH, 256>>>(p_sim, SS);
    // 10: wvals (ksplit atomic)
    gemm_nn<16><<<dim3(DD / 256, BB, 8), 256>>>(p_sim, SS, (long)HH * SS,
                                                p_vals, DD, (long)SS * DD,
                                                nullptr, p_wvals, DD, (long)HH * DD,
                                                HH, DD, SS, 1.0f, 0);
    // 11: wtext
    gemm_nn<64><<<dim3(DD / 256, 1, 4), 256>>>(p_wvals, DD, 0, o_w, DD, 0,
                                               nullptr, p_wtext, DD, 0,
                                               64, DD, DD, 1.0f, 0);
    // 12: out_pre
    gemm_nn<4><<<dim3(1024 / 256, HH, 4), 256>>>(p_wtext, HH * DD, (long)DD,
                                                 ctx_v_w, INNER, 1024L,
                                                 nullptr, p_outpre, INNER, 1024L,
                                                 BB, 1024, DD, 1.0f, 0);
    // 13: out head
    gemm_nn<4><<<dim3(DD / 256, 1, 32), 256>>>(p_outpre, INNER, 0, out_w, DD, 0,
                                               nullptr, out_head, DD, 0,
                                               BB, DD, INNER, 1.0f, 0);
    // 14: ctx_row
    gemm_nn<4><<<dim3(DD / 256, 1, 32), 256>>>(p_vv, INNER, 0, ctx_out_w, DD, 0,
                                               nullptr, p_ctxrow, DD, 0,
                                               BB, DD, INNER, 1.0f, 0);
    // 15-19: tiny MLP
    gemm_nn<4><<<dim3(DI2 / 256, 1, 8), 256>>>(p_ctxrow, DD, 0, w1, DI2, 0, nullptr,
                                               p_h1, DI2, 0, BB, DI2, DD, 1.0f, 0);
    tanh_bias_k<<<(BB * DI2 + 255) / 256, 256>>>(p_h1, b1, DI2, BB * DI2);
    gemm_nn<4><<<dim3(DI2 / 256, 1, 16), 256>>>(p_h1, DI2, 0, w2, DI2, 0, nullptr,
                                                p_h2, DI2, 0, BB, DI2, DI2, 1.0f, 0);
    tanh_bias_k<<<(BB * DI2 + 255) / 256, 256>>>(p_h2, b2, DI2, BB * DI2);
    gemm_nn<4><<<dim3(DD / 256, 1, 16), 256>>>(p_h2, DI2, 0, w3, DD, 0, nullptr,
                                               p_trow, DD, 0, BB, DD, DI2, 1.0f, 0);
    // 20: broadcast
    bcast_text<<<(BB * SS * DD / 4) / 256, 256>>>(p_trow, b3, out_text);
}

// round 7
// speedup vs baseline: 4.1689x; 1.4069x over previous
#include <cuda_runtime.h>
#include <cuda_bf16.h>
#include <cstdint>
#include <math.h>

#define BB 4
#define SS 1024
#define DD 1024
#define HH 16
#define INNER 16384
#define DI2 2048

// ---- scratch ----
__device__ float g_vals[BB * SS * DD];
__device__ float g_qkimg[BB * INNER];
__device__ float g_vv[BB * INNER];
__device__ float g_wq[BB * HH * DD];
__device__ float g_uq[BB * HH * DD];
__device__ float g_sim[BB * HH * SS];
__device__ float g_wvals[BB * HH * DD];
__device__ float g_wtext[BB * HH * DD];
__device__ float g_outpre[BB * INNER];
__device__ float g_ctxrow[BB * DD];
__device__ float g_h1[BB * DI2];
__device__ float g_h2[BB * DI2];
__device__ float g_trow[BB * DD];
__device__ __nv_bfloat16 g_Ahi[BB * SS * DD];
__device__ __nv_bfloat16 g_Alo[BB * SS * DD];
__device__ __nv_bfloat16 g_Bhi[DD * 3 * DD];
__device__ __nv_bfloat16 g_Blo[DD * 3 * DD];
__device__ __nv_bfloat16 g_qkvhi[BB * SS * 3 * DD];
__device__ __nv_bfloat16 g_qkvlo[BB * SS * 3 * DD];

// ---------------------------------------------------------------------------
__device__ __forceinline__ unsigned s2u(const void* p) {
    return (unsigned)__cvta_generic_to_shared(p);
}
__device__ __forceinline__ void ldsm_x4(unsigned* r, unsigned addr) {
    asm volatile("ldmatrix.sync.aligned.m8n8.x4.shared.b16 {%0,%1,%2,%3}, [%4];"
                 : "=r"(r[0]), "=r"(r[1]), "=r"(r[2]), "=r"(r[3]) : "r"(addr));
}
__device__ __forceinline__ void ldsm_x4t(unsigned* r, unsigned addr) {
    asm volatile("ldmatrix.sync.aligned.m8n8.x4.trans.shared.b16 {%0,%1,%2,%3}, [%4];"
                 : "=r"(r[0]), "=r"(r[1]), "=r"(r[2]), "=r"(r[3]) : "r"(addr));
}
__device__ __forceinline__ void mma_bf16(float* c, const unsigned* a,
                                         unsigned b0, unsigned b1) {
    asm volatile(
        "mma.sync.aligned.m16n8k16.row.col.f32.bf16.bf16.f32 "
        "{%0,%1,%2,%3}, {%4,%5,%6,%7}, {%8,%9}, {%0,%1,%2,%3};"
        : "+f"(c[0]), "+f"(c[1]), "+f"(c[2]), "+f"(c[3])
        : "r"(a[0]), "r"(a[1]), "r"(a[2]), "r"(a[3]), "r"(b0), "r"(b1));
}
__device__ __forceinline__ void cp16(unsigned dst, const void* src) {
    asm volatile("cp.async.cg.shared.global [%0], [%1], 16;" :: "r"(dst), "l"(src));
}
__device__ __forceinline__ void cp_commit() { asm volatile("cp.async.commit_group;"); }
__device__ __forceinline__ void cp_wait1() { asm volatile("cp.async.wait_group 1;"); }
__device__ __forceinline__ void cp_wait0() { asm volatile("cp.async.wait_group 0;"); }
__device__ __forceinline__ unsigned packbf(float x, float y) {
    unsigned short a = __bfloat16_as_ushort(__float2bfloat16(x));
    unsigned short b = __bfloat16_as_ushort(__float2bfloat16(y));
    return (unsigned)a | ((unsigned)b << 16);
}

// ---------------------------------------------------------------------------
__global__ void split2bf16(const float* __restrict__ x,
                           __nv_bfloat16* __restrict__ hi,
                           __nv_bfloat16* __restrict__ lo, int n4) {
    int i = blockIdx.x * 256 + threadIdx.x;
    if (i >= n4) return;
    float4 v = *(const float4*)&x[i * 4];
    __nv_bfloat16 h0 = __float2bfloat16(v.x);
    __nv_bfloat16 h1 = __float2bfloat16(v.y);
    __nv_bfloat16 h2 = __float2bfloat16(v.z);
    __nv_bfloat16 h3 = __float2bfloat16(v.w);
    *(__nv_bfloat162*)&hi[i * 4] = __halves2bfloat162(h0, h1);
    *(__nv_bfloat162*)&hi[i * 4 + 2] = __halves2bfloat162(h2, h3);
    *(__nv_bfloat162*)&lo[i * 4] = __halves2bfloat162(
        __float2bfloat16(v.x - __bfloat162float(h0)),
        __float2bfloat16(v.y - __bfloat162float(h1)));
    *(__nv_bfloat162*)&lo[i * 4 + 2] = __halves2bfloat162(
        __float2bfloat16(v.z - __bfloat162float(h2)),
        __float2bfloat16(v.w - __bfloat162float(h3)));
}

// ---------------------------------------------------------------------------
// bf16x3 tensor-core GEMM, 3-stage cp.async ring.
#define LDA_S 40
#define LDB_S 136
#define STAGE_ELEMS (128 * LDA_S * 2 + 32 * LDB_S * 2)
#define GEMM_SMEM (3 * STAGE_ELEMS * 2)

#define LOAD_STAGE(S, K0)                                                              \
    do {                                                                               \
        __nv_bfloat16* _b = smem + (S) * STAGE_ELEMS;                                  \
        cp16(s2u(_b + aR0 * LDA_S + aC0), Ahi + (size_t)(rowBase + aR0) * K + (K0) + aC0); \
        cp16(s2u(_b + aR1 * LDA_S + aC1), Ahi + (size_t)(rowBase + aR1) * K + (K0) + aC1); \
        cp16(s2u(_b + 128 * LDA_S + aR0 * LDA_S + aC0), Alo + (size_t)(rowBase + aR0) * K + (K0) + aC0); \
        cp16(s2u(_b + 128 * LDA_S + aR1 * LDA_S + aC1), Alo + (size_t)(rowBase + aR1) * K + (K0) + aC1); \
        cp16(s2u(_b + 256 * LDA_S + bR0 * LDB_S + bC0), Bhi + (size_t)((K0) + bR0) * N + colBase + bC0); \
        cp16(s2u(_b + 256 * LDA_S + bR1 * LDB_S + bC1), Bhi + (size_t)((K0) + bR1) * N + colBase + bC1); \
        cp16(s2u(_b + 256 * LDA_S + 32 * LDB_S + bR0 * LDB_S + bC0), Blo + (size_t)((K0) + bR0) * N + colBase + bC0); \
        cp16(s2u(_b + 256 * LDA_S + 32 * LDB_S + bR1 * LDB_S + bC1), Blo + (size_t)((K0) + bR1) * N + colBase + bC1); \
        cp_commit();                                                                   \
    } while (0)

__global__ __launch_bounds__(256) void gemm_bf16x3(
    const __nv_bfloat16* __restrict__ Ahi, const __nv_bfloat16* __restrict__ Alo,
    const __nv_bfloat16* __restrict__ Bhi, const __nv_bfloat16* __restrict__ Blo,
    const float* __restrict__ bias,
    __nv_bfloat16* __restrict__ Chi, __nv_bfloat16* __restrict__ Clo,
    int M, int N, int K) {
    extern __shared__ char dynsm[];
    __nv_bfloat16* smem = (__nv_bfloat16*)dynsm;
    const int tid = threadIdx.x;
    const int warp = tid >> 5, lane = tid & 31;
    const int wm = (warp >> 2) * 64, wn = (warp & 3) * 32;
    const int rowBase = blockIdx.y * 128, colBase = blockIdx.x * 128;

    const int aR0 = (tid * 2) >> 2, aC0 = ((tid * 2) & 3) << 3;
    const int aR1 = (tid * 2 + 1) >> 2, aC1 = ((tid * 2 + 1) & 3) << 3;
    const int bR0 = (tid * 2) >> 4, bC0 = ((tid * 2) & 15) << 3;
    const int bR1 = (tid * 2 + 1) >> 4, bC1 = ((tid * 2 + 1) & 15) << 3;

    float cacc[4][4][4];
#pragma unroll
    for (int i = 0; i < 4; i++)
#pragma unroll
        for (int j = 0; j < 4; j++)
#pragma unroll
            for (int v = 0; v < 4; v++) cacc[i][j][v] = 0.f;

    const int nIter = K / 32;
    LOAD_STAGE(0, 0);
    LOAD_STAGE(1, 32);

    for (int it = 0; it < nIter; it++) {
        if (it + 1 < nIter) cp_wait1(); else cp_wait0();
        __syncthreads();
        if (it + 2 < nIter) {
            LOAD_STAGE((it + 2) % 3, (it + 2) * 32);
        }
        const int cur = it % 3;
        __nv_bfloat16* sAh = smem + cur * STAGE_ELEMS;
        __nv_bfloat16* sAl = sAh + 128 * LDA_S;
        __nv_bfloat16* sBh = sAh + 256 * LDA_S;
        __nv_bfloat16* sBl = sAh + 256 * LDA_S + 32 * LDB_S;

#pragma unroll
        for (int ks = 0; ks < 32; ks += 16) {
            unsigned ah[4][4], al[4][4], bh[2][4], bl[2][4];
            const int arow = (lane & 15);
            const int acol = ks + ((lane >> 4) << 3);
#pragma unroll
            for (int mt = 0; mt < 4; mt++) {
                int off = (wm + mt * 16 + arow) * LDA_S + acol;
                ldsm_x4(ah[mt], s2u(sAh + off));
                ldsm_x4(al[mt], s2u(sAl + off));
            }
            const int brow = ks + (lane & 15);
            const int bcol0 = wn + ((lane >> 4) << 3);
#pragma unroll
            for (int nt = 0; nt < 2; nt++) {
                int off = brow * LDB_S + bcol0 + nt * 16;
                ldsm_x4t(bh[nt], s2u(sBh + off));
                ldsm_x4t(bl[nt], s2u(sBl + off));
            }
#pragma unroll
            for (int mt = 0; mt < 4; mt++) {
#pragma unroll
                for (int j = 0; j < 4; j++) {
                    unsigned bh0 = bh[j >> 1][(j & 1) * 2], bh1 = bh[j >> 1][(j & 1) * 2 + 1];
                    unsigned bl0 = bl[j >> 1][(j & 1) * 2], bl1 = bl[j >> 1][(j & 1) * 2 + 1];
                    mma_bf16(cacc[mt][j], ah[mt], bh0, bh1);
                    mma_bf16(cacc[mt][j], ah[mt], bl0, bl1);
                    mma_bf16(cacc[mt][j], al[mt], bh0, bh1);
                }
            }
        }
    }

#pragma unroll
    for (int mt = 0; mt < 4; mt++) {
#pragma unroll
        for (int j = 0; j < 4; j++) {
            int r0 = rowBase + wm + mt * 16 + (lane >> 2);
            int c0 = colBase + wn + j * 8 + (lane & 3) * 2;
            float b0 = bias[c0], b1 = bias[c0 + 1];
#pragma unroll
            for (int half = 0; half < 2; half++) {
                int r = r0 + half * 8;
                float x = cacc[mt][j][half * 2 + 0] + b0;
                float y = cacc[mt][j][half * 2 + 1] + b1;
                __nv_bfloat16 hx = __float2bfloat16(x);
                __nv_bfloat16 hy = __float2bfloat16(y);
                *(__nv_bfloat162*)&Chi[(size_t)r * N + c0] = __halves2bfloat162(hx, hy);
                *(__nv_bfloat162*)&Clo[(size_t)r * N + c0] = __halves2bfloat162(
                    __float2bfloat16(x - __bfloat162float(hx)),
                    __float2bfloat16(y - __bfloat162float(hy)));
            }
        }
    }
}

// ---------------------------------------------------------------------------
// Tensor-core flash attention (bf16x3).
#define SA 72
#define ATT_STAGE (4 * 64 * SA)
#define ATT_SMEM ((2 * 64 * SA + 2 * ATT_STAGE) * 2)

__global__ __launch_bounds__(128) void attn3(const __nv_bfloat16* __restrict__ qkvhi,
                                             const __nv_bfloat16* __restrict__ qkvlo,
                                             float* __restrict__ vals) {
    extern __shared__ char dynsm[];
    __nv_bfloat16* SM = (__nv_bfloat16*)dynsm;
    __nv_bfloat16* Qhi = SM;
    __nv_bfloat16* Qlo = SM + 64 * SA;
    const int tid = threadIdx.x;
    const int warp = tid >> 5, lane = tid & 31;
    const int b = blockIdx.x >> 4, h = blockIdx.x & 15;
    const int qbase = blockIdx.y * 64;
    const size_t gbase = (size_t)b * SS * 3072 + h * 192;

    {
#pragma unroll
        for (int i = 0; i < 4; i++) {
            int c = i * 128 + tid;
            int row = c >> 3, col = (c & 7) << 3;
            size_t src = gbase + (size_t)(qbase + row) * 3072 + col;
            cp16(s2u(Qhi + row * SA + col), qkvhi + src);
            cp16(s2u(Qlo + row * SA + col), qkvlo + src);
        }
        __nv_bfloat16* st = SM + 2 * 64 * SA;
#pragma unroll
        for (int i = 0; i < 4; i++) {
            int c = i * 128 + tid;
            int row = c >> 3, col = (c & 7) << 3;
            size_t srcK = gbase + (size_t)row * 3072 + 64 + col;
            size_t srcV = gbase + (size_t)row * 3072 + 128 + col;
            cp16(s2u(st + row * SA + col), qkvhi + srcK);
            cp16(s2u(st + 64 * SA + row * SA + col), qkvlo + srcK);
            cp16(s2u(st + 2 * 64 * SA + row * SA + col), qkvhi + srcV);
            cp16(s2u(st + 3 * 64 * SA + row * SA + col), qkvlo + srcV);
        }
        cp_commit();
    }

    unsigned qh[4][4], ql[4][4];
    float o[8][4];
    float m0 = -1e30f, m1 = -1e30f, l0 = 0.f, l1 = 0.f;
#pragma unroll
    for (int i = 0; i < 8; i++)
#pragma unroll
        for (int j = 0; j < 4; j++) o[i][j] = 0.f;

    const int NT = SS / 64;
    for (int t = 0; t < NT; t++) {
        const int cur = t & 1;
        if (t + 1 < NT) {
            __nv_bfloat16* st = SM + 2 * 64 * SA + (cur ^ 1) * ATT_STAGE;
            const int kv0 = (t + 1) * 64;
#pragma unroll
            for (int i = 0; i < 4; i++) {
                int c = i * 128 + tid;
                int row = c >> 3, col = (c & 7) << 3;
                size_t srcK = gbase + (size_t)(kv0 + row) * 3072 + 64 + col;
                size_t srcV = gbase + (size_t)(kv0 + row) * 3072 + 128 + col;
                cp16(s2u(st + row * SA + col), qkvhi + srcK);
                cp16(s2u(st + 64 * SA + row * SA + col), qkvlo + srcK);
                cp16(s2u(st + 2 * 64 * SA + row * SA + col), qkvhi + srcV);
                cp16(s2u(st + 3 * 64 * SA + row * SA + col), qkvlo + srcV);
            }
            cp_commit();
            cp_wait1();
        } else {
            cp_wait0();
        }
        __syncthreads();

        if (t == 0) {
#pragma unroll
            for (int kt = 0; kt < 4; kt++) {
                int off = (warp * 16 + (lane & 15)) * SA + kt * 16 + ((lane >> 4) << 3);
                ldsm_x4(qh[kt], s2u(Qhi + off));
                ldsm_x4(ql[kt], s2u(Qlo + off));
            }
        }

        __nv_bfloat16* sKh = SM + 2 * 64 * SA + cur * ATT_STAGE;
        __nv_bfloat16* sKl = sKh + 64 * SA;
        __nv_bfloat16* sVh = sKh + 2 * 64 * SA;
        __nv_bfloat16* sVl = sKh + 3 * 64 * SA;

        float sc[8][4];
#pragma unroll
        for (int n = 0; n < 8; n++)
#pragma unroll
            for (int v = 0; v < 4; v++) sc[n][v] = 0.f;
#pragma unroll
        for (int kt = 0; kt < 4; kt++) {
            unsigned kh[4][4], kl[4][4];
#pragma unroll
            for (int nt = 0; nt < 4; nt++) {
                int off = (nt * 16 + (lane & 15)) * SA + kt * 16 + ((lane >> 4) << 3);
                ldsm_x4(kh[nt], s2u(sKh + off));
                ldsm_x4(kl[nt], s2u(sKl + off));
            }
#pragma unroll
            for (int nt = 0; nt < 4; nt++) {
#pragma unroll
                for (int sub = 0; sub < 2; sub++) {
                    int n = nt * 2 + sub;
                    mma_bf16(sc[n], qh[kt], kh[nt][sub], kh[nt][sub + 2]);
                    mma_bf16(sc[n], qh[kt], kl[nt][sub], kl[nt][sub + 2]);
                    mma_bf16(sc[n], ql[kt], kh[nt][sub], kh[nt][sub + 2]);
                }
            }
        }
#pragma unroll
        for (int n = 0; n < 8; n++)
#pragma unroll
            for (int v = 0; v < 4; v++) sc[n][v] *= 0.125f;

        float mt0 = -1e30f, mt1 = -1e30f;
#pragma unroll
        for (int n = 0; n < 8; n++) {
            mt0 = fmaxf(mt0, fmaxf(sc[n][0], sc[n][1]));
            mt1 = fmaxf(mt1, fmaxf(sc[n][2], sc[n][3]));
        }
        mt0 = fmaxf(mt0, __shfl_xor_sync(0xffffffffu, mt0, 1));
        mt0 = fmaxf(mt0, __shfl_xor_sync(0xffffffffu, mt0, 2));
        mt1 = fmaxf(mt1, __shfl_xor_sync(0xffffffffu, mt1, 1));
        mt1 = fmaxf(mt1, __shfl_xor_sync(0xffffffffu, mt1, 2));
        float mn0 = fmaxf(m0, mt0), mn1 = fmaxf(m1, mt1);
        float cr0 = __expf(m0 - mn0), cr1 = __expf(m1 - mn1);
        float s0 = 0.f, s1 = 0.f;
#pragma unroll
        for (int n = 0; n < 8; n++) {
            sc[n][0] = __expf(sc[n][0] - mn0);
            sc[n][1] = __expf(sc[n][1] - mn0);
            sc[n][2] = __expf(sc[n][2] - mn1);
            sc[n][3] = __expf(sc[n][3] - mn1);
            s0 += sc[n][0] + sc[n][1];
            s1 += sc[n][2] + sc[n][3];
        }
        s0 += __shfl_xor_sync(0xffffffffu, s0, 1);
        s0 += __shfl_xor_sync(0xffffffffu, s0, 2);
        s1 += __shfl_xor_sync(0xffffffffu, s1, 1);
        s1 += __shfl_xor_sync(0xffffffffu, s1, 2);
        l0 = l0 * cr0 + s0; l1 = l1 * cr1 + s1;
        m0 = mn0; m1 = mn1;
#pragma unroll
        for (int d = 0; d < 8; d++) {
            o[d][0] *= cr0; o[d][1] *= cr0;
            o[d][2] *= cr1; o[d][3] *= cr1;
        }

        unsigned ph[4][4], pl[4][4];
#pragma unroll
        for (int kt2 = 0; kt2 < 4; kt2++) {
#pragma unroll
            for (int part = 0; part < 4; part++) {
                int n = kt2 * 2 + (part >> 1);
                int i0 = (part & 1) * 2;
                float x = sc[n][i0], y = sc[n][i0 + 1];
                __nv_bfloat16 hx = __float2bfloat16(x);
                __nv_bfloat16 hy = __float2bfloat16(y);
                ph[kt2][part] = (unsigned)__bfloat16_as_ushort(hx) |
                                ((unsigned)__bfloat16_as_ushort(hy) << 16);
                pl[kt2][part] = packbf(x - __bfloat162float(hx),
                                       y - __bfloat162float(hy));
            }
        }

#pragma unroll
        for (int kt2 = 0; kt2 < 4; kt2++) {
            unsigned vh[4][4], vl[4][4];
#pragma unroll
            for (int dt = 0; dt < 4; dt++) {
                int off = (kt2 * 16 + (lane & 15)) * SA + dt * 16 + ((lane >> 4) << 3);
                ldsm_x4t(vh[dt], s2u(sVh + off));
                ldsm_x4t(vl[dt], s2u(sVl + off));
            }
#pragma unroll
            for (int dt = 0; dt < 4; dt++) {
#pragma unroll
                for (int sub = 0; sub < 2; sub++) {
                    int d = dt * 2 + sub;
                    mma_bf16(o[d], ph[kt2], vh[dt][sub * 2], vh[dt][sub * 2 + 1]);
                    mma_bf16(o[d], ph[kt2], vl[dt][sub * 2], vl[dt][sub * 2 + 1]);
                    mma_bf16(o[d], pl[kt2], vh[dt][sub * 2], vh[dt][sub * 2 + 1]);
                }
            }
        }
        __syncthreads();
    }

    float inv0 = 1.f / l0, inv1 = 1.f / l1;
    int row0 = qbase + warp * 16 + (lane >> 2);
    int row1 = row0 + 8;
#pragma unroll
    for (int d = 0; d < 8; d++) {
        int c0 = h * 64 + d * 8 + (lane & 3) * 2;
        float2 v0; v0.x = o[d][0] * inv0; v0.y = o[d][1] * inv0;
        float2 v1; v1.x = o[d][2] * inv1; v1.y = o[d][3] * inv1;
        *(float2*)&vals[(size_t)(b * SS + row0) * DD + c0] = v0;
        *(float2*)&vals[(size_t)(b * SS + row1) * DD + c0] = v1;
    }
}

// ---------------------------------------------------------------------------
__global__ void init_all(float* __restrict__ qkimg, float* __restrict__ vv,
                         float* __restrict__ outpre, float* __restrict__ wvals,
                         float* __restrict__ h1, float* __restrict__ h2,
                         float* __restrict__ trow,
                         float* __restrict__ outh, const float* __restrict__ out_b,
                         float* __restrict__ ctxrow, const float* __restrict__ ctx_out_b,
                         float* __restrict__ wtext, const float* __restrict__ o_b) {
    int i = blockIdx.x * 256 + threadIdx.x;
    qkimg[i] = 0.f; vv[i] = 0.f; outpre[i] = 0.f; wvals[i] = 0.f;
    wtext[i] = o_b[i & 1023];
    if (i < BB * DI2) { h1[i] = 0.f; h2[i] = 0.f; }
    if (i < BB * DD) {
        trow[i] = 0.f;
        outh[i] = out_b[i & 1023];
        ctxrow[i] = ctx_out_b[i & 1023];
    }
}

// ---------------------------------------------------------------------------
__global__ void img_proj(const float* __restrict__ img,
                         const float* __restrict__ W1, const float* __restrict__ W2,
                         float* __restrict__ O1, float* __restrict__ O2) {
    const float* W = blockIdx.z ? W2 : W1;
    float* O = blockIdx.z ? O2 : O1;
    int col = blockIdx.x * 256 + threadIdx.x;
    int k0 = blockIdx.y * 128;
    __shared__ float xs[4][128];
    for (int i = threadIdx.x; i < 512; i += 256)
        xs[i >> 7][i & 127] = img[(i >> 7) * DD + k0 + (i & 127)];
    __syncthreads();
    float a0 = 0, a1 = 0, a2 = 0, a3 = 0;
    const float* wp = W + (size_t)k0 * INNER + col;
#pragma unroll 4
    for (int k = 0; k < 128; k++) {
        float wv = wp[(size_t)k * INNER];
        a0 += xs[0][k] * wv; a1 += xs[1][k] * wv;
        a2 += xs[2][k] * wv; a3 += xs[3][k] * wv;
    }
    atomicAdd(&O[col], a0);
    atomicAdd(&O[INNER + col], a1);
    atomicAdd(&O[2 * INNER + col], a2);
    atomicAdd(&O[3 * INNER + col], a3);
}

// ---------------------------------------------------------------------------
__global__ __launch_bounds__(256) void wq_kernel(const float* __restrict__ Wc,
                                                 const float* __restrict__ qkimg,
                                                 float* __restrict__ wq) {
    int gwarp = (blockIdx.x * 256 + threadIdx.x) >> 5;
    int lane = threadIdx.x & 31;
    int d = gwarp >> 4, h = gwarp & 15;
    const float* row = Wc + (size_t)d * INNER + h * 1024;
    const float* qb = qkimg + h * 1024;
    float a0 = 0, a1 = 0, a2 = 0, a3 = 0;
    for (int e = lane; e < 1024; e += 32) {
        float wv = row[e];
        a0 += wv * qb[e];
        a1 += wv * qb[INNER + e];
        a2 += wv * qb[2 * INNER + e];
        a3 += wv * qb[3 * INNER + e];
    }
#pragma unroll
    for (int o = 16; o; o >>= 1) {
        a0 += __shfl_xor_sync(0xffffffffu, a0, o);
        a1 += __shfl_xor_sync(0xffffffffu, a1, o);
        a2 += __shfl_xor_sync(0xffffffffu, a2, o);
        a3 += __shfl_xor_sync(0xffffffffu, a3, o);
    }
    if (lane == 0) {
        wq[(0 * HH + h) * DD + d] = a0;
        wq[(1 * HH + h) * DD + d] = a1;
        wq[(2 * HH + h) * DD + d] = a2;
        wq[(3 * HH + h) * DD + d] = a3;
    }
}

// ---------------------------------------------------------------------------
template <int MT>
__global__ __launch_bounds__(256) void gemm_nt(const float* __restrict__ A, int lda, long sA,
                                               const float* __restrict__ Bm, int ldb, long sB,
                                               float* __restrict__ C, int ldc, long sC,
                                               int M, int N, int K, float alpha) {
    int batch = blockIdx.y;
    A += (size_t)batch * sA; Bm += (size_t)batch * sB; C += (size_t)batch * sC;
    int warp = threadIdx.x >> 5, lane = threadIdx.x & 31;
    int j = blockIdx.x * 8 + warp;
    __shared__ float As[MT][128];
    float acc[MT];
#pragma unroll
    for (int i = 0; i < MT; i++) acc[i] = 0.f;
    for (int k0 = 0; k0 < K; k0 += 128) {
        __syncthreads();
        for (int i = threadIdx.x; i < MT * 128; i += 256) {
            int r = i >> 7, c = i & 127;
            As[r][c] = (r < M) ? A[(size_t)r * lda + k0 + c] : 0.f;
        }
        __syncthreads();
        const float* bp = Bm + (size_t)j * ldb + k0;
        for (int k = lane; k < 128; k += 32) {
            float bv = bp[k];
#pragma unroll
            for (int i = 0; i < MT; i++) acc[i] += As[i][k] * bv;
        }
    }
#pragma unroll
    for (int i = 0; i < MT; i++) {
        float v = acc[i];
#pragma unroll
        for (int o = 16; o; o >>= 1) v += __shfl_xor_sync(0xffffffffu, v, o);
        if (lane == 0 && i < M) C[(size_t)i * ldc + j] = alpha * v;
    }
}

// ---------------------------------------------------------------------------
// scalar-j gemm_nn (kept for wvals/wtext)
template <int MT>
__global__ __launch_bounds__(256) void gemm_nn(const float* __restrict__ A, int lda, long sA,
                                               const float* __restrict__ Bm, int ldb, long sB,
                                               const float* __restrict__ bias,
                                               float* __restrict__ C, int ldc, long sC,
                                               int M, int N, int K, float alpha, int act) {
    int batch = blockIdx.y;
    A += (size_t)batch * sA; Bm += (size_t)batch * sB; C += (size_t)batch * sC;
    int j = blockIdx.x * 256 + threadIdx.x;
    int kChunk = K / gridDim.z;
    int kBeg = blockIdx.z * kChunk;
    float acc[MT];
#pragma unroll
    for (int i = 0; i < MT; i++) acc[i] = 0.f;
    __shared__ float As[MT][32];
    for (int k0 = kBeg; k0 < kBeg + kChunk; k0 += 32) {
        __syncthreads();
        for (int i = threadIdx.x; i < MT * 32; i += 256) {
            int r = i >> 5, c = i & 31;
            As[r][c] = (r < M) ? A[(size_t)r * lda + k0 + c] : 0.f;
        }
        __syncthreads();
#pragma unroll 4
        for (int k = 0; k < 32; k++) {
            float bv = Bm[(size_t)(k0 + k) * ldb + j];
#pragma unroll
            for (int i = 0; i < MT; i++) acc[i] += As[i][k] * bv;
        }
    }
    if (gridDim.z == 1) {
        float bb = bias ? bias[j] : 0.f;
        for (int i = 0; i < MT && i < M; i++) {
            float v = alpha * acc[i] + bb;
            if (act) v = tanhf(v);
            C[(size_t)i * ldc + j] = v;
        }
    } else {
        for (int i = 0; i < MT && i < M; i++)
            atomicAdd(&C[(size_t)i * ldc + j], alpha * acc[i]);
    }
}

// ---------------------------------------------------------------------------
// vectorized gemm_nn: 4 j-columns per thread (float4 B loads), ksplit atomic.
// grid.x = N/1024. Always atomic-accumulate (outputs pre-initialized).
template <int MT>
__global__ __launch_bounds__(256) void gemm_nn4(const float* __restrict__ A, int lda, long sA,
                                                const float* __restrict__ Bm, int ldb, long sB,
                                                float* __restrict__ C, int ldc, long sC,
                                                int M, int K) {
    int batch = blockIdx.y;
    A += (size_t)batch * sA; Bm += (size_t)batch * sB; C += (size_t)batch * sC;
    int j4 = (blockIdx.x * 256 + threadIdx.x) * 4;
    int kChunk = K / gridDim.z;
    int kBeg = blockIdx.z * kChunk;
    float acc[MT][4];
#pragma unroll
    for (int i = 0; i < MT; i++) {
        acc[i][0] = 0.f; acc[i][1] = 0.f; acc[i][2] = 0.f; acc[i][3] = 0.f;
    }
    __shared__ float As[MT][32];
    for (int k0 = kBeg; k0 < kBeg + kChunk; k0 += 32) {
        __syncthreads();
        for (int i = threadIdx.x; i < MT * 32; i += 256) {
            int r = i >> 5, c = i & 31;
            As[r][c] = (r < M) ? A[(size_t)r * lda + k0 + c] : 0.f;
        }
        __syncthreads();
#pragma unroll 8
        for (int k = 0; k < 32; k++) {
            float4 bv = *(const float4*)&Bm[(size_t)(k0 + k) * ldb + j4];
#pragma unroll
            for (int i = 0; i < MT; i++) {
                float a = As[i][k];
                acc[i][0] += a * bv.x; acc[i][1] += a * bv.y;
                acc[i][2] += a * bv.z; acc[i][3] += a * bv.w;
            }
        }
    }
    for (int i = 0; i < MT && i < M; i++) {
        atomicAdd(&C[(size_t)i * ldc + j4 + 0], acc[i][0]);
        atomicAdd(&C[(size_t)i * ldc + j4 + 1], acc[i][1]);
        atomicAdd(&C[(size_t)i * ldc + j4 + 2], acc[i][2]);
        atomicAdd(&C[(size_t)i * ldc + j4 + 3], acc[i][3]);
    }
}

// ---------------------------------------------------------------------------
__global__ void softmax_rows(float* __restrict__ base, int n) {
    float* p = base + (size_t)blockIdx.x * n;
    __shared__ float red[8];
    __shared__ float red2[8];
    int tid = threadIdx.x;
    float m = -1e30f;
    for (int j = tid; j < n; j += 256) m = fmaxf(m, p[j]);
#pragma unroll
    for (int o = 16; o; o >>= 1) m = fmaxf(m, __shfl_xor_sync(0xffffffffu, m, o));
    if ((tid & 31) == 0) red[tid >> 5] = m;
    __syncthreads();
    float mm = red[0];
#pragma unroll
    for (int w = 1; w < 8; w++) mm = fmaxf(mm, red[w]);
    float sum = 0.f;
    for (int j = tid; j < n; j += 256) {
        float e = __expf(p[j] - mm);
        p[j] = e;
        sum += e;
    }
#pragma unroll
    for (int o = 16; o; o >>= 1) sum += __shfl_xor_sync(0xffffffffu, sum, o);
    if ((tid & 31) == 0) red2[tid >> 5] = sum;
    __syncthreads();
    float tot = 0.f;
#pragma unroll
    for (int w = 0; w < 8; w++) tot += red2[w];
    float inv = 1.f / tot;
    for (int j = tid; j < n; j += 256) p[j] *= inv;
}

// ---------------------------------------------------------------------------
__global__ void tanh_bias_k(float* __restrict__ x, const float* __restrict__ bias,
                            int n, int total) {
    int i = blockIdx.x * 256 + threadIdx.x;
    if (i < total) x[i] = tanhf(x[i] + bias[i % n]);
}

__global__ void bcast_text(const float* __restrict__ trow, const float* __restrict__ b3,
                           float* __restrict__ out) {
    size_t idx = (size_t)blockIdx.x * 256 + threadIdx.x;
    size_t e = idx * 4;
    int b = (int)(e / ((size_t)SS * DD));
    int d = (int)(e % DD);
    float4 t = *(const float4*)&trow[b * DD + d];
    float4 bb = *(const float4*)&b3[d];
    t.x += bb.x; t.y += bb.y; t.z += bb.z; t.w += bb.w;
    *(float4*)&out[e] = t;
}

// ---------------------------------------------------------------------------
extern "C" void kernel_launch(void* const* d_in, const int* in_sizes, int n_in,
                              void* d_out, int out_size) {
    (void)in_sizes; (void)n_in; (void)out_size;
    const float* img      = (const float*)d_in[0];
    const float* text_emb = (const float*)d_in[1];
    const float* qkv_w    = (const float*)d_in[2];
    const float* qkv_b    = (const float*)d_in[3];
    const float* o_w      = (const float*)d_in[4];
    const float* o_b      = (const float*)d_in[5];
    const float* qk_w     = (const float*)d_in[6];
    const float* ctx_qk_w = (const float*)d_in[7];
    const float* v_w      = (const float*)d_in[8];
    const float* ctx_v_w  = (const float*)d_in[9];
    const float* out_w    = (const float*)d_in[10];
    const float* out_b    = (const float*)d_in[11];
    const float* ctx_out_w= (const float*)d_in[12];
    const float* ctx_out_b= (const float*)d_in[13];
    const float* w1 = (const float*)d_in[14];
    const float* b1 = (const float*)d_in[15];
    const float* w2 = (const float*)d_in[16];
    const float* b2 = (const float*)d_in[17];
    const float* w3 = (const float*)d_in[18];
    const float* b3 = (const float*)d_in[19];

    float* out_head = (float*)d_out;
    float* out_text = (float*)d_out + BB * DD;

    float* p_vals;   cudaGetSymbolAddress((void**)&p_vals, g_vals);
    float* p_qkimg;  cudaGetSymbolAddress((void**)&p_qkimg, g_qkimg);
    float* p_vv;     cudaGetSymbolAddress((void**)&p_vv, g_vv);
    float* p_wq;     cudaGetSymbolAddress((void**)&p_wq, g_wq);
    float* p_uq;     cudaGetSymbolAddress((void**)&p_uq, g_uq);
    float* p_sim;    cudaGetSymbolAddress((void**)&p_sim, g_sim);
    float* p_wvals;  cudaGetSymbolAddress((void**)&p_wvals, g_wvals);
    float* p_wtext;  cudaGetSymbolAddress((void**)&p_wtext, g_wtext);
    float* p_outpre; cudaGetSymbolAddress((void**)&p_outpre, g_outpre);
    float* p_ctxrow; cudaGetSymbolAddress((void**)&p_ctxrow, g_ctxrow);
    float* p_h1;     cudaGetSymbolAddress((void**)&p_h1, g_h1);
    float* p_h2;     cudaGetSymbolAddress((void**)&p_h2, g_h2);
    float* p_trow;   cudaGetSymbolAddress((void**)&p_trow, g_trow);
    __nv_bfloat16* p_Ahi; cudaGetSymbolAddress((void**)&p_Ahi, g_Ahi);
    __nv_bfloat16* p_Alo; cudaGetSymbolAddress((void**)&p_Alo, g_Alo);
    __nv_bfloat16* p_Bhi; cudaGetSymbolAddress((void**)&p_Bhi, g_Bhi);
    __nv_bfloat16* p_Blo; cudaGetSymbolAddress((void**)&p_Blo, g_Blo);
    __nv_bfloat16* p_Qkvhi; cudaGetSymbolAddress((void**)&p_Qkvhi, g_qkvhi);
    __nv_bfloat16* p_Qkvlo; cudaGetSymbolAddress((void**)&p_Qkvlo, g_qkvlo);

    static bool attr_set = false;
    if (!attr_set) {
        cudaFuncSetAttribute((const void*)attn3,
                             cudaFuncAttributeMaxDynamicSharedMemorySize, ATT_SMEM);
        cudaFuncSetAttribute((const void*)gemm_bf16x3,
                             cudaFuncAttributeMaxDynamicSharedMemorySize, GEMM_SMEM);
        attr_set = true;
    }

    // 0-1: splits
    split2bf16<<<(BB * SS * DD / 4 + 255) / 256, 256>>>(text_emb, p_Ahi, p_Alo,
                                                        BB * SS * DD / 4);
    split2bf16<<<(DD * 3 * DD / 4 + 255) / 256, 256>>>(qkv_w, p_Bhi, p_Blo,
                                                       DD * 3 * DD / 4);
    // 2: QKV GEMM
    gemm_bf16x3<<<dim3(3072 / 128, 4096 / 128), 256, GEMM_SMEM>>>(
        p_Ahi, p_Alo, p_Bhi, p_Blo, qkv_b, p_Qkvhi, p_Qkvlo, BB * SS, 3 * DD, DD);
    // 3: tensor-core flash attention (PROFILED: launch index 3)
    attn3<<<dim3(BB * HH, SS / 64), 128, ATT_SMEM>>>(p_Qkvhi, p_Qkvlo, p_vals);
    // 4: fused inits
    init_all<<<256, 256>>>(p_qkimg, p_vv, p_outpre, p_wvals, p_h1, p_h2, p_trow,
                           out_head, out_b, p_ctxrow, ctx_out_b, p_wtext, o_b);
    // 5: img projections
    img_proj<<<dim3(INNER / 256, 8, 2), 256>>>(img, qk_w, v_w, p_qkimg, p_vv);
    // 6: wq
    wq_kernel<<<2048, 256>>>(ctx_qk_w, p_qkimg, p_wq);
    // 7: uq
    gemm_nt<64><<<dim3(DD / 8, 1), 256>>>(p_wq, DD, 0, o_w, DD, 0, p_uq, DD, 0,
                                          64, DD, DD, 1.0f);
    // 8: sim
    gemm_nt<16><<<dim3(SS / 8, BB), 256>>>(p_uq, DD, (long)HH * DD,
                                           p_vals, DD, (long)SS * DD,
                                           p_sim, SS, (long)HH * SS,
                                           HH, SS, DD, 1.0f / 32.0f);
    // 9: row softmax
    softmax_rows<<<BB * HH, 256>>>(p_sim, SS);
    // 10: wvals (scalar gemm_nn, ksplit atomic)
    gemm_nn<16><<<dim3(DD / 256, BB, 8), 256>>>(p_sim, SS, (long)HH * SS,
                                                p_vals, DD, (long)SS * DD,
                                                nullptr, p_wvals, DD, (long)HH * DD,
                                                HH, DD, SS, 1.0f, 0);
    // 11: wtext (ksplit 16)
    gemm_nn<64><<<dim3(DD / 256, 1, 16), 256>>>(p_wvals, DD, 0, o_w, DD, 0,
                                                nullptr, p_wtext, DD, 0,
                                                64, DD, DD, 1.0f, 0);
    // 12: out_pre (v4: grid (1,16,8), kChunk=128)
    gemm_nn4<4><<<dim3(1, HH, 8), 256>>>(p_wtext, HH * DD, (long)DD,
                                         ctx_v_w, INNER, 1024L,
                                         p_outpre, INNER, 1024L, BB, DD);
    // 13: out head (v4: grid (1,1,128), kChunk=128)
    gemm_nn4<4><<<dim3(1, 1, 128), 256>>>(p_outpre, INNER, 0, out_w, DD, 0,
                                          out_head, DD, 0, BB, INNER);
    // 14: ctx_row (v4: grid (1,1,128))
    gemm_nn4<4><<<dim3(1, 1, 128), 256>>>(p_vv, INNER, 0, ctx_out_w, DD, 0,
                                          p_ctxrow, DD, 0, BB, INNER);
    // 15-19: tiny MLP (v4 + tanh/bias epilogues)
    gemm_nn4<4><<<dim3(DI2 / 1024, 1, 16), 256>>>(p_ctxrow, DD, 0, w1, DI2, 0,
                                                  p_h1, DI2, 0, BB, DD);
    tanh_bias_k<<<(BB * DI2 + 255) / 256, 256>>>(p_h1, b1, DI2, BB * DI2);
    gemm_nn4<4><<<dim3(DI2 / 1024, 1, 32), 256>>>(p_h1, DI2, 0, w2, DI2, 0,
                                                  p_h2, DI2, 0, BB, DI2);
    tanh_bias_k<<<(BB * DI2 + 255) / 256, 256>>>(p_h2, b2, DI2, BB * DI2);
    gemm_nn4<4><<<dim3(1, 1, 32), 256>>>(p_h2, DI2, 0, w3, DD, 0,
                                         p_trow, DD, 0, BB, DI2);
    // 20: broadcast
    bcast_text<<<(BB * SS * DD / 4) / 256, 256>>>(p_trow, b3, out_text);
}